// round 11
// baseline (speedup 1.0000x reference)
#include <cuda_runtime.h>
#include <cuda_bf16.h>
#include <math.h>
#include <stddef.h>
#include <stdint.h>

typedef unsigned long long ull;

// ---------------- problem constants ----------------
#define BB   32
#define LL   512
#define DM   384
#define DI   768
#define DS   64
#define NH   16
#define HD   48
#define DIP  1680
#define CD   896
#define NT   (BB*LL)
#define NOUT 38667
#define N_ORDER 60
#define N_FAMILY 427
#define N_GENUS 14216
#define N_SPECIES 23964

#define WIN1  (DM*DIP)
#define WOUT1 (DI*DM)

#define NCHUNK 8
#define CLEN   64
#define SFL    3072

// ---------------- scratch ----------------
__device__ float g_resid[(size_t)NT*DM];
__device__ float g_h    [(size_t)NT*DM];
__device__ float g_zx   [(size_t)NT*DIP];
__device__ float g_xBC  [(size_t)NT*CD];
__device__ float g_dt   [(size_t)NT*NH];
__device__ float g_dA   [(size_t)NT*NH];    // log(dA)
__device__ float g_lc   [(size_t)NT*NH];
__device__ float g_ys   [(size_t)NT*DI];
__device__ float g_state[(size_t)BB*NH*NCHUNK*SFL];
__device__ float g_sin  [(size_t)BB*NH*NCHUNK*SFL];
__device__ float g_pool [BB*16*DM];
__device__ float g_featT[DM*BB];
// bf16 split operands
__device__ __nv_bfloat16 g_xh[(size_t)NT*DM];
__device__ __nv_bfloat16 g_xl[(size_t)NT*DM];
__device__ __nv_bfloat16 g_yh[(size_t)NT*DI];
__device__ __nv_bfloat16 g_yl[(size_t)NT*DI];
__device__ __nv_bfloat16 g_wh[2*WIN1 + 2*WOUT1];   // transposed [N][K]
__device__ __nv_bfloat16 g_wl[2*WIN1 + 2*WOUT1];

__device__ __forceinline__ void bf16_split(float v, __nv_bfloat16& hi, __nv_bfloat16& lo){
    hi = __float2bfloat16(v);
    lo = __float2bfloat16(v - __bfloat162float(hi));
}

// ---------------- weight transpose + bf16 hi/lo split ----------------
__global__ __launch_bounds__(256) void wcvt_t_kernel(const float* __restrict__ Win,
                                                     const float* __restrict__ Wout)
{
    int r = blockIdx.z;
    const float* src; size_t doff; int K_, N_;
    if (r < 2){ src = Win  + (size_t)r*WIN1;      doff = (size_t)r*WIN1;              K_ = DM; N_ = DIP; }
    else      { src = Wout + (size_t)(r-2)*WOUT1; doff = 2*WIN1 + (size_t)(r-2)*WOUT1; K_ = DI; N_ = DM; }
    int k0 = blockIdx.y*32, n0 = blockIdx.x*32;
    if (k0 >= K_ || n0 >= N_) return;
    __shared__ float sm[32][33];
    int tx = threadIdx.x & 31, ty = threadIdx.x >> 5;
    #pragma unroll
    for (int q=0;q<4;q++){
        int k = k0 + ty + q*8;
        if (k < K_ && n0+tx < N_) sm[ty+q*8][tx] = src[(size_t)k*N_ + n0+tx];
    }
    __syncthreads();
    #pragma unroll
    for (int q=0;q<4;q++){
        int n = n0 + ty + q*8;
        int k = k0 + tx;
        if (n < N_ && k < K_){
            __nv_bfloat16 hi, lo;
            bf16_split(sm[tx][ty+q*8], hi, lo);
            g_wh[doff + (size_t)n*K_ + k] = hi;
            g_wl[doff + (size_t)n*K_ + k] = lo;
        }
    }
}

// ---------------- fused embedding + layer-0 layernorm (bf16 split out) ----------------
__global__ __launch_bounds__(128) void embed_ln_kernel(const int* __restrict__ tokens,
                                                       const float* __restrict__ emb,
                                                       const float* __restrict__ w,
                                                       const float* __restrict__ b)
{
    __shared__ float red[128];
    int row = blockIdx.x, tid = threadIdx.x;
    const float* er = emb + (size_t)tokens[row]*DM;
    float v0 = er[tid], v1 = er[tid+128], v2 = er[tid+256];
    float* rr = g_resid + (size_t)row*DM;
    rr[tid] = v0; rr[tid+128] = v1; rr[tid+256] = v2;

    red[tid] = v0+v1+v2; __syncthreads();
    for (int s=64;s>0;s>>=1){ if(tid<s) red[tid]+=red[tid+s]; __syncthreads(); }
    float mu = red[0] * (1.0f/DM);
    __syncthreads();
    float d0=v0-mu, d1=v1-mu, d2=v2-mu;
    red[tid] = d0*d0+d1*d1+d2*d2; __syncthreads();
    for (int s=64;s>0;s>>=1){ if(tid<s) red[tid]+=red[tid+s]; __syncthreads(); }
    float inv = rsqrtf(red[0]*(1.0f/DM) + 1e-5f);
    float o0 = d0*inv*w[tid]     + b[tid];
    float o1 = d1*inv*w[tid+128] + b[tid+128];
    float o2 = d2*inv*w[tid+256] + b[tid+256];
    __nv_bfloat16 h, l;
    size_t base = (size_t)row*DM;
    bf16_split(o0, h, l); g_xh[base+tid]     = h; g_xl[base+tid]     = l;
    bf16_split(o1, h, l); g_xh[base+tid+128] = h; g_xl[base+tid+128] = l;
    bf16_split(o2, h, l); g_xh[base+tid+256] = h; g_xl[base+tid+256] = l;
}

// ---------------- layernorm: tf=1 -> bf16 split; tf=0 -> fp32 g_h ----------------
__global__ __launch_bounds__(128) void ln_kernel(const float* __restrict__ w, const float* __restrict__ b, int tf)
{
    __shared__ float red[128];
    int row = blockIdx.x, tid = threadIdx.x;
    const float* xr = g_resid + (size_t)row*DM;
    float v0 = xr[tid], v1 = xr[tid+128], v2 = xr[tid+256];
    red[tid] = v0+v1+v2; __syncthreads();
    for (int s=64;s>0;s>>=1){ if(tid<s) red[tid]+=red[tid+s]; __syncthreads(); }
    float mu = red[0] * (1.0f/DM);
    __syncthreads();
    float d0=v0-mu, d1=v1-mu, d2=v2-mu;
    red[tid] = d0*d0+d1*d1+d2*d2; __syncthreads();
    for (int s=64;s>0;s>>=1){ if(tid<s) red[tid]+=red[tid+s]; __syncthreads(); }
    float inv = rsqrtf(red[0]*(1.0f/DM) + 1e-5f);
    float o0 = d0*inv*w[tid]     + b[tid];
    float o1 = d1*inv*w[tid+128] + b[tid+128];
    float o2 = d2*inv*w[tid+256] + b[tid+256];
    if (tf){
        __nv_bfloat16 h, l;
        size_t base = (size_t)row*DM;
        bf16_split(o0, h, l); g_xh[base+tid]     = h; g_xl[base+tid]     = l;
        bf16_split(o1, h, l); g_xh[base+tid+128] = h; g_xl[base+tid+128] = l;
        bf16_split(o2, h, l); g_xh[base+tid+256] = h; g_xl[base+tid+256] = l;
    } else {
        float* o = g_h + (size_t)row*DM;
        o[tid] = o0; o[tid+128] = o1; o[tid+256] = o2;
    }
}

// ---------------- bf16 split-compensated GEMM (mma.sync.m16n8k16) ----------------
// Stage layout (FIXED): per stage s: A tile at sh2 + s*STAGE_E, B tile at sh2 + s*STAGE_E + TILE_E.
// MODE 0: g_zx = X @ W      (M=NT, N=DIP, K=DM, 3 passes)
// MODE 1: g_resid += Y @ W  (M=NT, N=DM,  K=DI, 3 passes, split-K 2)
#define GBK2 32
#define NSTG 4
#define TSTR2 40                          // bf16 elems per row (80 B, conflict-free)
#define TILE_E (128*TSTR2)                // 5120 bf16 per tile
#define STAGE_E (2*TILE_E)
#define SMEM2_BYTES (NSTG*STAGE_E*2)      // 81920 B

__device__ __forceinline__ void mma_bf16(float* c, const uint32_t* a, const uint32_t* b){
    asm volatile(
      "mma.sync.aligned.m16n8k16.row.col.f32.bf16.bf16.f32 "
      "{%0,%1,%2,%3}, {%4,%5,%6,%7}, {%8,%9}, {%0,%1,%2,%3};\n"
      : "+f"(c[0]), "+f"(c[1]), "+f"(c[2]), "+f"(c[3])
      : "r"(a[0]), "r"(a[1]), "r"(a[2]), "r"(a[3]), "r"(b[0]), "r"(b[1]));
}

template<int MODE, int SPLITK>
__global__ __launch_bounds__(256,2) void gemm_bf(int layer)
{
    const __nv_bfloat16* Ah = MODE ? g_yh : g_xh;
    const __nv_bfloat16* Al = MODE ? g_yl : g_xl;
    const size_t woff = MODE ? (2*(size_t)WIN1 + (size_t)layer*WOUT1) : ((size_t)layer*WIN1);
    const __nv_bfloat16* Wh = g_wh + woff;
    const __nv_bfloat16* Wl = g_wl + woff;
    float* C = MODE ? g_resid : g_zx;
    const int N  = MODE ? DM : DIP;
    const int K  = MODE ? DI : DM;
    const int KT = K / GBK2;              // k-tiles per pass
    const int NT_ALL = 3*KT;              // total tiles over 3 passes
    const int TPB = NT_ALL / SPLITK;      // tiles for this z
    const int g_off = blockIdx.z * TPB;

    extern __shared__ __nv_bfloat16 sh2[];
    __nv_bfloat16* shB2 = sh2 + TILE_E;   // B tile follows A tile within each stage

    int tid  = threadIdx.x;
    int warp = tid >> 5;
    int lane = tid & 31;
    int gid  = lane >> 2;
    int tig  = lane & 3;

    int m0 = blockIdx.y * 128;
    int n0 = blockIdx.x * 128;
    int wm = (warp & 1) * 64;
    int wn = (warp >> 1) * 32;

    float acc[4][4][4];
    #pragma unroll
    for (int i=0;i<4;i++)
        #pragma unroll
        for (int j=0;j<4;j++)
            #pragma unroll
            for (int q=0;q<4;q++) acc[i][j][q]=0.f;

    // copy mapping: tile = 128 rows x 32 bf16 = 512 chunks of 16B; 2 per thread
    int row0 = tid >> 2,  c80 = (tid & 3) << 3;
    int row1 = row0 + 64, c81 = c80;
    int bok0 = (n0 + row0 < N) ? 16 : 0;
    int bok1 = (n0 + row1 < N) ? 16 : 0;
    int bn0 = (n0 + row0 < N) ? (n0 + row0) : 0;
    int bn1 = (n0 + row1 < N) ? (n0 + row1) : 0;

    uint32_t adst0, adst1, bdst0, bdst1;
    {
        uint32_t a0, a1, b0, b1;
        asm("{ .reg .u64 t; cvta.to.shared.u64 t, %1; cvt.u32.u64 %0, t; }" : "=r"(a0) : "l"(&sh2 [row0*TSTR2 + c80]));
        asm("{ .reg .u64 t; cvta.to.shared.u64 t, %1; cvt.u32.u64 %0, t; }" : "=r"(a1) : "l"(&sh2 [row1*TSTR2 + c81]));
        asm("{ .reg .u64 t; cvta.to.shared.u64 t, %1; cvt.u32.u64 %0, t; }" : "=r"(b0) : "l"(&shB2[row0*TSTR2 + c80]));
        asm("{ .reg .u64 t; cvta.to.shared.u64 t, %1; cvt.u32.u64 %0, t; }" : "=r"(b1) : "l"(&shB2[row1*TSTR2 + c81]));
        adst0=a0; adst1=a1; bdst0=b0; bdst1=b1;
    }

    auto issue_copy = [&](int slot, int g){
        int gg = g_off + g;
        int ph = gg / KT, kt = gg - ph*KT;
        const __nv_bfloat16* As = (ph < 2) ? Ah : Al;
        const __nv_bfloat16* Ws = (ph == 1) ? Wl : Wh;
        int k0 = kt * GBK2;
        uint32_t so = (uint32_t)slot * STAGE_E * 2;   // bytes
        asm volatile("cp.async.cg.shared.global [%0], [%1], 16;\n"
                     :: "r"(adst0 + so), "l"(As + (size_t)(m0+row0)*K + k0 + c80));
        asm volatile("cp.async.cg.shared.global [%0], [%1], 16;\n"
                     :: "r"(adst1 + so), "l"(As + (size_t)(m0+row1)*K + k0 + c81));
        asm volatile("cp.async.cg.shared.global [%0], [%1], 16, %2;\n"
                     :: "r"(bdst0 + so), "l"(Ws + (size_t)bn0*K + k0 + c80), "r"(bok0));
        asm volatile("cp.async.cg.shared.global [%0], [%1], 16, %2;\n"
                     :: "r"(bdst1 + so), "l"(Ws + (size_t)bn1*K + k0 + c81), "r"(bok1));
    };

    #pragma unroll
    for (int st=0; st<NSTG-1; st++){
        if (st < TPB) issue_copy(st, st);
        asm volatile("cp.async.commit_group;\n");
    }

    for (int it=0; it<TPB; ++it){
        asm volatile("cp.async.wait_group %0;\n" :: "n"(NSTG-2));
        __syncthreads();

        int cb = it & (NSTG-1);
        const __nv_bfloat16* Asb = &sh2 [cb*STAGE_E];
        const __nv_bfloat16* Bsb = &shB2[cb*STAGE_E];

        #pragma unroll
        for (int ks=0; ks<GBK2; ks+=16){
            uint32_t af[4][4], bf[4][2];
            #pragma unroll
            for (int mi=0; mi<4; mi++){
                int mr = wm + 16*mi;
                af[mi][0] = *(const uint32_t*)&Asb[(mr+gid  )*TSTR2 + ks + 2*tig    ];
                af[mi][1] = *(const uint32_t*)&Asb[(mr+gid+8)*TSTR2 + ks + 2*tig    ];
                af[mi][2] = *(const uint32_t*)&Asb[(mr+gid  )*TSTR2 + ks + 2*tig + 8];
                af[mi][3] = *(const uint32_t*)&Asb[(mr+gid+8)*TSTR2 + ks + 2*tig + 8];
            }
            #pragma unroll
            for (int ni=0; ni<4; ni++){
                int nb = wn + 8*ni;
                bf[ni][0] = *(const uint32_t*)&Bsb[(nb+gid)*TSTR2 + ks + 2*tig    ];
                bf[ni][1] = *(const uint32_t*)&Bsb[(nb+gid)*TSTR2 + ks + 2*tig + 8];
            }
            #pragma unroll
            for (int mi=0; mi<4; mi++)
                #pragma unroll
                for (int ni=0; ni<4; ni++)
                    mma_bf16(acc[mi][ni], af[mi], bf[ni]);
        }

        int nx = it + NSTG - 1;
        if (nx < TPB) issue_copy(nx & (NSTG-1), nx);
        asm volatile("cp.async.commit_group;\n");
    }

    #pragma unroll
    for (int mi=0; mi<4; mi++){
        int r0 = m0 + wm + 16*mi + gid;
        #pragma unroll
        for (int ni=0; ni<4; ni++){
            int c0 = n0 + wn + 8*ni + 2*tig;
            float* a = acc[mi][ni];
            #pragma unroll
            for (int half=0; half<2; half++){
                int cc = c0 + half;
                if (cc < N){
                    size_t i0 = (size_t)r0*N + cc;
                    size_t i2 = (size_t)(r0+8)*N + cc;
                    if (MODE){ atomicAdd(&C[i0], a[half]); atomicAdd(&C[i2], a[2+half]); }
                    else     { C[i0] = a[half]; C[i2] = a[2+half]; }
                }
            }
        }
    }
}

// ---------------- fused conv (16-step chunks) + dt/logdA ----------------
#define CONV_BLKS (BB*32)
#define DTDA_TOT  (NT*(NH/4))
#define DTDA_BLKS ((DTDA_TOT + 223)/224)
__global__ __launch_bounds__(224) void conv_dtda_kernel(const float* __restrict__ cw, const float* __restrict__ cb,
                                                        const float* __restrict__ dtb, const float* __restrict__ alog)
{
    int blk = blockIdx.x;
    int tid = threadIdx.x;
    if (blk < CONV_BLKS){
        int b  = blk >> 5;
        int tc = blk & 31;
        int t0 = tc * 16;
        int c  = tid << 2;

        float4 tw[4];
        #pragma unroll
        for (int k=0;k<4;k++){
            tw[k].x = cw[(c+0)*4+k];
            tw[k].y = cw[(c+1)*4+k];
            tw[k].z = cw[(c+2)*4+k];
            tw[k].w = cw[(c+3)*4+k];
        }
        float4 bias = *(const float4*)&cb[c];

        const float* base = g_zx + (size_t)(b*LL + t0)*DIP + DI + c;
        float* obase = g_xBC + (size_t)(b*LL + t0)*CD + c;

        float4 p1, p2, p3;
        if (t0 > 0){
            p1 = *(const float4*)(base - 3*DIP);
            p2 = *(const float4*)(base - 2*DIP);
            p3 = *(const float4*)(base - 1*DIP);
        } else {
            p1 = p2 = p3 = make_float4(0.f,0.f,0.f,0.f);
        }

        #pragma unroll
        for (int i=0;i<16;i++){
            float4 v = *(const float4*)(base + (size_t)i*DIP);
            float4 a;
            a.x = bias.x + p1.x*tw[0].x + p2.x*tw[1].x + p3.x*tw[2].x + v.x*tw[3].x;
            a.y = bias.y + p1.y*tw[0].y + p2.y*tw[1].y + p3.y*tw[2].y + v.y*tw[3].y;
            a.z = bias.z + p1.z*tw[0].z + p2.z*tw[1].z + p3.z*tw[2].z + v.z*tw[3].z;
            a.w = bias.w + p1.w*tw[0].w + p2.w*tw[1].w + p3.w*tw[2].w + v.w*tw[3].w;
            float4 r;
            r.x = a.x / (1.f + __expf(-a.x));
            r.y = a.y / (1.f + __expf(-a.y));
            r.z = a.z / (1.f + __expf(-a.z));
            r.w = a.w / (1.f + __expf(-a.w));
            *(float4*)(obase + (size_t)i*CD) = r;
            p1 = p2; p2 = p3; p3 = v;
        }
    } else {
        int j = (blk - CONV_BLKS)*224 + tid;
        if (j >= DTDA_TOT) return;
        int hq = (j & 3) << 2;
        int bt = j >> 2;
        #pragma unroll
        for (int q=0;q<4;q++){
            int hh = hq + q;
            float raw = g_zx[(size_t)bt*DIP + (DIP-NH) + hh] + dtb[hh];
            float sp = (raw > 20.f) ? raw : log1pf(expf(raw));
            g_dt[bt*NH + hh] = sp;
            g_dA[bt*NH + hh] = -expf(alog[hh]) * sp;
        }
    }
}

// ---------------- legacy tf32 mma helper (SSD kernels) ----------------
__device__ __forceinline__ void mma_tf32(float* c, const uint32_t* a, const uint32_t* b){
    asm volatile(
      "mma.sync.aligned.m16n8k8.row.col.f32.tf32.tf32.f32 "
      "{%0,%1,%2,%3}, {%4,%5,%6,%7}, {%8,%9}, {%0,%1,%2,%3};\n"
      : "+f"(c[0]), "+f"(c[1]), "+f"(c[2]), "+f"(c[3])
      : "r"(a[0]), "r"(a[1]), "r"(a[2]), "r"(a[3]), "r"(b[0]), "r"(b[1]));
}

// ---------------- SSD scan pass A ----------------
#define SA_STR 68
#define SSD_A_SMEM ((3*64*SA_STR + 2*48*SA_STR + 192)*4)

__global__ __launch_bounds__(128) void ssd_local_kernel()
{
    int blk = blockIdx.x;
    int c  = blk & (NCHUNK-1);
    int bh = blk >> 3;
    int b  = bh >> 4;
    int h  = bh & 15;
    int tid = threadIdx.x;
    int warp = tid >> 5, lane = tid & 31, gid = lane >> 2, tig = lane & 3;
    int bt0 = b*LL + c*CLEN;

    extern __shared__ float sa[];
    float* sC   = sa;
    float* sBW  = sC  + 64*SA_STR;
    float* sBT  = sBW + 64*SA_STR;
    float* sXT  = sBT + 64*SA_STR;
    float* sXwT = sXT + 48*SA_STR;
    float* lc_sh = sXwT + 48*SA_STR;
    float* dt_sh = lc_sh + 64;
    float* w2_sh = dt_sh + 64;

    for (int i = tid; i < 64*16; i += 128){
        int t = i >> 4, q = (i & 15) << 2;
        const float* row = g_xBC + (size_t)(bt0+t)*CD + DI;
        float4 vb = *(const float4*)(row + q);
        float4 vc = *(const float4*)(row + DS + q);
        *(float4*)&sBW[t*SA_STR + q] = vb;
        *(float4*)&sC [t*SA_STR + q] = vc;
        sBT[(q+0)*SA_STR + t] = vb.x;
        sBT[(q+1)*SA_STR + t] = vb.y;
        sBT[(q+2)*SA_STR + t] = vb.z;
        sBT[(q+3)*SA_STR + t] = vb.w;
    }
    for (int i = tid; i < 64*12; i += 128){
        int t = i / 12, q = (i % 12) << 2;
        float4 vx = *(const float4*)(g_xBC + (size_t)(bt0+t)*CD + h*HD + q);
        sXT[(q+0)*SA_STR + t] = vx.x;
        sXT[(q+1)*SA_STR + t] = vx.y;
        sXT[(q+2)*SA_STR + t] = vx.z;
        sXT[(q+3)*SA_STR + t] = vx.w;
    }
    if (tid < 64) dt_sh[tid] = g_dt[(size_t)(bt0+tid)*NH + h];
    if (warp == 0){
        float v0 = g_dA[(size_t)(bt0+lane)*NH + h];
        float v1 = g_dA[(size_t)(bt0+32+lane)*NH + h];
        #pragma unroll
        for (int d=1; d<32; d<<=1){
            float u0 = __shfl_up_sync(0xffffffffu, v0, d);
            float u1 = __shfl_up_sync(0xffffffffu, v1, d);
            if (lane >= d){ v0 += u0; v1 += u1; }
        }
        float tot = __shfl_sync(0xffffffffu, v0, 31);
        v1 += tot;
        lc_sh[lane]    = v0;
        lc_sh[32+lane] = v1;
        g_lc[(size_t)(bt0+lane)*NH + h]    = v0;
        g_lc[(size_t)(bt0+32+lane)*NH + h] = v1;
    }
    __syncthreads();

    int wt0 = warp*16;
    float gacc[8][4];
    #pragma unroll
    for (int ni=0;ni<8;ni++){ gacc[ni][0]=0.f; gacc[ni][1]=0.f; gacc[ni][2]=0.f; gacc[ni][3]=0.f; }
    #pragma unroll
    for (int kk=0; kk<64; kk+=8){
        uint32_t af[4];
        af[0] = __float_as_uint(sC[(wt0+gid  )*SA_STR + kk+tig  ]);
        af[1] = __float_as_uint(sC[(wt0+gid+8)*SA_STR + kk+tig  ]);
        af[2] = __float_as_uint(sC[(wt0+gid  )*SA_STR + kk+tig+4]);
        af[3] = __float_as_uint(sC[(wt0+gid+8)*SA_STR + kk+tig+4]);
        #pragma unroll
        for (int ni=0; ni<8; ni++){
            uint32_t bf[2];
            bf[0] = __float_as_uint(sBW[(8*ni+gid)*SA_STR + kk+tig  ]);
            bf[1] = __float_as_uint(sBW[(8*ni+gid)*SA_STR + kk+tig+4]);
            mma_tf32(gacc[ni], af, bf);
        }
    }
    if (tid < 64) w2_sh[tid] = __expf(lc_sh[63] - lc_sh[tid]) * dt_sh[tid];
    __syncthreads();

    {
        int t0r = wt0 + gid, t1r = t0r + 8;
        float lct0 = lc_sh[t0r], lct1 = lc_sh[t1r];
        #pragma unroll
        for (int ni=0; ni<8; ni++){
            int s0 = 8*ni + 2*tig, s1 = s0 + 1;
            float lcs0 = lc_sh[s0], lcs1 = lc_sh[s1];
            float d0 = dt_sh[s0],   d1 = dt_sh[s1];
            sBW[t0r*SA_STR + s0] = (s0<=t0r) ? gacc[ni][0]*__expf(lct0-lcs0)*d0 : 0.f;
            sBW[t0r*SA_STR + s1] = (s1<=t0r) ? gacc[ni][1]*__expf(lct0-lcs1)*d1 : 0.f;
            sBW[t1r*SA_STR + s0] = (s0<=t1r) ? gacc[ni][2]*__expf(lct1-lcs0)*d0 : 0.f;
            sBW[t1r*SA_STR + s1] = (s1<=t1r) ? gacc[ni][3]*__expf(lct1-lcs1)*d1 : 0.f;
        }
    }
    for (int i = tid; i < 48*64; i += 128){
        int p = i >> 6, s = i & 63;
        sXwT[p*SA_STR + s] = sXT[p*SA_STR + s] * w2_sh[s];
    }
    __syncthreads();

    float yacc[6][4], sacc[6][4];
    #pragma unroll
    for (int ni=0;ni<6;ni++){
        yacc[ni][0]=yacc[ni][1]=yacc[ni][2]=yacc[ni][3]=0.f;
        sacc[ni][0]=sacc[ni][1]=sacc[ni][2]=sacc[ni][3]=0.f;
    }
    #pragma unroll
    for (int kk=0; kk<64; kk+=8){
        uint32_t afW[4], afB[4];
        afW[0] = __float_as_uint(sBW[(wt0+gid  )*SA_STR + kk+tig  ]);
        afW[1] = __float_as_uint(sBW[(wt0+gid+8)*SA_STR + kk+tig  ]);
        afW[2] = __float_as_uint(sBW[(wt0+gid  )*SA_STR + kk+tig+4]);
        afW[3] = __float_as_uint(sBW[(wt0+gid+8)*SA_STR + kk+tig+4]);
        afB[0] = __float_as_uint(sBT[(wt0+gid  )*SA_STR + kk+tig  ]);
        afB[1] = __float_as_uint(sBT[(wt0+gid+8)*SA_STR + kk+tig  ]);
        afB[2] = __float_as_uint(sBT[(wt0+gid  )*SA_STR + kk+tig+4]);
        afB[3] = __float_as_uint(sBT[(wt0+gid+8)*SA_STR + kk+tig+4]);
        #pragma unroll
        for (int ni=0; ni<6; ni++){
            uint32_t bfX[2], bfW2[2];
            bfX[0]  = __float_as_uint(sXT [(8*ni+gid)*SA_STR + kk+tig  ]);
            bfX[1]  = __float_as_uint(sXT [(8*ni+gid)*SA_STR + kk+tig+4]);
            mma_tf32(yacc[ni], afW, bfX);
            bfW2[0] = __float_as_uint(sXwT[(8*ni+gid)*SA_STR + kk+tig  ]);
            bfW2[1] = __float_as_uint(sXwT[(8*ni+gid)*SA_STR + kk+tig+4]);
            mma_tf32(sacc[ni], afB, bfW2);
        }
    }

    size_t sbase = ((size_t)bh*NCHUNK + c)*SFL;
    #pragma unroll
    for (int ni=0; ni<6; ni++){
        int p = 8*ni + 2*tig;
        int tr = wt0 + gid;
        float* y0 = &g_ys[(size_t)(bt0+tr)*DI + h*HD + p];
        *(float2*)y0            = make_float2(yacc[ni][0], yacc[ni][1]);
        *(float2*)(y0 + 8*DI)   = make_float2(yacc[ni][2], yacc[ni][3]);
        float* s0 = &g_state[sbase + tr*HD + p];
        *(float2*)s0            = make_float2(sacc[ni][0], sacc[ni][1]);
        *(float2*)(s0 + 8*HD)   = make_float2(sacc[ni][2], sacc[ni][3]);
    }
}

// ---------------- SSD pass B ----------------
__global__ __launch_bounds__(128) void ssd_combine_kernel()
{
    int bh = blockIdx.x;
    int b  = bh >> 4;
    int h  = bh & 15;
    int tid = threadIdx.x;
    size_t base = (size_t)bh*NCHUNK*SFL;

    float sin[SFL/128];
    #pragma unroll
    for (int j=0;j<SFL/128;j++) sin[j]=0.f;

    for (int c=0;c<NCHUNK-1;c++){
        float ef = __expf(g_lc[(size_t)(b*LL + c*CLEN + CLEN-1)*NH + h]);
        #pragma unroll
        for (int j=0;j<SFL/128;j++)
            sin[j] = sin[j]*ef + g_state[base + (size_t)c*SFL + j*128 + tid];
        #pragma unroll
        for (int j=0;j<SFL/128;j++)
            g_sin[base + (size_t)(c+1)*SFL + j*128 + tid] = sin[j];
    }
}

// ---------------- SSD pass C ----------------
__global__ __launch_bounds__(128) void ssd_fix_kernel()
{
    int blk = blockIdx.x;
    int bh  = blk / (NCHUNK-1);
    int c   = blk - bh*(NCHUNK-1) + 1;
    int b   = bh >> 4;
    int h   = bh & 15;
    int tid = threadIdx.x;
    int warp = tid >> 5, lane = tid & 31, gid = lane >> 2, tig = lane & 3;
    int bt0 = b*LL + c*CLEN;

    __shared__ float sC2[64*SA_STR];
    __shared__ float sST[48*SA_STR];
    __shared__ float lc2[64];

    for (int i = tid; i < 64*16; i += 128){
        int t = i >> 4, q = (i & 15) << 2;
        float4 vc = *(const float4*)(g_xBC + (size_t)(bt0+t)*CD + DI + DS + q);
        *(float4*)&sC2[t*SA_STR + q] = vc;
    }
    size_t sbase = ((size_t)bh*NCHUNK + c)*SFL;
    for (int i = tid; i < SFL; i += 128){
        int n = i / HD, p = i - n*HD;
        sST[p*SA_STR + n] = g_sin[sbase + i];
    }
    if (tid < 64) lc2[tid] = g_lc[(size_t)(bt0+tid)*NH + h];
    __syncthreads();

    int wt0 = warp*16;
    float facc[6][4];
    #pragma unroll
    for (int ni=0;ni<6;ni++){ facc[ni][0]=facc[ni][1]=facc[ni][2]=facc[ni][3]=0.f; }
    #pragma unroll
    for (int kk=0; kk<64; kk+=8){
        uint32_t af[4];
        af[0] = __float_as_uint(sC2[(wt0+gid  )*SA_STR + kk+tig  ]);
        af[1] = __float_as_uint(sC2[(wt0+gid+8)*SA_STR + kk+tig  ]);
        af[2] = __float_as_uint(sC2[(wt0+gid  )*SA_STR + kk+tig+4]);
        af[3] = __float_as_uint(sC2[(wt0+gid+8)*SA_STR + kk+tig+4]);
        #pragma unroll
        for (int ni=0; ni<6; ni++){
            uint32_t bf[2];
            bf[0] = __float_as_uint(sST[(8*ni+gid)*SA_STR + kk+tig  ]);
            bf[1] = __float_as_uint(sST[(8*ni+gid)*SA_STR + kk+tig+4]);
            mma_tf32(facc[ni], af, bf);
        }
    }

    int tr = wt0 + gid;
    float e0 = __expf(lc2[tr]);
    float e1 = __expf(lc2[tr+8]);
    #pragma unroll
    for (int ni=0; ni<6; ni++){
        int p = 8*ni + 2*tig;
        float2* y0 = (float2*)&g_ys[(size_t)(bt0+tr)*DI + h*HD + p];
        float2 v0 = *y0; v0.x += e0*facc[ni][0]; v0.y += e0*facc[ni][1]; *y0 = v0;
        float2* y1 = (float2*)&g_ys[(size_t)(bt0+tr+8)*DI + h*HD + p];
        float2 v1 = *y1; v1.x += e1*facc[ni][2]; v1.y += e1*facc[ni][3]; *y1 = v1;
    }
}

// ---------------- y = (ys + D*x) * silu(z); RMS-norm -> bf16 split ----------------
__global__ __launch_bounds__(256) void gate_rms_kernel(const float* __restrict__ Dp,
                                                       const float* __restrict__ gnorm)
{
    __shared__ float red[256];
    int row = blockIdx.x, tid = threadIdx.x;
    float v[3]; float ss = 0.f;
    #pragma unroll
    for (int q=0;q<3;q++){
        int i = tid + q*256;
        float ys = g_ys[(size_t)row*DI + i];
        float xv = g_xBC[(size_t)row*CD + i];
        float z  = g_zx [(size_t)row*DIP + i];
        float val = (ys + Dp[i/HD]*xv) * (z / (1.f + __expf(-z)));
        v[q] = val; ss += val*val;
    }
    red[tid] = ss; __syncthreads();
    for (int s=128;s>0;s>>=1){ if(tid<s) red[tid]+=red[tid+s]; __syncthreads(); }
    float scale = rsqrtf(red[0]*(1.0f/DI) + 1e-5f);
    #pragma unroll
    for (int q=0;q<3;q++){
        int i = tid + q*256;
        __nv_bfloat16 h, l;
        bf16_split(v[q]*scale*gnorm[i], h, l);
        g_yh[(size_t)row*DI + i] = h;
        g_yl[(size_t)row*DI + i] = l;
    }
}

// ---------------- pool stage 1 ----------------
__global__ __launch_bounds__(128) void pool1_kernel()
{
    int blk = blockIdx.x;
    int b   = blk >> 4;
    int tc  = blk & 15;
    int tid = threadIdx.x;
    #pragma unroll
    for (int q=0;q<3;q++){
        int d = tid + q*128;
        const float* p = g_h + (size_t)(b*LL + tc*32)*DM + d;
        float s = 0.f;
        #pragma unroll 8
        for (int t=0;t<32;t++) s += p[(size_t)t*DM];
        g_pool[blk*DM + d] = s;
    }
}

// ---------------- pool stage 2 ----------------
__global__ __launch_bounds__(128) void pool2_kernel(const float* __restrict__ w,
                                                    const float* __restrict__ b2)
{
    __shared__ float red[128];
    int b = blockIdx.x, tid = threadIdx.x;
    float v[3];
    #pragma unroll
    for (int q=0;q<3;q++){
        int d = tid + q*128;
        float s = 0.f;
        #pragma unroll
        for (int tc=0;tc<16;tc++) s += g_pool[(b*16+tc)*DM + d];
        v[q] = s * (1.0f/LL);
    }
    red[tid] = v[0]+v[1]+v[2]; __syncthreads();
    for (int s=64;s>0;s>>=1){ if(tid<s) red[tid]+=red[tid+s]; __syncthreads(); }
    float mu = red[0]*(1.0f/DM);
    __syncthreads();
    float d0=v[0]-mu, d1=v[1]-mu, d2=v[2]-mu;
    red[tid] = d0*d0+d1*d1+d2*d2; __syncthreads();
    for (int s=64;s>0;s>>=1){ if(tid<s) red[tid]+=red[tid+s]; __syncthreads(); }
    float inv = rsqrtf(red[0]*(1.0f/DM) + 1e-5f);
    g_featT[(tid    )*BB + b] = d0*inv*w[tid]     + b2[tid];
    g_featT[(tid+128)*BB + b] = d1*inv*w[tid+128] + b2[tid+128];
    g_featT[(tid+256)*BB + b] = d2*inv*w[tid+256] + b2[tid+256];
}

// ---------------- classification heads ----------------
__global__ __launch_bounds__(256) void heads_kernel(
    const float* __restrict__ ow, const float* __restrict__ ob,
    const float* __restrict__ fw, const float* __restrict__ fb,
    const float* __restrict__ gw, const float* __restrict__ gb,
    const float* __restrict__ sw, const float* __restrict__ sb,
    float* __restrict__ out)
{
    __shared__ __align__(16) float sf[DM*BB];
    int tid = threadIdx.x;
    for (int i = tid; i < DM*BB; i += blockDim.x) sf[i] = g_featT[i];
    __syncthreads();

    int j = blockIdx.x * blockDim.x + tid;
    if (j >= NOUT) return;

    const float* W; const float* Bv; int jj, Nseg;
    if (j < N_ORDER)                      { W=ow; Bv=ob; jj=j;                     Nseg=N_ORDER; }
    else if (j < N_ORDER+N_FAMILY)        { W=fw; Bv=fb; jj=j-N_ORDER;             Nseg=N_FAMILY; }
    else if (j < N_ORDER+N_FAMILY+N_GENUS){ W=gw; Bv=gb; jj=j-N_ORDER-N_FAMILY;    Nseg=N_GENUS; }
    else                                  { W=sw; Bv=sb; jj=j-N_ORDER-N_FAMILY-N_GENUS; Nseg=N_SPECIES; }

    float acc[BB];
    #pragma unroll
    for (int b=0;b<BB;b++) acc[b]=0.f;
    for (int k=0;k<DM;k++){
        float wv = W[(size_t)k*Nseg + jj];
        const float4* row = (const float4*)&sf[k*BB];
        #pragma unroll
        for (int bq=0;bq<8;bq++){
            float4 f = row[bq];
            acc[4*bq+0] = fmaf(f.x, wv, acc[4*bq+0]);
            acc[4*bq+1] = fmaf(f.y, wv, acc[4*bq+1]);
            acc[4*bq+2] = fmaf(f.z, wv, acc[4*bq+2]);
            acc[4*bq+3] = fmaf(f.w, wv, acc[4*bq+3]);
        }
    }
    float bias = Bv[jj];
    #pragma unroll
    for (int b=0;b<BB;b++) out[(size_t)b*NOUT + j] = acc[b] + bias;
}

// ---------------- orchestration ----------------
extern "C" void kernel_launch(void* const* d_in, const int* in_sizes, int n_in,
                              void* d_out, int out_size)
{
    const int*   tokens = (const int*)  d_in[0];
    const float* emb    = (const float*)d_in[1];
    const float* ln_w   = (const float*)d_in[2];
    const float* ln_b   = (const float*)d_in[3];
    const float* Win    = (const float*)d_in[4];
    const float* cw     = (const float*)d_in[5];
    const float* cb     = (const float*)d_in[6];
    const float* dtb    = (const float*)d_in[7];
    const float* alog   = (const float*)d_in[8];
    const float* Dd     = (const float*)d_in[9];
    const float* gnw    = (const float*)d_in[10];
    const float* Wout   = (const float*)d_in[11];
    const float* nfw    = (const float*)d_in[12];
    const float* nfb    = (const float*)d_in[13];
    const float* plw    = (const float*)d_in[14];
    const float* plb    = (const float*)d_in[15];
    const float* ow     = (const float*)d_in[16];
    const float* ob     = (const float*)d_in[17];
    const float* fw     = (const float*)d_in[18];
    const float* fb     = (const float*)d_in[19];
    const float* gw     = (const float*)d_in[20];
    const float* gb     = (const float*)d_in[21];
    const float* sw     = (const float*)d_in[22];
    const float* sb     = (const float*)d_in[23];
    float* out = (float*)d_out;

    cudaFuncSetAttribute((const void*)gemm_bf<0,1>, cudaFuncAttributeMaxDynamicSharedMemorySize, SMEM2_BYTES);
    cudaFuncSetAttribute((const void*)gemm_bf<1,2>, cudaFuncAttributeMaxDynamicSharedMemorySize, SMEM2_BYTES);
    cudaFuncSetAttribute((const void*)ssd_local_kernel, cudaFuncAttributeMaxDynamicSharedMemorySize, SSD_A_SMEM);

    wcvt_t_kernel<<<dim3((DIP+31)/32, (DI+31)/32, 4), 256>>>(Win, Wout);
    embed_ln_kernel<<<NT, 128>>>(tokens, emb, ln_w, ln_b);

    for (int l = 0; l < 2; l++) {
        if (l > 0) ln_kernel<<<NT, 128>>>(ln_w + l*DM, ln_b + l*DM, 1);
        gemm_bf<0,1><<<dim3((DIP+127)/128, NT/128, 1), 256, SMEM2_BYTES>>>(l);
        conv_dtda_kernel<<<CONV_BLKS + DTDA_BLKS, 224>>>(cw + (size_t)l*CD*4, cb + l*CD,
                                                         dtb + l*NH, alog + l*NH);
        ssd_local_kernel  <<<BB*NH*NCHUNK, 128, SSD_A_SMEM>>>();
        ssd_combine_kernel<<<BB*NH, 128>>>();
        ssd_fix_kernel    <<<BB*NH*(NCHUNK-1), 128>>>();
        gate_rms_kernel<<<NT, 256>>>(Dd + l*NH, gnw + l*DI);
        gemm_bf<1,2><<<dim3((DM+127)/128, NT/128, 2), 256, SMEM2_BYTES>>>(l);
    }

    ln_kernel<<<NT, 128>>>(nfw, nfb, 0);
    pool1_kernel<<<BB*16, 128>>>();
    pool2_kernel<<<BB, 128>>>(plw, plb);
    heads_kernel<<<(NOUT + 255)/256, 256>>>(ow, ob, fw, fb, gw, gb, sw, sb, out);
}

// round 12
// speedup vs baseline: 1.1875x; 1.1875x over previous
#include <cuda_runtime.h>
#include <math.h>
#include <stddef.h>
#include <stdint.h>

typedef unsigned long long ull;

// ---------------- problem constants ----------------
#define BB   32
#define LL   512
#define DM   384
#define DI   768
#define DS   64
#define NH   16
#define HD   48
#define DIP  1680
#define CD   896
#define NT   (BB*LL)
#define NOUT 38667
#define N_ORDER 60
#define N_FAMILY 427
#define N_GENUS 14216
#define N_SPECIES 23964

#define WIN1  (DM*DIP)
#define WOUT1 (DI*DM)

#define NCHUNK 8
#define CLEN   64
#define SFL    3072          // DS*HD floats per (b,h,chunk) state

// k-permutation within each 8-group: pos = k<4 ? 2k : 2(k-4)+1
__device__ __forceinline__ int kperm(int k){
    int j = k & 7;
    return (k & ~7) | ((j<4) ? (j<<1) : (((j-4)<<1)|1));
}

// ---------------- scratch ----------------
__device__ float g_resid[(size_t)NT*DM];
__device__ float g_h    [(size_t)NT*DM];
__device__ float g_zx   [(size_t)NT*DIP];
__device__ float g_xBC  [(size_t)NT*CD];
__device__ float g_dt   [(size_t)NT*NH];
__device__ float g_dA   [(size_t)NT*NH];    // stores log(dA) = -exp(A_log)*dt
__device__ float g_lc   [(size_t)NT*NH];    // chunk-local cumsum of log dA
__device__ float g_ys   [(size_t)NT*DI];
__device__ float g_yn   [(size_t)NT*DI];
__device__ float g_wtB  [2*WIN1 + 2*WOUT1];
__device__ float g_state[(size_t)BB*NH*NCHUNK*SFL];
__device__ float g_sin  [(size_t)BB*NH*NCHUNK*SFL];
__device__ float g_pool [BB*16*DM];
__device__ float g_featT[DM*BB];

__device__ __forceinline__ uint32_t f2tf(float x){
    uint32_t y;
    asm volatile("cvt.rna.tf32.f32 %0, %1;" : "=r"(y) : "f"(x));
    return y;
}
__device__ __forceinline__ void upk2u(uint32_t& lo, uint32_t& hi, ull v){
    asm("mov.b64 {%0, %1}, %2;" : "=r"(lo), "=r"(hi) : "l"(v));
}

// ---------------- weight transpose + permute + tf32 convert ----------------
__global__ __launch_bounds__(256) void wcvt_t_kernel(const float* __restrict__ Win,
                                                     const float* __restrict__ Wout)
{
    int r = blockIdx.z;
    const float* src; float* dst; int K_, N_;
    if (r < 2){ src = Win  + (size_t)r*WIN1;      dst = g_wtB + (size_t)r*WIN1;              K_ = DM; N_ = DIP; }
    else      { src = Wout + (size_t)(r-2)*WOUT1; dst = g_wtB + 2*WIN1 + (size_t)(r-2)*WOUT1; K_ = DI; N_ = DM; }
    int k0 = blockIdx.y*32, n0 = blockIdx.x*32;
    if (k0 >= K_ || n0 >= N_) return;
    __shared__ float sm[32][33];
    int tx = threadIdx.x & 31, ty = threadIdx.x >> 5;
    #pragma unroll
    for (int q=0;q<4;q++){
        int k = k0 + ty + q*8;
        if (k < K_ && n0+tx < N_) sm[ty+q*8][tx] = src[(size_t)k*N_ + n0+tx];
    }
    __syncthreads();
    #pragma unroll
    for (int q=0;q<4;q++){
        int n = n0 + ty + q*8;
        int k = k0 + tx;
        if (n < N_ && k < K_)
            dst[(size_t)n*K_ + kperm(k)] = __uint_as_float(f2tf(sm[tx][ty+q*8]));
    }
}

// ---------------- fused embedding + layer-0 layernorm (k-permuted) ----------------
__global__ __launch_bounds__(128) void embed_ln_kernel(const int* __restrict__ tokens,
                                                       const float* __restrict__ emb,
                                                       const float* __restrict__ w,
                                                       const float* __restrict__ b)
{
    __shared__ float red[128];
    int row = blockIdx.x, tid = threadIdx.x;
    const float* er = emb + (size_t)tokens[row]*DM;
    float v0 = er[tid], v1 = er[tid+128], v2 = er[tid+256];
    float* rr = g_resid + (size_t)row*DM;
    rr[tid] = v0; rr[tid+128] = v1; rr[tid+256] = v2;

    red[tid] = v0+v1+v2; __syncthreads();
    for (int s=64;s>0;s>>=1){ if(tid<s) red[tid]+=red[tid+s]; __syncthreads(); }
    float mu = red[0] * (1.0f/DM);
    __syncthreads();
    float d0=v0-mu, d1=v1-mu, d2=v2-mu;
    red[tid] = d0*d0+d1*d1+d2*d2; __syncthreads();
    for (int s=64;s>0;s>>=1){ if(tid<s) red[tid]+=red[tid+s]; __syncthreads(); }
    float inv = rsqrtf(red[0]*(1.0f/DM) + 1e-5f);
    float* o = g_h + (size_t)row*DM;
    o[kperm(tid)]     = __uint_as_float(f2tf(d0*inv*w[tid]     + b[tid]));
    o[kperm(tid+128)] = __uint_as_float(f2tf(d1*inv*w[tid+128] + b[tid+128]));
    o[kperm(tid+256)] = __uint_as_float(f2tf(d2*inv*w[tid+256] + b[tid+256]));
}

// ---------------- layernorm: g_resid -> g_h ----------------
__global__ __launch_bounds__(128) void ln_kernel(const float* __restrict__ w, const float* __restrict__ b, int tf)
{
    __shared__ float red[128];
    int row = blockIdx.x, tid = threadIdx.x;
    const float* xr = g_resid + (size_t)row*DM;
    float v0 = xr[tid], v1 = xr[tid+128], v2 = xr[tid+256];
    red[tid] = v0+v1+v2; __syncthreads();
    for (int s=64;s>0;s>>=1){ if(tid<s) red[tid]+=red[tid+s]; __syncthreads(); }
    float mu = red[0] * (1.0f/DM);
    __syncthreads();
    float d0=v0-mu, d1=v1-mu, d2=v2-mu;
    red[tid] = d0*d0+d1*d1+d2*d2; __syncthreads();
    for (int s=64;s>0;s>>=1){ if(tid<s) red[tid]+=red[tid+s]; __syncthreads(); }
    float inv = rsqrtf(red[0]*(1.0f/DM) + 1e-5f);
    float o0 = d0*inv*w[tid]     + b[tid];
    float o1 = d1*inv*w[tid+128] + b[tid+128];
    float o2 = d2*inv*w[tid+256] + b[tid+256];
    float* o = g_h + (size_t)row*DM;
    if (tf){
        o[kperm(tid)]     = __uint_as_float(f2tf(o0));
        o[kperm(tid+128)] = __uint_as_float(f2tf(o1));
        o[kperm(tid+256)] = __uint_as_float(f2tf(o2));
    } else {
        o[tid] = o0; o[tid+128] = o1; o[tid+256] = o2;
    }
}

// ---------------- tf32 mma helper ----------------
__device__ __forceinline__ void mma_tf32(float* c, const uint32_t* a, const uint32_t* b){
    asm volatile(
      "mma.sync.aligned.m16n8k8.row.col.f32.tf32.tf32.f32 "
      "{%0,%1,%2,%3}, {%4,%5,%6,%7}, {%8,%9}, {%0,%1,%2,%3};\n"
      : "+f"(c[0]), "+f"(c[1]), "+f"(c[2]), "+f"(c[3])
      : "r"(a[0]), "r"(a[1]), "r"(a[2]), "r"(a[3]), "r"(b[0]), "r"(b[1]));
}

// ---------------- tf32 tensor-core GEMM (R8-proven) ----------------
#define GBM 128
#define GBN 128
#define GBK 16
#define NSTAGE 4
#define TSTR 24
#define AS_FLOATS (GBM*TSTR)
#define BS_FLOATS (GBN*TSTR)
#define SMEM_FLOATS (NSTAGE*(AS_FLOATS+BS_FLOATS))

template<int MODE, int SPLITK>
__global__ __launch_bounds__(256,2) void gemm_tc(int layer)
{
    const float* __restrict__ A = (MODE==0) ? g_h : g_yn;
    const float* __restrict__ W = (MODE==0) ? (g_wtB + (size_t)layer*WIN1)
                                            : (g_wtB + 2*WIN1 + (size_t)layer*WOUT1);
    float* C = (MODE==0) ? g_zx : g_resid;
    const int N = (MODE==0) ? DIP : DM;
    const int K = (MODE==0) ? DM  : DI;
    const int Ks = K / SPLITK;
    const int k_origin = blockIdx.z * Ks;

    extern __shared__ float sh[];
    float* shB = sh + NSTAGE*AS_FLOATS;

    int tid  = threadIdx.x;
    int warp = tid >> 5;
    int lane = tid & 31;
    int gid  = lane >> 2;
    int tig  = lane & 3;

    int m0 = blockIdx.y * GBM;
    int n0 = blockIdx.x * GBN;
    int wm = (warp & 1) * 64;
    int wn = (warp >> 1) * 32;

    float acc[4][4][4];
    #pragma unroll
    for (int i=0;i<4;i++)
        #pragma unroll
        for (int j=0;j<4;j++)
            #pragma unroll
            for (int q=0;q<4;q++) acc[i][j][q]=0.f;

    const int niter = Ks / GBK;

    int row0 = tid >> 2,        kc0 = (tid & 3) << 2;
    int row1 = (tid+256) >> 2,  kc1 = (tid & 3) << 2;
    int b_ok0 = (n0 + row0 < N) ? 16 : 0;
    int b_ok1 = (n0 + row1 < N) ? 16 : 0;
    const float* asrc0 = A + (size_t)(m0 + row0)*K + k_origin + kc0;
    const float* asrc1 = A + (size_t)(m0 + row1)*K + k_origin + kc1;
    const float* bsrc0 = W + (size_t)((n0 + row0 < N) ? (n0 + row0) : 0)*K + k_origin + kc0;
    const float* bsrc1 = W + (size_t)((n0 + row1 < N) ? (n0 + row1) : 0)*K + k_origin + kc1;

    uint32_t adst0 = (uint32_t)__cvta_generic_to_shared(&sh [row0*TSTR + kc0]);
    uint32_t adst1 = (uint32_t)__cvta_generic_to_shared(&sh [row1*TSTR + kc1]);
    uint32_t bdst0 = (uint32_t)__cvta_generic_to_shared(&shB[row0*TSTR + kc0]);
    uint32_t bdst1 = (uint32_t)__cvta_generic_to_shared(&shB[row1*TSTR + kc1]);

    auto issue_copy = [&](int st, int it){
        int k0 = it * GBK;
        uint32_t ao = st*AS_FLOATS*4, bo = st*BS_FLOATS*4;
        asm volatile("cp.async.cg.shared.global [%0], [%1], 16;\n"
                     :: "r"(adst0 + ao), "l"(asrc0 + k0));
        asm volatile("cp.async.cg.shared.global [%0], [%1], 16;\n"
                     :: "r"(adst1 + ao), "l"(asrc1 + k0));
        asm volatile("cp.async.cg.shared.global [%0], [%1], 16, %2;\n"
                     :: "r"(bdst0 + bo), "l"(bsrc0 + k0), "r"(b_ok0));
        asm volatile("cp.async.cg.shared.global [%0], [%1], 16, %2;\n"
                     :: "r"(bdst1 + bo), "l"(bsrc1 + k0), "r"(b_ok1));
    };

    #pragma unroll
    for (int st=0; st<NSTAGE-1; st++){
        if (st < niter) issue_copy(st, st);
        asm volatile("cp.async.commit_group;\n");
    }

    for (int it=0; it<niter; ++it){
        asm volatile("cp.async.wait_group %0;\n" :: "n"(NSTAGE-2));
        __syncthreads();

        int cb = it & (NSTAGE-1);
        const float* Asb = &sh [cb*AS_FLOATS];
        const float* Bsb = &shB[cb*BS_FLOATS];

        #pragma unroll
        for (int ks=0; ks<GBK; ks+=8){
            uint32_t af[4][4], bf[4][2];
            #pragma unroll
            for (int mi=0; mi<4; mi++){
                int mr = wm + 16*mi;
                ull lo8 = *(const ull*)&Asb[(mr+gid  )*TSTR + ks + 2*tig];
                ull hi8 = *(const ull*)&Asb[(mr+gid+8)*TSTR + ks + 2*tig];
                upk2u(af[mi][0], af[mi][2], lo8);
                upk2u(af[mi][1], af[mi][3], hi8);
            }
            #pragma unroll
            for (int ni=0; ni<4; ni++){
                int nb = wn + 8*ni;
                ull bb = *(const ull*)&Bsb[(nb+gid)*TSTR + ks + 2*tig];
                upk2u(bf[ni][0], bf[ni][1], bb);
            }
            #pragma unroll
            for (int mi=0; mi<4; mi++)
                #pragma unroll
                for (int ni=0; ni<4; ni++)
                    mma_tf32(acc[mi][ni], af[mi], bf[ni]);
        }

        int nx = it + NSTAGE - 1;
        if (nx < niter) issue_copy(nx & (NSTAGE-1), nx);
        asm volatile("cp.async.commit_group;\n");
    }

    #pragma unroll
    for (int mi=0; mi<4; mi++){
        int r0 = m0 + wm + 16*mi + gid;
        #pragma unroll
        for (int ni=0; ni<4; ni++){
            int c0 = n0 + wn + 8*ni + 2*tig;
            float* a = acc[mi][ni];
            #pragma unroll
            for (int half=0; half<2; half++){
                int cc = c0 + half;
                if (cc < N){
                    size_t i0 = (size_t)r0*N + cc;
                    size_t i2 = (size_t)(r0+8)*N + cc;
                    if (MODE){ atomicAdd(&C[i0], a[half]); atomicAdd(&C[i2], a[2+half]); }
                    else     { C[i0] = a[half]; C[i2] = a[2+half]; }
                }
            }
        }
    }
}

// ---------------- fused conv (8-step chunks) + dt/logdA ----------------
#define CONV_BLKS (BB*64)
#define DTDA_TOT  (NT*(NH/4))
#define DTDA_BLKS ((DTDA_TOT + 223)/224)
__global__ __launch_bounds__(224) void conv_dtda_kernel(const float* __restrict__ cw, const float* __restrict__ cb,
                                                        const float* __restrict__ dtb, const float* __restrict__ alog)
{
    int blk = blockIdx.x;
    int tid = threadIdx.x;
    if (blk < CONV_BLKS){
        int b  = blk >> 6;
        int tc = blk & 63;
        int t0 = tc * 8;
        int c  = tid << 2;

        float4 tw[4];
        #pragma unroll
        for (int k=0;k<4;k++){
            tw[k].x = cw[(c+0)*4+k];
            tw[k].y = cw[(c+1)*4+k];
            tw[k].z = cw[(c+2)*4+k];
            tw[k].w = cw[(c+3)*4+k];
        }
        float4 bias = *(const float4*)&cb[c];

        const float* base = g_zx + (size_t)(b*LL + t0)*DIP + DI + c;
        float* obase = g_xBC + (size_t)(b*LL + t0)*CD + c;

        float4 p1, p2, p3;
        if (t0 > 0){
            p1 = *(const float4*)(base - 3*DIP);
            p2 = *(const float4*)(base - 2*DIP);
            p3 = *(const float4*)(base - 1*DIP);
        } else {
            p1 = p2 = p3 = make_float4(0.f,0.f,0.f,0.f);
        }

        #pragma unroll
        for (int i=0;i<8;i++){
            float4 v = *(const float4*)(base + (size_t)i*DIP);
            float4 a;
            a.x = bias.x + p1.x*tw[0].x + p2.x*tw[1].x + p3.x*tw[2].x + v.x*tw[3].x;
            a.y = bias.y + p1.y*tw[0].y + p2.y*tw[1].y + p3.y*tw[2].y + v.y*tw[3].y;
            a.z = bias.z + p1.z*tw[0].z + p2.z*tw[1].z + p3.z*tw[2].z + v.z*tw[3].z;
            a.w = bias.w + p1.w*tw[0].w + p2.w*tw[1].w + p3.w*tw[2].w + v.w*tw[3].w;
            float4 r;
            r.x = a.x / (1.f + __expf(-a.x));
            r.y = a.y / (1.f + __expf(-a.y));
            r.z = a.z / (1.f + __expf(-a.z));
            r.w = a.w / (1.f + __expf(-a.w));
            *(float4*)(obase + (size_t)i*CD) = r;
            p1 = p2; p2 = p3; p3 = v;
        }
    } else {
        int j = (blk - CONV_BLKS)*224 + tid;
        if (j >= DTDA_TOT) return;
        int hq = (j & 3) << 2;
        int bt = j >> 2;
        #pragma unroll
        for (int q=0;q<4;q++){
            int hh = hq + q;
            float raw = g_zx[(size_t)bt*DIP + (DIP-NH) + hh] + dtb[hh];
            float sp = (raw > 20.f) ? raw : log1pf(expf(raw));
            g_dt[bt*NH + hh] = sp;
            g_dA[bt*NH + hh] = -expf(alog[hh]) * sp;    // log(dA)
        }
    }
}

// ---------------- SSD scan pass A: per (b,h,chunk) tensor-core local scan ----------------
#define SA_STR 68
#define SSD_A_SMEM ((3*64*SA_STR + 2*48*SA_STR + 192)*4)

__global__ __launch_bounds__(128) void ssd_local_kernel()
{
    int blk = blockIdx.x;           // BB*NH*NCHUNK
    int c  = blk & (NCHUNK-1);
    int bh = blk >> 3;
    int b  = bh >> 4;
    int h  = bh & 15;
    int tid = threadIdx.x;
    int warp = tid >> 5, lane = tid & 31, gid = lane >> 2, tig = lane & 3;
    int bt0 = b*LL + c*CLEN;

    extern __shared__ float sa[];
    float* sC   = sa;
    float* sBW  = sC  + 64*SA_STR;
    float* sBT  = sBW + 64*SA_STR;
    float* sXT  = sBT + 64*SA_STR;
    float* sXwT = sXT + 48*SA_STR;
    float* lc_sh = sXwT + 48*SA_STR;
    float* dt_sh = lc_sh + 64;
    float* w2_sh = dt_sh + 64;

    for (int i = tid; i < 64*16; i += 128){
        int t = i >> 4, q = (i & 15) << 2;
        const float* row = g_xBC + (size_t)(bt0+t)*CD + DI;
        float4 vb = *(const float4*)(row + q);
        float4 vc = *(const float4*)(row + DS + q);
        *(float4*)&sBW[t*SA_STR + q] = vb;
        *(float4*)&sC [t*SA_STR + q] = vc;
        sBT[(q+0)*SA_STR + t] = vb.x;
        sBT[(q+1)*SA_STR + t] = vb.y;
        sBT[(q+2)*SA_STR + t] = vb.z;
        sBT[(q+3)*SA_STR + t] = vb.w;
    }
    for (int i = tid; i < 64*12; i += 128){
        int t = i / 12, q = (i % 12) << 2;
        float4 vx = *(const float4*)(g_xBC + (size_t)(bt0+t)*CD + h*HD + q);
        sXT[(q+0)*SA_STR + t] = vx.x;
        sXT[(q+1)*SA_STR + t] = vx.y;
        sXT[(q+2)*SA_STR + t] = vx.z;
        sXT[(q+3)*SA_STR + t] = vx.w;
    }
    if (tid < 64) dt_sh[tid] = g_dt[(size_t)(bt0+tid)*NH + h];
    if (warp == 0){
        float v0 = g_dA[(size_t)(bt0+lane)*NH + h];
        float v1 = g_dA[(size_t)(bt0+32+lane)*NH + h];
        #pragma unroll
        for (int d=1; d<32; d<<=1){
            float u0 = __shfl_up_sync(0xffffffffu, v0, d);
            float u1 = __shfl_up_sync(0xffffffffu, v1, d);
            if (lane >= d){ v0 += u0; v1 += u1; }
        }
        float tot = __shfl_sync(0xffffffffu, v0, 31);
        v1 += tot;
        lc_sh[lane]    = v0;
        lc_sh[32+lane] = v1;
        g_lc[(size_t)(bt0+lane)*NH + h]    = v0;
        g_lc[(size_t)(bt0+32+lane)*NH + h] = v1;
    }
    __syncthreads();

    int wt0 = warp*16;
    float gacc[8][4];
    #pragma unroll
    for (int ni=0;ni<8;ni++){ gacc[ni][0]=0.f; gacc[ni][1]=0.f; gacc[ni][2]=0.f; gacc[ni][3]=0.f; }
    #pragma unroll
    for (int kk=0; kk<64; kk+=8){
        uint32_t af[4];
        af[0] = __float_as_uint(sC[(wt0+gid  )*SA_STR + kk+tig  ]);
        af[1] = __float_as_uint(sC[(wt0+gid+8)*SA_STR + kk+tig  ]);
        af[2] = __float_as_uint(sC[(wt0+gid  )*SA_STR + kk+tig+4]);
        af[3] = __float_as_uint(sC[(wt0+gid+8)*SA_STR + kk+tig+4]);
        #pragma unroll
        for (int ni=0; ni<8; ni++){
            uint32_t bf[2];
            bf[0] = __float_as_uint(sBW[(8*ni+gid)*SA_STR + kk+tig  ]);
            bf[1] = __float_as_uint(sBW[(8*ni+gid)*SA_STR + kk+tig+4]);
            mma_tf32(gacc[ni], af, bf);
        }
    }
    if (tid < 64) w2_sh[tid] = __expf(lc_sh[63] - lc_sh[tid]) * dt_sh[tid];
    __syncthreads();

    {
        int t0r = wt0 + gid, t1r = t0r + 8;
        float lct0 = lc_sh[t0r], lct1 = lc_sh[t1r];
        #pragma unroll
        for (int ni=0; ni<8; ni++){
            int s0 = 8*ni + 2*tig, s1 = s0 + 1;
            float lcs0 = lc_sh[s0], lcs1 = lc_sh[s1];
            float d0 = dt_sh[s0],   d1 = dt_sh[s1];
            sBW[t0r*SA_STR + s0] = (s0<=t0r) ? gacc[ni][0]*__expf(lct0-lcs0)*d0 : 0.f;
            sBW[t0r*SA_STR + s1] = (s1<=t0r) ? gacc[ni][1]*__expf(lct0-lcs1)*d1 : 0.f;
            sBW[t1r*SA_STR + s0] = (s0<=t1r) ? gacc[ni][2]*__expf(lct1-lcs0)*d0 : 0.f;
            sBW[t1r*SA_STR + s1] = (s1<=t1r) ? gacc[ni][3]*__expf(lct1-lcs1)*d1 : 0.f;
        }
    }
    for (int i = tid; i < 48*64; i += 128){
        int p = i >> 6, s = i & 63;
        sXwT[p*SA_STR + s] = sXT[p*SA_STR + s] * w2_sh[s];
    }
    __syncthreads();

    float yacc[6][4], sacc[6][4];
    #pragma unroll
    for (int ni=0;ni<6;ni++){
        yacc[ni][0]=yacc[ni][1]=yacc[ni][2]=yacc[ni][3]=0.f;
        sacc[ni][0]=sacc[ni][1]=sacc[ni][2]=sacc[ni][3]=0.f;
    }
    #pragma unroll
    for (int kk=0; kk<64; kk+=8){
        uint32_t afW[4], afB[4];
        afW[0] = __float_as_uint(sBW[(wt0+gid  )*SA_STR + kk+tig  ]);
        afW[1] = __float_as_uint(sBW[(wt0+gid+8)*SA_STR + kk+tig  ]);
        afW[2] = __float_as_uint(sBW[(wt0+gid  )*SA_STR + kk+tig+4]);
        afW[3] = __float_as_uint(sBW[(wt0+gid+8)*SA_STR + kk+tig+4]);
        afB[0] = __float_as_uint(sBT[(wt0+gid  )*SA_STR + kk+tig  ]);
        afB[1] = __float_as_uint(sBT[(wt0+gid+8)*SA_STR + kk+tig  ]);
        afB[2] = __float_as_uint(sBT[(wt0+gid  )*SA_STR + kk+tig+4]);
        afB[3] = __float_as_uint(sBT[(wt0+gid+8)*SA_STR + kk+tig+4]);
        #pragma unroll
        for (int ni=0; ni<6; ni++){
            uint32_t bfX[2], bfW2[2];
            bfX[0]  = __float_as_uint(sXT [(8*ni+gid)*SA_STR + kk+tig  ]);
            bfX[1]  = __float_as_uint(sXT [(8*ni+gid)*SA_STR + kk+tig+4]);
            mma_tf32(yacc[ni], afW, bfX);
            bfW2[0] = __float_as_uint(sXwT[(8*ni+gid)*SA_STR + kk+tig  ]);
            bfW2[1] = __float_as_uint(sXwT[(8*ni+gid)*SA_STR + kk+tig+4]);
            mma_tf32(sacc[ni], afB, bfW2);
        }
    }

    size_t sbase = ((size_t)bh*NCHUNK + c)*SFL;
    #pragma unroll
    for (int ni=0; ni<6; ni++){
        int p = 8*ni + 2*tig;
        int tr = wt0 + gid;
        float* y0 = &g_ys[(size_t)(bt0+tr)*DI + h*HD + p];
        *(float2*)y0            = make_float2(yacc[ni][0], yacc[ni][1]);
        *(float2*)(y0 + 8*DI)   = make_float2(yacc[ni][2], yacc[ni][3]);
        float* s0 = &g_state[sbase + tr*HD + p];
        *(float2*)s0            = make_float2(sacc[ni][0], sacc[ni][1]);
        *(float2*)(s0 + 8*HD)   = make_float2(sacc[ni][2], sacc[ni][3]);
    }
}

// ---------------- SSD pass B: sequential chunk-state combine ----------------
__global__ __launch_bounds__(128) void ssd_combine_kernel()
{
    int bh = blockIdx.x;
    int b  = bh >> 4;
    int h  = bh & 15;
    int tid = threadIdx.x;
    size_t base = (size_t)bh*NCHUNK*SFL;

    float sin[SFL/128];
    #pragma unroll
    for (int j=0;j<SFL/128;j++) sin[j]=0.f;

    for (int c=0;c<NCHUNK-1;c++){
        float ef = __expf(g_lc[(size_t)(b*LL + c*CLEN + CLEN-1)*NH + h]);
        #pragma unroll
        for (int j=0;j<SFL/128;j++)
            sin[j] = sin[j]*ef + g_state[base + (size_t)c*SFL + j*128 + tid];
        #pragma unroll
        for (int j=0;j<SFL/128;j++)
            g_sin[base + (size_t)(c+1)*SFL + j*128 + tid] = sin[j];
    }
}

// ---------------- SSD pass C: y += exp(lc_t) * (C @ S_in) ----------------
__global__ __launch_bounds__(128) void ssd_fix_kernel()
{
    int blk = blockIdx.x;
    int bh  = blk / (NCHUNK-1);
    int c   = blk - bh*(NCHUNK-1) + 1;
    int b   = bh >> 4;
    int h   = bh & 15;
    int tid = threadIdx.x;
    int warp = tid >> 5, lane = tid & 31, gid = lane >> 2, tig = lane & 3;
    int bt0 = b*LL + c*CLEN;

    __shared__ float sC2[64*SA_STR];
    __shared__ float sST[48*SA_STR];
    __shared__ float lc2[64];

    for (int i = tid; i < 64*16; i += 128){
        int t = i >> 4, q = (i & 15) << 2;
        float4 vc = *(const float4*)(g_xBC + (size_t)(bt0+t)*CD + DI + DS + q);
        *(float4*)&sC2[t*SA_STR + q] = vc;
    }
    size_t sbase = ((size_t)bh*NCHUNK + c)*SFL;
    for (int i = tid; i < SFL; i += 128){
        int n = i / HD, p = i - n*HD;
        sST[p*SA_STR + n] = g_sin[sbase + i];
    }
    if (tid < 64) lc2[tid] = g_lc[(size_t)(bt0+tid)*NH + h];
    __syncthreads();

    int wt0 = warp*16;
    float facc[6][4];
    #pragma unroll
    for (int ni=0;ni<6;ni++){ facc[ni][0]=facc[ni][1]=facc[ni][2]=facc[ni][3]=0.f; }
    #pragma unroll
    for (int kk=0; kk<64; kk+=8){
        uint32_t af[4];
        af[0] = __float_as_uint(sC2[(wt0+gid  )*SA_STR + kk+tig  ]);
        af[1] = __float_as_uint(sC2[(wt0+gid+8)*SA_STR + kk+tig  ]);
        af[2] = __float_as_uint(sC2[(wt0+gid  )*SA_STR + kk+tig+4]);
        af[3] = __float_as_uint(sC2[(wt0+gid+8)*SA_STR + kk+tig+4]);
        #pragma unroll
        for (int ni=0; ni<6; ni++){
            uint32_t bf[2];
            bf[0] = __float_as_uint(sST[(8*ni+gid)*SA_STR + kk+tig  ]);
            bf[1] = __float_as_uint(sST[(8*ni+gid)*SA_STR + kk+tig+4]);
            mma_tf32(facc[ni], af, bf);
        }
    }

    int tr = wt0 + gid;
    float e0 = __expf(lc2[tr]);
    float e1 = __expf(lc2[tr+8]);
    #pragma unroll
    for (int ni=0; ni<6; ni++){
        int p = 8*ni + 2*tig;
        float2* y0 = (float2*)&g_ys[(size_t)(bt0+tr)*DI + h*HD + p];
        float2 v0 = *y0; v0.x += e0*facc[ni][0]; v0.y += e0*facc[ni][1]; *y0 = v0;
        float2* y1 = (float2*)&g_ys[(size_t)(bt0+tr+8)*DI + h*HD + p];
        float2 v1 = *y1; v1.x += e1*facc[ni][2]; v1.y += e1*facc[ni][3]; *y1 = v1;
    }
}

// ---------------- y = (ys + D*x) * silu(z); RMS-norm -> g_yn (tf32, k-permuted) ----------------
__global__ __launch_bounds__(256) void gate_rms_kernel(const float* __restrict__ Dp,
                                                       const float* __restrict__ gnorm)
{
    __shared__ float red[256];
    int row = blockIdx.x, tid = threadIdx.x;
    float v[3]; float ss = 0.f;
    #pragma unroll
    for (int q=0;q<3;q++){
        int i = tid + q*256;
        float ys = g_ys[(size_t)row*DI + i];
        float xv = g_xBC[(size_t)row*CD + i];
        float z  = g_zx [(size_t)row*DIP + i];
        float val = (ys + Dp[i/HD]*xv) * (z / (1.f + __expf(-z)));
        v[q] = val; ss += val*val;
    }
    red[tid] = ss; __syncthreads();
    for (int s=128;s>0;s>>=1){ if(tid<s) red[tid]+=red[tid+s]; __syncthreads(); }
    float scale = rsqrtf(red[0]*(1.0f/DI) + 1e-5f);
    #pragma unroll
    for (int q=0;q<3;q++){
        int i = tid + q*256;
        g_yn[(size_t)row*DI + kperm(i)] = __uint_as_float(f2tf(v[q]*scale*gnorm[i]));
    }
}

// ---------------- pool stage 1 ----------------
__global__ __launch_bounds__(128) void pool1_kernel()
{
    int blk = blockIdx.x;
    int b   = blk >> 4;
    int tc  = blk & 15;
    int tid = threadIdx.x;
    #pragma unroll
    for (int q=0;q<3;q++){
        int d = tid + q*128;
        const float* p = g_h + (size_t)(b*LL + tc*32)*DM + d;
        float s = 0.f;
        #pragma unroll 8
        for (int t=0;t<32;t++) s += p[(size_t)t*DM];
        g_pool[blk*DM + d] = s;
    }
}

// ---------------- pool stage 2 ----------------
__global__ __launch_bounds__(128) void pool2_kernel(const float* __restrict__ w,
                                                    const float* __restrict__ b2)
{
    __shared__ float red[128];
    int b = blockIdx.x, tid = threadIdx.x;
    float v[3];
    #pragma unroll
    for (int q=0;q<3;q++){
        int d = tid + q*128;
        float s = 0.f;
        #pragma unroll
        for (int tc=0;tc<16;tc++) s += g_pool[(b*16+tc)*DM + d];
        v[q] = s * (1.0f/LL);
    }
    red[tid] = v[0]+v[1]+v[2]; __syncthreads();
    for (int s=64;s>0;s>>=1){ if(tid<s) red[tid]+=red[tid+s]; __syncthreads(); }
    float mu = red[0]*(1.0f/DM);
    __syncthreads();
    float d0=v[0]-mu, d1=v[1]-mu, d2=v[2]-mu;
    red[tid] = d0*d0+d1*d1+d2*d2; __syncthreads();
    for (int s=64;s>0;s>>=1){ if(tid<s) red[tid]+=red[tid+s]; __syncthreads(); }
    float inv = rsqrtf(red[0]*(1.0f/DM) + 1e-5f);
    g_featT[(tid    )*BB + b] = d0*inv*w[tid]     + b2[tid];
    g_featT[(tid+128)*BB + b] = d1*inv*w[tid+128] + b2[tid+128];
    g_featT[(tid+256)*BB + b] = d2*inv*w[tid+256] + b2[tid+256];
}

// ---------------- classification heads ----------------
__global__ __launch_bounds__(256) void heads_kernel(
    const float* __restrict__ ow, const float* __restrict__ ob,
    const float* __restrict__ fw, const float* __restrict__ fb,
    const float* __restrict__ gw, const float* __restrict__ gb,
    const float* __restrict__ sw, const float* __restrict__ sb,
    float* __restrict__ out)
{
    __shared__ __align__(16) float sf[DM*BB];
    int tid = threadIdx.x;
    for (int i = tid; i < DM*BB; i += blockDim.x) sf[i] = g_featT[i];
    __syncthreads();

    int j = blockIdx.x * blockDim.x + tid;
    if (j >= NOUT) return;

    const float* W; const float* Bv; int jj, Nseg;
    if (j < N_ORDER)                      { W=ow; Bv=ob; jj=j;                     Nseg=N_ORDER; }
    else if (j < N_ORDER+N_FAMILY)        { W=fw; Bv=fb; jj=j-N_ORDER;             Nseg=N_FAMILY; }
    else if (j < N_ORDER+N_FAMILY+N_GENUS){ W=gw; Bv=gb; jj=j-N_ORDER-N_FAMILY;    Nseg=N_GENUS; }
    else                                  { W=sw; Bv=sb; jj=j-N_ORDER-N_FAMILY-N_GENUS; Nseg=N_SPECIES; }

    float acc[BB];
    #pragma unroll
    for (int b=0;b<BB;b++) acc[b]=0.f;
    for (int k=0;k<DM;k+=2){
        float wv0 = W[(size_t)k*Nseg + jj];
        float wv1 = W[(size_t)(k+1)*Nseg + jj];
        const float4* row0 = (const float4*)&sf[k*BB];
        const float4* row1 = (const float4*)&sf[(k+1)*BB];
        #pragma unroll
        for (int bq=0;bq<8;bq++){
            float4 f0 = row0[bq];
            float4 f1 = row1[bq];
            acc[4*bq+0] = fmaf(f1.x, wv1, fmaf(f0.x, wv0, acc[4*bq+0]));
            acc[4*bq+1] = fmaf(f1.y, wv1, fmaf(f0.y, wv0, acc[4*bq+1]));
            acc[4*bq+2] = fmaf(f1.z, wv1, fmaf(f0.z, wv0, acc[4*bq+2]));
            acc[4*bq+3] = fmaf(f1.w, wv1, fmaf(f0.w, wv0, acc[4*bq+3]));
        }
    }
    float bias = Bv[jj];
    #pragma unroll
    for (int b=0;b<BB;b++) out[(size_t)b*NOUT + j] = acc[b] + bias;
}

// ---------------- orchestration ----------------
extern "C" void kernel_launch(void* const* d_in, const int* in_sizes, int n_in,
                              void* d_out, int out_size)
{
    const int*   tokens = (const int*)  d_in[0];
    const float* emb    = (const float*)d_in[1];
    const float* ln_w   = (const float*)d_in[2];
    const float* ln_b   = (const float*)d_in[3];
    const float* Win    = (const float*)d_in[4];
    const float* cw     = (const float*)d_in[5];
    const float* cb     = (const float*)d_in[6];
    const float* dtb    = (const float*)d_in[7];
    const float* alog   = (const float*)d_in[8];
    const float* Dd     = (const float*)d_in[9];
    const float* gnw    = (const float*)d_in[10];
    const float* Wout   = (const float*)d_in[11];
    const float* nfw    = (const float*)d_in[12];
    const float* nfb    = (const float*)d_in[13];
    const float* plw    = (const float*)d_in[14];
    const float* plb    = (const float*)d_in[15];
    const float* ow     = (const float*)d_in[16];
    const float* ob     = (const float*)d_in[17];
    const float* fw     = (const float*)d_in[18];
    const float* fb     = (const float*)d_in[19];
    const float* gw     = (const float*)d_in[20];
    const float* gb     = (const float*)d_in[21];
    const float* sw     = (const float*)d_in[22];
    const float* sb     = (const float*)d_in[23];
    float* out = (float*)d_out;

    const int smem_bytes = SMEM_FLOATS * 4;
    cudaFuncSetAttribute((const void*)gemm_tc<0,1>, cudaFuncAttributeMaxDynamicSharedMemorySize, smem_bytes);
    cudaFuncSetAttribute((const void*)gemm_tc<1,2>, cudaFuncAttributeMaxDynamicSharedMemorySize, smem_bytes);
    cudaFuncSetAttribute((const void*)ssd_local_kernel, cudaFuncAttributeMaxDynamicSharedMemorySize, SSD_A_SMEM);

    wcvt_t_kernel<<<dim3((DIP+31)/32, (DI+31)/32, 4), 256>>>(Win, Wout);
    embed_ln_kernel<<<NT, 128>>>(tokens, emb, ln_w, ln_b);

    for (int l = 0; l < 2; l++) {
        if (l > 0) ln_kernel<<<NT, 128>>>(ln_w + l*DM, ln_b + l*DM, 1);
        gemm_tc<0,1><<<dim3((DIP+GBN-1)/GBN, NT/GBM, 1), 256, smem_bytes>>>(l);
        conv_dtda_kernel<<<CONV_BLKS + DTDA_BLKS, 224>>>(cw + (size_t)l*CD*4, cb + l*CD,
                                                         dtb + l*NH, alog + l*NH);
        ssd_local_kernel  <<<BB*NH*NCHUNK, 128, SSD_A_SMEM>>>();
        ssd_combine_kernel<<<BB*NH, 128>>>();
        ssd_fix_kernel    <<<BB*NH*(NCHUNK-1), 128>>>();
        gate_rms_kernel<<<NT, 256>>>(Dd + l*NH, gnw + l*DI);
        gemm_tc<1,2><<<dim3((DM+GBN-1)/GBN, NT/GBM, 2), 256, smem_bytes>>>(l);
    }

    ln_kernel<<<NT, 128>>>(nfw, nfb, 0);
    pool1_kernel<<<BB*16, 128>>>();
    pool2_kernel<<<BB, 128>>>(plw, plb);
    heads_kernel<<<(NOUT + 255)/256, 256>>>(ow, ob, fw, fb, gw, gb, sw, sb, out);
}

// round 13
// speedup vs baseline: 1.2059x; 1.0155x over previous
#include <cuda_runtime.h>
#include <math.h>
#include <stddef.h>
#include <stdint.h>

typedef unsigned long long ull;

// ---------------- problem constants ----------------
#define BB   32
#define LL   512
#define DM   384
#define DI   768
#define DS   64
#define NH   16
#define HD   48
#define DIP  1680
#define CD   896
#define NT   (BB*LL)
#define NOUT 38667
#define N_ORDER 60
#define N_FAMILY 427
#define N_GENUS 14216
#define N_SPECIES 23964

#define WIN1  (DM*DIP)
#define WOUT1 (DI*DM)

#define NCHUNK 8
#define CLEN   64
#define SFL    3072          // DS*HD floats per (b,h,chunk) state

// k-permutation within each 8-group: pos = k<4 ? 2k : 2(k-4)+1
__device__ __forceinline__ int kperm(int k){
    int j = k & 7;
    return (k & ~7) | ((j<4) ? (j<<1) : (((j-4)<<1)|1));
}

// ---------------- scratch ----------------
__device__ float g_resid[(size_t)NT*DM];
__device__ float g_h    [(size_t)NT*DM];
__device__ float g_zx   [(size_t)NT*DIP];
__device__ float g_xBC  [(size_t)NT*CD];
__device__ float g_dt   [(size_t)NT*NH];
__device__ float g_dA   [(size_t)NT*NH];    // stores log(dA) = -exp(A_log)*dt
__device__ float g_lc   [(size_t)NT*NH];    // chunk-local cumsum of log dA
__device__ float g_ys   [(size_t)NT*DI];
__device__ float g_yn   [(size_t)NT*DI];
__device__ float g_wtB  [2*WIN1 + 2*WOUT1];
__device__ float g_state[(size_t)BB*NH*NCHUNK*SFL];
__device__ float g_sin  [(size_t)BB*NH*NCHUNK*SFL];
__device__ float g_pool [BB*16*DM];
__device__ float g_featT[DM*BB];

__device__ __forceinline__ uint32_t f2tf(float x){
    uint32_t y;
    asm volatile("cvt.rna.tf32.f32 %0, %1;" : "=r"(y) : "f"(x));
    return y;
}
__device__ __forceinline__ void upk2u(uint32_t& lo, uint32_t& hi, ull v){
    asm("mov.b64 {%0, %1}, %2;" : "=r"(lo), "=r"(hi) : "l"(v));
}

// ---------------- weight transpose + permute + tf32 convert ----------------
__global__ __launch_bounds__(256) void wcvt_t_kernel(const float* __restrict__ Win,
                                                     const float* __restrict__ Wout)
{
    int r = blockIdx.z;
    const float* src; float* dst; int K_, N_;
    if (r < 2){ src = Win  + (size_t)r*WIN1;      dst = g_wtB + (size_t)r*WIN1;              K_ = DM; N_ = DIP; }
    else      { src = Wout + (size_t)(r-2)*WOUT1; dst = g_wtB + 2*WIN1 + (size_t)(r-2)*WOUT1; K_ = DI; N_ = DM; }
    int k0 = blockIdx.y*32, n0 = blockIdx.x*32;
    if (k0 >= K_ || n0 >= N_) return;
    __shared__ float sm[32][33];
    int tx = threadIdx.x & 31, ty = threadIdx.x >> 5;
    #pragma unroll
    for (int q=0;q<4;q++){
        int k = k0 + ty + q*8;
        if (k < K_ && n0+tx < N_) sm[ty+q*8][tx] = src[(size_t)k*N_ + n0+tx];
    }
    __syncthreads();
    #pragma unroll
    for (int q=0;q<4;q++){
        int n = n0 + ty + q*8;
        int k = k0 + tx;
        if (n < N_ && k < K_)
            dst[(size_t)n*K_ + kperm(k)] = __uint_as_float(f2tf(sm[tx][ty+q*8]));
    }
}

// ---------------- fused embedding + layer-0 layernorm (k-permuted) ----------------
__global__ __launch_bounds__(128) void embed_ln_kernel(const int* __restrict__ tokens,
                                                       const float* __restrict__ emb,
                                                       const float* __restrict__ w,
                                                       const float* __restrict__ b)
{
    __shared__ float red[128];
    int row = blockIdx.x, tid = threadIdx.x;
    const float* er = emb + (size_t)tokens[row]*DM;
    float v0 = er[tid], v1 = er[tid+128], v2 = er[tid+256];
    float* rr = g_resid + (size_t)row*DM;
    rr[tid] = v0; rr[tid+128] = v1; rr[tid+256] = v2;

    red[tid] = v0+v1+v2; __syncthreads();
    for (int s=64;s>0;s>>=1){ if(tid<s) red[tid]+=red[tid+s]; __syncthreads(); }
    float mu = red[0] * (1.0f/DM);
    __syncthreads();
    float d0=v0-mu, d1=v1-mu, d2=v2-mu;
    red[tid] = d0*d0+d1*d1+d2*d2; __syncthreads();
    for (int s=64;s>0;s>>=1){ if(tid<s) red[tid]+=red[tid+s]; __syncthreads(); }
    float inv = rsqrtf(red[0]*(1.0f/DM) + 1e-5f);
    float* o = g_h + (size_t)row*DM;
    o[kperm(tid)]     = __uint_as_float(f2tf(d0*inv*w[tid]     + b[tid]));
    o[kperm(tid+128)] = __uint_as_float(f2tf(d1*inv*w[tid+128] + b[tid+128]));
    o[kperm(tid+256)] = __uint_as_float(f2tf(d2*inv*w[tid+256] + b[tid+256]));
}

// ---------------- layernorm: g_resid -> g_h ----------------
__global__ __launch_bounds__(128) void ln_kernel(const float* __restrict__ w, const float* __restrict__ b, int tf)
{
    __shared__ float red[128];
    int row = blockIdx.x, tid = threadIdx.x;
    const float* xr = g_resid + (size_t)row*DM;
    float v0 = xr[tid], v1 = xr[tid+128], v2 = xr[tid+256];
    red[tid] = v0+v1+v2; __syncthreads();
    for (int s=64;s>0;s>>=1){ if(tid<s) red[tid]+=red[tid+s]; __syncthreads(); }
    float mu = red[0] * (1.0f/DM);
    __syncthreads();
    float d0=v0-mu, d1=v1-mu, d2=v2-mu;
    red[tid] = d0*d0+d1*d1+d2*d2; __syncthreads();
    for (int s=64;s>0;s>>=1){ if(tid<s) red[tid]+=red[tid+s]; __syncthreads(); }
    float inv = rsqrtf(red[0]*(1.0f/DM) + 1e-5f);
    float o0 = d0*inv*w[tid]     + b[tid];
    float o1 = d1*inv*w[tid+128] + b[tid+128];
    float o2 = d2*inv*w[tid+256] + b[tid+256];
    float* o = g_h + (size_t)row*DM;
    if (tf){
        o[kperm(tid)]     = __uint_as_float(f2tf(o0));
        o[kperm(tid+128)] = __uint_as_float(f2tf(o1));
        o[kperm(tid+256)] = __uint_as_float(f2tf(o2));
    } else {
        o[tid] = o0; o[tid+128] = o1; o[tid+256] = o2;
    }
}

// ---------------- tf32 mma helper ----------------
__device__ __forceinline__ void mma_tf32(float* c, const uint32_t* a, const uint32_t* b){
    asm volatile(
      "mma.sync.aligned.m16n8k8.row.col.f32.tf32.tf32.f32 "
      "{%0,%1,%2,%3}, {%4,%5,%6,%7}, {%8,%9}, {%0,%1,%2,%3};\n"
      : "+f"(c[0]), "+f"(c[1]), "+f"(c[2]), "+f"(c[3])
      : "r"(a[0]), "r"(a[1]), "r"(a[2]), "r"(a[3]), "r"(b[0]), "r"(b[1]));
}

// ---------------- tf32 tensor-core GEMM (R8-proven) ----------------
#define GBM 128
#define GBN 128
#define GBK 16
#define NSTAGE 4
#define TSTR 24
#define AS_FLOATS (GBM*TSTR)
#define BS_FLOATS (GBN*TSTR)
#define SMEM_FLOATS (NSTAGE*(AS_FLOATS+BS_FLOATS))

template<int MODE, int SPLITK>
__global__ __launch_bounds__(256,2) void gemm_tc(int layer)
{
    const float* __restrict__ A = (MODE==0) ? g_h : g_yn;
    const float* __restrict__ W = (MODE==0) ? (g_wtB + (size_t)layer*WIN1)
                                            : (g_wtB + 2*WIN1 + (size_t)layer*WOUT1);
    float* C = (MODE==0) ? g_zx : g_resid;
    const int N = (MODE==0) ? DIP : DM;
    const int K = (MODE==0) ? DM  : DI;
    const int Ks = K / SPLITK;
    const int k_origin = blockIdx.z * Ks;

    extern __shared__ float sh[];
    float* shB = sh + NSTAGE*AS_FLOATS;

    int tid  = threadIdx.x;
    int warp = tid >> 5;
    int lane = tid & 31;
    int gid  = lane >> 2;
    int tig  = lane & 3;

    int m0 = blockIdx.y * GBM;
    int n0 = blockIdx.x * GBN;
    int wm = (warp & 1) * 64;
    int wn = (warp >> 1) * 32;

    float acc[4][4][4];
    #pragma unroll
    for (int i=0;i<4;i++)
        #pragma unroll
        for (int j=0;j<4;j++)
            #pragma unroll
            for (int q=0;q<4;q++) acc[i][j][q]=0.f;

    const int niter = Ks / GBK;

    int row0 = tid >> 2,        kc0 = (tid & 3) << 2;
    int row1 = (tid+256) >> 2,  kc1 = (tid & 3) << 2;
    int b_ok0 = (n0 + row0 < N) ? 16 : 0;
    int b_ok1 = (n0 + row1 < N) ? 16 : 0;
    const float* asrc0 = A + (size_t)(m0 + row0)*K + k_origin + kc0;
    const float* asrc1 = A + (size_t)(m0 + row1)*K + k_origin + kc1;
    const float* bsrc0 = W + (size_t)((n0 + row0 < N) ? (n0 + row0) : 0)*K + k_origin + kc0;
    const float* bsrc1 = W + (size_t)((n0 + row1 < N) ? (n0 + row1) : 0)*K + k_origin + kc1;

    uint32_t adst0 = (uint32_t)__cvta_generic_to_shared(&sh [row0*TSTR + kc0]);
    uint32_t adst1 = (uint32_t)__cvta_generic_to_shared(&sh [row1*TSTR + kc1]);
    uint32_t bdst0 = (uint32_t)__cvta_generic_to_shared(&shB[row0*TSTR + kc0]);
    uint32_t bdst1 = (uint32_t)__cvta_generic_to_shared(&shB[row1*TSTR + kc1]);

    auto issue_copy = [&](int st, int it){
        int k0 = it * GBK;
        uint32_t ao = st*AS_FLOATS*4, bo = st*BS_FLOATS*4;
        asm volatile("cp.async.cg.shared.global [%0], [%1], 16;\n"
                     :: "r"(adst0 + ao), "l"(asrc0 + k0));
        asm volatile("cp.async.cg.shared.global [%0], [%1], 16;\n"
                     :: "r"(adst1 + ao), "l"(asrc1 + k0));
        asm volatile("cp.async.cg.shared.global [%0], [%1], 16, %2;\n"
                     :: "r"(bdst0 + bo), "l"(bsrc0 + k0), "r"(b_ok0));
        asm volatile("cp.async.cg.shared.global [%0], [%1], 16, %2;\n"
                     :: "r"(bdst1 + bo), "l"(bsrc1 + k0), "r"(b_ok1));
    };

    #pragma unroll
    for (int st=0; st<NSTAGE-1; st++){
        if (st < niter) issue_copy(st, st);
        asm volatile("cp.async.commit_group;\n");
    }

    for (int it=0; it<niter; ++it){
        asm volatile("cp.async.wait_group %0;\n" :: "n"(NSTAGE-2));
        __syncthreads();

        int cb = it & (NSTAGE-1);
        const float* Asb = &sh [cb*AS_FLOATS];
        const float* Bsb = &shB[cb*BS_FLOATS];

        #pragma unroll
        for (int ks=0; ks<GBK; ks+=8){
            uint32_t af[4][4], bf[4][2];
            #pragma unroll
            for (int mi=0; mi<4; mi++){
                int mr = wm + 16*mi;
                ull lo8 = *(const ull*)&Asb[(mr+gid  )*TSTR + ks + 2*tig];
                ull hi8 = *(const ull*)&Asb[(mr+gid+8)*TSTR + ks + 2*tig];
                upk2u(af[mi][0], af[mi][2], lo8);
                upk2u(af[mi][1], af[mi][3], hi8);
            }
            #pragma unroll
            for (int ni=0; ni<4; ni++){
                int nb = wn + 8*ni;
                ull bb = *(const ull*)&Bsb[(nb+gid)*TSTR + ks + 2*tig];
                upk2u(bf[ni][0], bf[ni][1], bb);
            }
            #pragma unroll
            for (int mi=0; mi<4; mi++)
                #pragma unroll
                for (int ni=0; ni<4; ni++)
                    mma_tf32(acc[mi][ni], af[mi], bf[ni]);
        }

        int nx = it + NSTAGE - 1;
        if (nx < niter) issue_copy(nx & (NSTAGE-1), nx);
        asm volatile("cp.async.commit_group;\n");
    }

    #pragma unroll
    for (int mi=0; mi<4; mi++){
        int r0 = m0 + wm + 16*mi + gid;
        #pragma unroll
        for (int ni=0; ni<4; ni++){
            int c0 = n0 + wn + 8*ni + 2*tig;
            float* a = acc[mi][ni];
            #pragma unroll
            for (int half=0; half<2; half++){
                int cc = c0 + half;
                if (cc < N){
                    size_t i0 = (size_t)r0*N + cc;
                    size_t i2 = (size_t)(r0+8)*N + cc;
                    if (MODE){ atomicAdd(&C[i0], a[half]); atomicAdd(&C[i2], a[2+half]); }
                    else     { C[i0] = a[half]; C[i2] = a[2+half]; }
                }
            }
        }
    }
}

// ---------------- fused conv (8-step chunks) + dt/logdA ----------------
#define CONV_BLKS (BB*64)
#define DTDA_TOT  (NT*(NH/4))
#define DTDA_BLKS ((DTDA_TOT + 223)/224)
__global__ __launch_bounds__(224) void conv_dtda_kernel(const float* __restrict__ cw, const float* __restrict__ cb,
                                                        const float* __restrict__ dtb, const float* __restrict__ alog)
{
    int blk = blockIdx.x;
    int tid = threadIdx.x;
    if (blk < CONV_BLKS){
        int b  = blk >> 6;
        int tc = blk & 63;
        int t0 = tc * 8;
        int c  = tid << 2;

        float4 tw[4];
        #pragma unroll
        for (int k=0;k<4;k++){
            tw[k].x = cw[(c+0)*4+k];
            tw[k].y = cw[(c+1)*4+k];
            tw[k].z = cw[(c+2)*4+k];
            tw[k].w = cw[(c+3)*4+k];
        }
        float4 bias = *(const float4*)&cb[c];

        const float* base = g_zx + (size_t)(b*LL + t0)*DIP + DI + c;
        float* obase = g_xBC + (size_t)(b*LL + t0)*CD + c;

        float4 p1, p2, p3;
        if (t0 > 0){
            p1 = *(const float4*)(base - 3*DIP);
            p2 = *(const float4*)(base - 2*DIP);
            p3 = *(const float4*)(base - 1*DIP);
        } else {
            p1 = p2 = p3 = make_float4(0.f,0.f,0.f,0.f);
        }

        #pragma unroll
        for (int i=0;i<8;i++){
            float4 v = *(const float4*)(base + (size_t)i*DIP);
            float4 a;
            a.x = bias.x + p1.x*tw[0].x + p2.x*tw[1].x + p3.x*tw[2].x + v.x*tw[3].x;
            a.y = bias.y + p1.y*tw[0].y + p2.y*tw[1].y + p3.y*tw[2].y + v.y*tw[3].y;
            a.z = bias.z + p1.z*tw[0].z + p2.z*tw[1].z + p3.z*tw[2].z + v.z*tw[3].z;
            a.w = bias.w + p1.w*tw[0].w + p2.w*tw[1].w + p3.w*tw[2].w + v.w*tw[3].w;
            float4 r;
            r.x = a.x / (1.f + __expf(-a.x));
            r.y = a.y / (1.f + __expf(-a.y));
            r.z = a.z / (1.f + __expf(-a.z));
            r.w = a.w / (1.f + __expf(-a.w));
            *(float4*)(obase + (size_t)i*CD) = r;
            p1 = p2; p2 = p3; p3 = v;
        }
    } else {
        int j = (blk - CONV_BLKS)*224 + tid;
        if (j >= DTDA_TOT) return;
        int hq = (j & 3) << 2;
        int bt = j >> 2;
        #pragma unroll
        for (int q=0;q<4;q++){
            int hh = hq + q;
            float raw = g_zx[(size_t)bt*DIP + (DIP-NH) + hh] + dtb[hh];
            float sp = (raw > 20.f) ? raw : log1pf(expf(raw));
            g_dt[bt*NH + hh] = sp;
            g_dA[bt*NH + hh] = -expf(alog[hh]) * sp;    // log(dA)
        }
    }
}

// ---------------- SSD scan pass A: per (b,h,chunk) tensor-core local scan ----------------
#define SA_STR 68
#define SSD_A_SMEM ((3*64*SA_STR + 2*48*SA_STR + 192)*4)

__global__ __launch_bounds__(128) void ssd_local_kernel()
{
    int blk = blockIdx.x;           // BB*NH*NCHUNK
    int c  = blk & (NCHUNK-1);
    int bh = blk >> 3;
    int b  = bh >> 4;
    int h  = bh & 15;
    int tid = threadIdx.x;
    int warp = tid >> 5, lane = tid & 31, gid = lane >> 2, tig = lane & 3;
    int bt0 = b*LL + c*CLEN;

    extern __shared__ float sa[];
    float* sC   = sa;
    float* sBW  = sC  + 64*SA_STR;
    float* sBT  = sBW + 64*SA_STR;
    float* sXT  = sBT + 64*SA_STR;
    float* sXwT = sXT + 48*SA_STR;
    float* lc_sh = sXwT + 48*SA_STR;
    float* dt_sh = lc_sh + 64;
    float* w2_sh = dt_sh + 64;

    for (int i = tid; i < 64*16; i += 128){
        int t = i >> 4, q = (i & 15) << 2;
        const float* row = g_xBC + (size_t)(bt0+t)*CD + DI;
        float4 vb = *(const float4*)(row + q);
        float4 vc = *(const float4*)(row + DS + q);
        *(float4*)&sBW[t*SA_STR + q] = vb;
        *(float4*)&sC [t*SA_STR + q] = vc;
        sBT[(q+0)*SA_STR + t] = vb.x;
        sBT[(q+1)*SA_STR + t] = vb.y;
        sBT[(q+2)*SA_STR + t] = vb.z;
        sBT[(q+3)*SA_STR + t] = vb.w;
    }
    for (int i = tid; i < 64*12; i += 128){
        int t = i / 12, q = (i % 12) << 2;
        float4 vx = *(const float4*)(g_xBC + (size_t)(bt0+t)*CD + h*HD + q);
        sXT[(q+0)*SA_STR + t] = vx.x;
        sXT[(q+1)*SA_STR + t] = vx.y;
        sXT[(q+2)*SA_STR + t] = vx.z;
        sXT[(q+3)*SA_STR + t] = vx.w;
    }
    if (tid < 64) dt_sh[tid] = g_dt[(size_t)(bt0+tid)*NH + h];
    if (warp == 0){
        float v0 = g_dA[(size_t)(bt0+lane)*NH + h];
        float v1 = g_dA[(size_t)(bt0+32+lane)*NH + h];
        #pragma unroll
        for (int d=1; d<32; d<<=1){
            float u0 = __shfl_up_sync(0xffffffffu, v0, d);
            float u1 = __shfl_up_sync(0xffffffffu, v1, d);
            if (lane >= d){ v0 += u0; v1 += u1; }
        }
        float tot = __shfl_sync(0xffffffffu, v0, 31);
        v1 += tot;
        lc_sh[lane]    = v0;
        lc_sh[32+lane] = v1;
        g_lc[(size_t)(bt0+lane)*NH + h]    = v0;
        g_lc[(size_t)(bt0+32+lane)*NH + h] = v1;
    }
    __syncthreads();

    int wt0 = warp*16;
    float gacc[8][4];
    #pragma unroll
    for (int ni=0;ni<8;ni++){ gacc[ni][0]=0.f; gacc[ni][1]=0.f; gacc[ni][2]=0.f; gacc[ni][3]=0.f; }
    #pragma unroll
    for (int kk=0; kk<64; kk+=8){
        uint32_t af[4];
        af[0] = __float_as_uint(sC[(wt0+gid  )*SA_STR + kk+tig  ]);
        af[1] = __float_as_uint(sC[(wt0+gid+8)*SA_STR + kk+tig  ]);
        af[2] = __float_as_uint(sC[(wt0+gid  )*SA_STR + kk+tig+4]);
        af[3] = __float_as_uint(sC[(wt0+gid+8)*SA_STR + kk+tig+4]);
        #pragma unroll
        for (int ni=0; ni<8; ni++){
            uint32_t bf[2];
            bf[0] = __float_as_uint(sBW[(8*ni+gid)*SA_STR + kk+tig  ]);
            bf[1] = __float_as_uint(sBW[(8*ni+gid)*SA_STR + kk+tig+4]);
            mma_tf32(gacc[ni], af, bf);
        }
    }
    if (tid < 64) w2_sh[tid] = __expf(lc_sh[63] - lc_sh[tid]) * dt_sh[tid];
    __syncthreads();

    {
        int t0r = wt0 + gid, t1r = t0r + 8;
        float lct0 = lc_sh[t0r], lct1 = lc_sh[t1r];
        #pragma unroll
        for (int ni=0; ni<8; ni++){
            int s0 = 8*ni + 2*tig, s1 = s0 + 1;
            float lcs0 = lc_sh[s0], lcs1 = lc_sh[s1];
            float d0 = dt_sh[s0],   d1 = dt_sh[s1];
            sBW[t0r*SA_STR + s0] = (s0<=t0r) ? gacc[ni][0]*__expf(lct0-lcs0)*d0 : 0.f;
            sBW[t0r*SA_STR + s1] = (s1<=t0r) ? gacc[ni][1]*__expf(lct0-lcs1)*d1 : 0.f;
            sBW[t1r*SA_STR + s0] = (s0<=t1r) ? gacc[ni][2]*__expf(lct1-lcs0)*d0 : 0.f;
            sBW[t1r*SA_STR + s1] = (s1<=t1r) ? gacc[ni][3]*__expf(lct1-lcs1)*d1 : 0.f;
        }
    }
    for (int i = tid; i < 48*64; i += 128){
        int p = i >> 6, s = i & 63;
        sXwT[p*SA_STR + s] = sXT[p*SA_STR + s] * w2_sh[s];
    }
    __syncthreads();

    float yacc[6][4], sacc[6][4];
    #pragma unroll
    for (int ni=0;ni<6;ni++){
        yacc[ni][0]=yacc[ni][1]=yacc[ni][2]=yacc[ni][3]=0.f;
        sacc[ni][0]=sacc[ni][1]=sacc[ni][2]=sacc[ni][3]=0.f;
    }
    #pragma unroll
    for (int kk=0; kk<64; kk+=8){
        uint32_t afW[4], afB[4];
        afW[0] = __float_as_uint(sBW[(wt0+gid  )*SA_STR + kk+tig  ]);
        afW[1] = __float_as_uint(sBW[(wt0+gid+8)*SA_STR + kk+tig  ]);
        afW[2] = __float_as_uint(sBW[(wt0+gid  )*SA_STR + kk+tig+4]);
        afW[3] = __float_as_uint(sBW[(wt0+gid+8)*SA_STR + kk+tig+4]);
        afB[0] = __float_as_uint(sBT[(wt0+gid  )*SA_STR + kk+tig  ]);
        afB[1] = __float_as_uint(sBT[(wt0+gid+8)*SA_STR + kk+tig  ]);
        afB[2] = __float_as_uint(sBT[(wt0+gid  )*SA_STR + kk+tig+4]);
        afB[3] = __float_as_uint(sBT[(wt0+gid+8)*SA_STR + kk+tig+4]);
        #pragma unroll
        for (int ni=0; ni<6; ni++){
            uint32_t bfX[2], bfW2[2];
            bfX[0]  = __float_as_uint(sXT [(8*ni+gid)*SA_STR + kk+tig  ]);
            bfX[1]  = __float_as_uint(sXT [(8*ni+gid)*SA_STR + kk+tig+4]);
            mma_tf32(yacc[ni], afW, bfX);
            bfW2[0] = __float_as_uint(sXwT[(8*ni+gid)*SA_STR + kk+tig  ]);
            bfW2[1] = __float_as_uint(sXwT[(8*ni+gid)*SA_STR + kk+tig+4]);
            mma_tf32(sacc[ni], afB, bfW2);
        }
    }

    size_t sbase = ((size_t)bh*NCHUNK + c)*SFL;
    #pragma unroll
    for (int ni=0; ni<6; ni++){
        int p = 8*ni + 2*tig;
        int tr = wt0 + gid;
        float* y0 = &g_ys[(size_t)(bt0+tr)*DI + h*HD + p];
        *(float2*)y0            = make_float2(yacc[ni][0], yacc[ni][1]);
        *(float2*)(y0 + 8*DI)   = make_float2(yacc[ni][2], yacc[ni][3]);
        float* s0 = &g_state[sbase + tr*HD + p];
        *(float2*)s0            = make_float2(sacc[ni][0], sacc[ni][1]);
        *(float2*)(s0 + 8*HD)   = make_float2(sacc[ni][2], sacc[ni][3]);
    }
}

// ---------------- SSD pass B: sequential chunk-state combine (float4) ----------------
__global__ __launch_bounds__(128) void ssd_combine_kernel()
{
    int bh = blockIdx.x;
    int b  = bh >> 4;
    int h  = bh & 15;
    int tid = threadIdx.x;
    size_t base = (size_t)bh*NCHUNK*SFL;

    float4 sin[SFL/512];
    #pragma unroll
    for (int j=0;j<SFL/512;j++) sin[j]=make_float4(0.f,0.f,0.f,0.f);

    for (int c=0;c<NCHUNK-1;c++){
        float ef = __expf(g_lc[(size_t)(b*LL + c*CLEN + CLEN-1)*NH + h]);
        #pragma unroll
        for (int j=0;j<SFL/512;j++){
            float4 S = *(const float4*)&g_state[base + (size_t)c*SFL + j*512 + tid*4];
            sin[j].x = sin[j].x*ef + S.x;
            sin[j].y = sin[j].y*ef + S.y;
            sin[j].z = sin[j].z*ef + S.z;
            sin[j].w = sin[j].w*ef + S.w;
        }
        #pragma unroll
        for (int j=0;j<SFL/512;j++)
            *(float4*)&g_sin[base + (size_t)(c+1)*SFL + j*512 + tid*4] = sin[j];
    }
}

// ---------------- SSD pass C: y += exp(lc_t) * (C @ S_in) ----------------
__global__ __launch_bounds__(128) void ssd_fix_kernel()
{
    int blk = blockIdx.x;
    int bh  = blk / (NCHUNK-1);
    int c   = blk - bh*(NCHUNK-1) + 1;
    int b   = bh >> 4;
    int h   = bh & 15;
    int tid = threadIdx.x;
    int warp = tid >> 5, lane = tid & 31, gid = lane >> 2, tig = lane & 3;
    int bt0 = b*LL + c*CLEN;

    __shared__ float sC2[64*SA_STR];
    __shared__ float sST[48*SA_STR];
    __shared__ float lc2[64];

    for (int i = tid; i < 64*16; i += 128){
        int t = i >> 4, q = (i & 15) << 2;
        float4 vc = *(const float4*)(g_xBC + (size_t)(bt0+t)*CD + DI + DS + q);
        *(float4*)&sC2[t*SA_STR + q] = vc;
    }
    size_t sbase = ((size_t)bh*NCHUNK + c)*SFL;
    for (int i = tid; i < SFL; i += 128){
        int n = i / HD, p = i - n*HD;
        sST[p*SA_STR + n] = g_sin[sbase + i];
    }
    if (tid < 64) lc2[tid] = g_lc[(size_t)(bt0+tid)*NH + h];
    __syncthreads();

    int wt0 = warp*16;
    float facc[6][4];
    #pragma unroll
    for (int ni=0;ni<6;ni++){ facc[ni][0]=facc[ni][1]=facc[ni][2]=facc[ni][3]=0.f; }
    #pragma unroll
    for (int kk=0; kk<64; kk+=8){
        uint32_t af[4];
        af[0] = __float_as_uint(sC2[(wt0+gid  )*SA_STR + kk+tig  ]);
        af[1] = __float_as_uint(sC2[(wt0+gid+8)*SA_STR + kk+tig  ]);
        af[2] = __float_as_uint(sC2[(wt0+gid  )*SA_STR + kk+tig+4]);
        af[3] = __float_as_uint(sC2[(wt0+gid+8)*SA_STR + kk+tig+4]);
        #pragma unroll
        for (int ni=0; ni<6; ni++){
            uint32_t bf[2];
            bf[0] = __float_as_uint(sST[(8*ni+gid)*SA_STR + kk+tig  ]);
            bf[1] = __float_as_uint(sST[(8*ni+gid)*SA_STR + kk+tig+4]);
            mma_tf32(facc[ni], af, bf);
        }
    }

    int tr = wt0 + gid;
    float e0 = __expf(lc2[tr]);
    float e1 = __expf(lc2[tr+8]);
    #pragma unroll
    for (int ni=0; ni<6; ni++){
        int p = 8*ni + 2*tig;
        float2* y0 = (float2*)&g_ys[(size_t)(bt0+tr)*DI + h*HD + p];
        float2 v0 = *y0; v0.x += e0*facc[ni][0]; v0.y += e0*facc[ni][1]; *y0 = v0;
        float2* y1 = (float2*)&g_ys[(size_t)(bt0+tr+8)*DI + h*HD + p];
        float2 v1 = *y1; v1.x += e1*facc[ni][2]; v1.y += e1*facc[ni][3]; *y1 = v1;
    }
}

// ---------------- y = (ys + D*x) * silu(z); RMS-norm -> g_yn (tf32, k-permuted) ----------------
__global__ __launch_bounds__(256) void gate_rms_kernel(const float* __restrict__ Dp,
                                                       const float* __restrict__ gnorm)
{
    __shared__ float red[256];
    int row = blockIdx.x, tid = threadIdx.x;
    float v[3]; float ss = 0.f;
    #pragma unroll
    for (int q=0;q<3;q++){
        int i = tid + q*256;
        float ys = g_ys[(size_t)row*DI + i];
        float xv = g_xBC[(size_t)row*CD + i];
        float z  = g_zx [(size_t)row*DIP + i];
        float val = (ys + Dp[i/HD]*xv) * (z / (1.f + __expf(-z)));
        v[q] = val; ss += val*val;
    }
    red[tid] = ss; __syncthreads();
    for (int s=128;s>0;s>>=1){ if(tid<s) red[tid]+=red[tid+s]; __syncthreads(); }
    float scale = rsqrtf(red[0]*(1.0f/DI) + 1e-5f);
    #pragma unroll
    for (int q=0;q<3;q++){
        int i = tid + q*256;
        g_yn[(size_t)row*DI + kperm(i)] = __uint_as_float(f2tf(v[q]*scale*gnorm[i]));
    }
}

// ---------------- pool stage 1 ----------------
__global__ __launch_bounds__(128) void pool1_kernel()
{
    int blk = blockIdx.x;
    int b   = blk >> 4;
    int tc  = blk & 15;
    int tid = threadIdx.x;
    #pragma unroll
    for (int q=0;q<3;q++){
        int d = tid + q*128;
        const float* p = g_h + (size_t)(b*LL + tc*32)*DM + d;
        float s = 0.f;
        #pragma unroll 8
        for (int t=0;t<32;t++) s += p[(size_t)t*DM];
        g_pool[blk*DM + d] = s;
    }
}

// ---------------- pool stage 2 ----------------
__global__ __launch_bounds__(128) void pool2_kernel(const float* __restrict__ w,
                                                    const float* __restrict__ b2)
{
    __shared__ float red[128];
    int b = blockIdx.x, tid = threadIdx.x;
    float v[3];
    #pragma unroll
    for (int q=0;q<3;q++){
        int d = tid + q*128;
        float s = 0.f;
        #pragma unroll
        for (int tc=0;tc<16;tc++) s += g_pool[(b*16+tc)*DM + d];
        v[q] = s * (1.0f/LL);
    }
    red[tid] = v[0]+v[1]+v[2]; __syncthreads();
    for (int s=64;s>0;s>>=1){ if(tid<s) red[tid]+=red[tid+s]; __syncthreads(); }
    float mu = red[0]*(1.0f/DM);
    __syncthreads();
    float d0=v[0]-mu, d1=v[1]-mu, d2=v[2]-mu;
    red[tid] = d0*d0+d1*d1+d2*d2; __syncthreads();
    for (int s=64;s>0;s>>=1){ if(tid<s) red[tid]+=red[tid+s]; __syncthreads(); }
    float inv = rsqrtf(red[0]*(1.0f/DM) + 1e-5f);
    g_featT[(tid    )*BB + b] = d0*inv*w[tid]     + b2[tid];
    g_featT[(tid+128)*BB + b] = d1*inv*w[tid+128] + b2[tid+128];
    g_featT[(tid+256)*BB + b] = d2*inv*w[tid+256] + b2[tid+256];
}

// ---------------- classification heads (R8 form) ----------------
__global__ __launch_bounds__(256) void heads_kernel(
    const float* __restrict__ ow, const float* __restrict__ ob,
    const float* __restrict__ fw, const float* __restrict__ fb,
    const float* __restrict__ gw, const float* __restrict__ gb,
    const float* __restrict__ sw, const float* __restrict__ sb,
    float* __restrict__ out)
{
    __shared__ __align__(16) float sf[DM*BB];
    int tid = threadIdx.x;
    for (int i = tid; i < DM*BB; i += blockDim.x) sf[i] = g_featT[i];
    __syncthreads();

    int j = blockIdx.x * blockDim.x + tid;
    if (j >= NOUT) return;

    const float* W; const float* Bv; int jj, Nseg;
    if (j < N_ORDER)                      { W=ow; Bv=ob; jj=j;                     Nseg=N_ORDER; }
    else if (j < N_ORDER+N_FAMILY)        { W=fw; Bv=fb; jj=j-N_ORDER;             Nseg=N_FAMILY; }
    else if (j < N_ORDER+N_FAMILY+N_GENUS){ W=gw; Bv=gb; jj=j-N_ORDER-N_FAMILY;    Nseg=N_GENUS; }
    else                                  { W=sw; Bv=sb; jj=j-N_ORDER-N_FAMILY-N_GENUS; Nseg=N_SPECIES; }

    float acc[BB];
    #pragma unroll
    for (int b=0;b<BB;b++) acc[b]=0.f;
    for (int k=0;k<DM;k++){
        float wv = W[(size_t)k*Nseg + jj];
        const float4* row = (const float4*)&sf[k*BB];
        #pragma unroll
        for (int bq=0;bq<8;bq++){
            float4 f = row[bq];
            acc[4*bq+0] = fmaf(f.x, wv, acc[4*bq+0]);
            acc[4*bq+1] = fmaf(f.y, wv, acc[4*bq+1]);
            acc[4*bq+2] = fmaf(f.z, wv, acc[4*bq+2]);
            acc[4*bq+3] = fmaf(f.w, wv, acc[4*bq+3]);
        }
    }
    float bias = Bv[jj];
    #pragma unroll
    for (int b=0;b<BB;b++) out[(size_t)b*NOUT + j] = acc[b] + bias;
}

// ---------------- orchestration ----------------
extern "C" void kernel_launch(void* const* d_in, const int* in_sizes, int n_in,
                              void* d_out, int out_size)
{
    const int*   tokens = (const int*)  d_in[0];
    const float* emb    = (const float*)d_in[1];
    const float* ln_w   = (const float*)d_in[2];
    const float* ln_b   = (const float*)d_in[3];
    const float* Win    = (const float*)d_in[4];
    const float* cw     = (const float*)d_in[5];
    const float* cb     = (const float*)d_in[6];
    const float* dtb    = (const float*)d_in[7];
    const float* alog   = (const float*)d_in[8];
    const float* Dd     = (const float*)d_in[9];
    const float* gnw    = (const float*)d_in[10];
    const float* Wout   = (const float*)d_in[11];
    const float* nfw    = (const float*)d_in[12];
    const float* nfb    = (const float*)d_in[13];
    const float* plw    = (const float*)d_in[14];
    const float* plb    = (const float*)d_in[15];
    const float* ow     = (const float*)d_in[16];
    const float* ob     = (const float*)d_in[17];
    const float* fw     = (const float*)d_in[18];
    const float* fb     = (const float*)d_in[19];
    const float* gw     = (const float*)d_in[20];
    const float* gb     = (const float*)d_in[21];
    const float* sw     = (const float*)d_in[22];
    const float* sb     = (const float*)d_in[23];
    float* out = (float*)d_out;

    const int smem_bytes = SMEM_FLOATS * 4;
    cudaFuncSetAttribute((const void*)gemm_tc<0,1>, cudaFuncAttributeMaxDynamicSharedMemorySize, smem_bytes);
    cudaFuncSetAttribute((const void*)gemm_tc<1,2>, cudaFuncAttributeMaxDynamicSharedMemorySize, smem_bytes);
    cudaFuncSetAttribute((const void*)ssd_local_kernel, cudaFuncAttributeMaxDynamicSharedMemorySize, SSD_A_SMEM);

    wcvt_t_kernel<<<dim3((DIP+31)/32, (DI+31)/32, 4), 256>>>(Win, Wout);
    embed_ln_kernel<<<NT, 128>>>(tokens, emb, ln_w, ln_b);

    for (int l = 0; l < 2; l++) {
        if (l > 0) ln_kernel<<<NT, 128>>>(ln_w + l*DM, ln_b + l*DM, 1);
        gemm_tc<0,1><<<dim3((DIP+GBN-1)/GBN, NT/GBM, 1), 256, smem_bytes>>>(l);
        conv_dtda_kernel<<<CONV_BLKS + DTDA_BLKS, 224>>>(cw + (size_t)l*CD*4, cb + l*CD,
                                                         dtb + l*NH, alog + l*NH);
        ssd_local_kernel  <<<BB*NH*NCHUNK, 128, SSD_A_SMEM>>>();
        ssd_combine_kernel<<<BB*NH, 128>>>();
        ssd_fix_kernel    <<<BB*NH*(NCHUNK-1), 128>>>();
        gate_rms_kernel<<<NT, 256>>>(Dd + l*NH, gnw + l*DI);
        gemm_tc<1,2><<<dim3((DM+GBN-1)/GBN, NT/GBM, 2), 256, smem_bytes>>>(l);
    }

    ln_kernel<<<NT, 128>>>(nfw, nfb, 0);
    pool1_kernel<<<BB*16, 128>>>();
    pool2_kernel<<<BB, 128>>>(plw, plb);
    heads_kernel<<<(NOUT + 255)/256, 256>>>(ow, ob, fw, fb, gw, gb, sw, sb, out);
}

// round 14
// speedup vs baseline: 1.2642x; 1.0483x over previous
#include <cuda_runtime.h>
#include <math.h>
#include <stddef.h>
#include <stdint.h>

typedef unsigned long long ull;

// ---------------- problem constants ----------------
#define BB   32
#define LL   512
#define DM   384
#define DI   768
#define DS   64
#define NH   16
#define HD   48
#define DIP  1680
#define CD   896
#define NT   (BB*LL)
#define NOUT 38667
#define N_ORDER 60
#define N_FAMILY 427
#define N_GENUS 14216
#define N_SPECIES 23964

#define WIN1  (DM*DIP)
#define WOUT1 (DI*DM)

#define NCHUNK 8
#define CLEN   64
#define SFL    3072          // DS*HD floats per (b,h,chunk) state

// k-permutation within each 8-group: pos = k<4 ? 2k : 2(k-4)+1
__device__ __forceinline__ int kperm(int k){
    int j = k & 7;
    return (k & ~7) | ((j<4) ? (j<<1) : (((j-4)<<1)|1));
}

// ---------------- scratch ----------------
__device__ float g_resid[(size_t)NT*DM];
__device__ float g_h    [(size_t)NT*DM];
__device__ float g_zx   [(size_t)NT*DIP];
__device__ float g_xBC  [(size_t)NT*CD];
__device__ float g_dt   [(size_t)NT*NH];
__device__ float g_dA   [(size_t)NT*NH];    // stores log(dA) = -exp(A_log)*dt
__device__ float g_lc   [(size_t)NT*NH];    // chunk-local cumsum of log dA
__device__ float g_ys   [(size_t)NT*DI];
__device__ float g_yn   [(size_t)NT*DI];
__device__ float g_wtB  [2*WIN1 + 2*WOUT1];
__device__ float g_state[(size_t)BB*NH*NCHUNK*SFL];
__device__ float g_sin  [(size_t)BB*NH*NCHUNK*SFL];
__device__ float g_pool [BB*16*DM];
__device__ float g_featT[DM*BB];

__device__ __forceinline__ uint32_t f2tf(float x){
    uint32_t y;
    asm volatile("cvt.rna.tf32.f32 %0, %1;" : "=r"(y) : "f"(x));
    return y;
}
__device__ __forceinline__ void upk2u(uint32_t& lo, uint32_t& hi, ull v){
    asm("mov.b64 {%0, %1}, %2;" : "=r"(lo), "=r"(hi) : "l"(v));
}

// ---------------- weight transpose + permute + tf32 convert ----------------
__global__ __launch_bounds__(256) void wcvt_t_kernel(const float* __restrict__ Win,
                                                     const float* __restrict__ Wout)
{
    int r = blockIdx.z;
    const float* src; float* dst; int K_, N_;
    if (r < 2){ src = Win  + (size_t)r*WIN1;      dst = g_wtB + (size_t)r*WIN1;              K_ = DM; N_ = DIP; }
    else      { src = Wout + (size_t)(r-2)*WOUT1; dst = g_wtB + 2*WIN1 + (size_t)(r-2)*WOUT1; K_ = DI; N_ = DM; }
    int k0 = blockIdx.y*32, n0 = blockIdx.x*32;
    if (k0 >= K_ || n0 >= N_) return;
    __shared__ float sm[32][33];
    int tx = threadIdx.x & 31, ty = threadIdx.x >> 5;
    #pragma unroll
    for (int q=0;q<4;q++){
        int k = k0 + ty + q*8;
        if (k < K_ && n0+tx < N_) sm[ty+q*8][tx] = src[(size_t)k*N_ + n0+tx];
    }
    __syncthreads();
    #pragma unroll
    for (int q=0;q<4;q++){
        int n = n0 + ty + q*8;
        int k = k0 + tx;
        if (n < N_ && k < K_)
            dst[(size_t)n*K_ + kperm(k)] = __uint_as_float(f2tf(sm[tx][ty+q*8]));
    }
}

// ---------------- fused embedding + layer-0 layernorm (k-permuted) ----------------
__global__ __launch_bounds__(128) void embed_ln_kernel(const int* __restrict__ tokens,
                                                       const float* __restrict__ emb,
                                                       const float* __restrict__ w,
                                                       const float* __restrict__ b)
{
    __shared__ float red[128];
    int row = blockIdx.x, tid = threadIdx.x;
    const float* er = emb + (size_t)tokens[row]*DM;
    float v0 = er[tid], v1 = er[tid+128], v2 = er[tid+256];
    float* rr = g_resid + (size_t)row*DM;
    rr[tid] = v0; rr[tid+128] = v1; rr[tid+256] = v2;

    red[tid] = v0+v1+v2; __syncthreads();
    for (int s=64;s>0;s>>=1){ if(tid<s) red[tid]+=red[tid+s]; __syncthreads(); }
    float mu = red[0] * (1.0f/DM);
    __syncthreads();
    float d0=v0-mu, d1=v1-mu, d2=v2-mu;
    red[tid] = d0*d0+d1*d1+d2*d2; __syncthreads();
    for (int s=64;s>0;s>>=1){ if(tid<s) red[tid]+=red[tid+s]; __syncthreads(); }
    float inv = rsqrtf(red[0]*(1.0f/DM) + 1e-5f);
    float* o = g_h + (size_t)row*DM;
    o[kperm(tid)]     = __uint_as_float(f2tf(d0*inv*w[tid]     + b[tid]));
    o[kperm(tid+128)] = __uint_as_float(f2tf(d1*inv*w[tid+128] + b[tid+128]));
    o[kperm(tid+256)] = __uint_as_float(f2tf(d2*inv*w[tid+256] + b[tid+256]));
}

// ---------------- layernorm: g_resid -> g_h ----------------
__global__ __launch_bounds__(128) void ln_kernel(const float* __restrict__ w, const float* __restrict__ b, int tf)
{
    __shared__ float red[128];
    int row = blockIdx.x, tid = threadIdx.x;
    const float* xr = g_resid + (size_t)row*DM;
    float v0 = xr[tid], v1 = xr[tid+128], v2 = xr[tid+256];
    red[tid] = v0+v1+v2; __syncthreads();
    for (int s=64;s>0;s>>=1){ if(tid<s) red[tid]+=red[tid+s]; __syncthreads(); }
    float mu = red[0] * (1.0f/DM);
    __syncthreads();
    float d0=v0-mu, d1=v1-mu, d2=v2-mu;
    red[tid] = d0*d0+d1*d1+d2*d2; __syncthreads();
    for (int s=64;s>0;s>>=1){ if(tid<s) red[tid]+=red[tid+s]; __syncthreads(); }
    float inv = rsqrtf(red[0]*(1.0f/DM) + 1e-5f);
    float o0 = d0*inv*w[tid]     + b[tid];
    float o1 = d1*inv*w[tid+128] + b[tid+128];
    float o2 = d2*inv*w[tid+256] + b[tid+256];
    float* o = g_h + (size_t)row*DM;
    if (tf){
        o[kperm(tid)]     = __uint_as_float(f2tf(o0));
        o[kperm(tid+128)] = __uint_as_float(f2tf(o1));
        o[kperm(tid+256)] = __uint_as_float(f2tf(o2));
    } else {
        o[tid] = o0; o[tid+128] = o1; o[tid+256] = o2;
    }
}

// ---------------- tf32 mma helper ----------------
__device__ __forceinline__ void mma_tf32(float* c, const uint32_t* a, const uint32_t* b){
    asm volatile(
      "mma.sync.aligned.m16n8k8.row.col.f32.tf32.tf32.f32 "
      "{%0,%1,%2,%3}, {%4,%5,%6,%7}, {%8,%9}, {%0,%1,%2,%3};\n"
      : "+f"(c[0]), "+f"(c[1]), "+f"(c[2]), "+f"(c[3])
      : "r"(a[0]), "r"(a[1]), "r"(a[2]), "r"(a[3]), "r"(b[0]), "r"(b[1]));
}

// ---------------- tf32 tensor-core GEMM (R8-proven; float2 epilogue for MODE 0) ----------------
#define GBM 128
#define GBN 128
#define GBK 16
#define NSTAGE 4
#define TSTR 24
#define AS_FLOATS (GBM*TSTR)
#define BS_FLOATS (GBN*TSTR)
#define SMEM_FLOATS (NSTAGE*(AS_FLOATS+BS_FLOATS))

template<int MODE, int SPLITK>
__global__ __launch_bounds__(256,2) void gemm_tc(int layer)
{
    const float* __restrict__ A = (MODE==0) ? g_h : g_yn;
    const float* __restrict__ W = (MODE==0) ? (g_wtB + (size_t)layer*WIN1)
                                            : (g_wtB + 2*WIN1 + (size_t)layer*WOUT1);
    float* C = (MODE==0) ? g_zx : g_resid;
    const int N = (MODE==0) ? DIP : DM;
    const int K = (MODE==0) ? DM  : DI;
    const int Ks = K / SPLITK;
    const int k_origin = blockIdx.z * Ks;

    extern __shared__ float sh[];
    float* shB = sh + NSTAGE*AS_FLOATS;

    int tid  = threadIdx.x;
    int warp = tid >> 5;
    int lane = tid & 31;
    int gid  = lane >> 2;
    int tig  = lane & 3;

    int m0 = blockIdx.y * GBM;
    int n0 = blockIdx.x * GBN;
    int wm = (warp & 1) * 64;
    int wn = (warp >> 1) * 32;

    float acc[4][4][4];
    #pragma unroll
    for (int i=0;i<4;i++)
        #pragma unroll
        for (int j=0;j<4;j++)
            #pragma unroll
            for (int q=0;q<4;q++) acc[i][j][q]=0.f;

    const int niter = Ks / GBK;

    int row0 = tid >> 2,        kc0 = (tid & 3) << 2;
    int row1 = (tid+256) >> 2,  kc1 = (tid & 3) << 2;
    int b_ok0 = (n0 + row0 < N) ? 16 : 0;
    int b_ok1 = (n0 + row1 < N) ? 16 : 0;
    const float* asrc0 = A + (size_t)(m0 + row0)*K + k_origin + kc0;
    const float* asrc1 = A + (size_t)(m0 + row1)*K + k_origin + kc1;
    const float* bsrc0 = W + (size_t)((n0 + row0 < N) ? (n0 + row0) : 0)*K + k_origin + kc0;
    const float* bsrc1 = W + (size_t)((n0 + row1 < N) ? (n0 + row1) : 0)*K + k_origin + kc1;

    uint32_t adst0 = (uint32_t)__cvta_generic_to_shared(&sh [row0*TSTR + kc0]);
    uint32_t adst1 = (uint32_t)__cvta_generic_to_shared(&sh [row1*TSTR + kc1]);
    uint32_t bdst0 = (uint32_t)__cvta_generic_to_shared(&shB[row0*TSTR + kc0]);
    uint32_t bdst1 = (uint32_t)__cvta_generic_to_shared(&shB[row1*TSTR + kc1]);

    auto issue_copy = [&](int st, int it){
        int k0 = it * GBK;
        uint32_t ao = st*AS_FLOATS*4, bo = st*BS_FLOATS*4;
        asm volatile("cp.async.cg.shared.global [%0], [%1], 16;\n"
                     :: "r"(adst0 + ao), "l"(asrc0 + k0));
        asm volatile("cp.async.cg.shared.global [%0], [%1], 16;\n"
                     :: "r"(adst1 + ao), "l"(asrc1 + k0));
        asm volatile("cp.async.cg.shared.global [%0], [%1], 16, %2;\n"
                     :: "r"(bdst0 + bo), "l"(bsrc0 + k0), "r"(b_ok0));
        asm volatile("cp.async.cg.shared.global [%0], [%1], 16, %2;\n"
                     :: "r"(bdst1 + bo), "l"(bsrc1 + k0), "r"(b_ok1));
    };

    #pragma unroll
    for (int st=0; st<NSTAGE-1; st++){
        if (st < niter) issue_copy(st, st);
        asm volatile("cp.async.commit_group;\n");
    }

    for (int it=0; it<niter; ++it){
        asm volatile("cp.async.wait_group %0;\n" :: "n"(NSTAGE-2));
        __syncthreads();

        int cb = it & (NSTAGE-1);
        const float* Asb = &sh [cb*AS_FLOATS];
        const float* Bsb = &shB[cb*BS_FLOATS];

        #pragma unroll
        for (int ks=0; ks<GBK; ks+=8){
            uint32_t af[4][4], bf[4][2];
            #pragma unroll
            for (int mi=0; mi<4; mi++){
                int mr = wm + 16*mi;
                ull lo8 = *(const ull*)&Asb[(mr+gid  )*TSTR + ks + 2*tig];
                ull hi8 = *(const ull*)&Asb[(mr+gid+8)*TSTR + ks + 2*tig];
                upk2u(af[mi][0], af[mi][2], lo8);
                upk2u(af[mi][1], af[mi][3], hi8);
            }
            #pragma unroll
            for (int ni=0; ni<4; ni++){
                int nb = wn + 8*ni;
                ull bb = *(const ull*)&Bsb[(nb+gid)*TSTR + ks + 2*tig];
                upk2u(bf[ni][0], bf[ni][1], bb);
            }
            #pragma unroll
            for (int mi=0; mi<4; mi++)
                #pragma unroll
                for (int ni=0; ni<4; ni++)
                    mma_tf32(acc[mi][ni], af[mi], bf[ni]);
        }

        int nx = it + NSTAGE - 1;
        if (nx < niter) issue_copy(nx & (NSTAGE-1), nx);
        asm volatile("cp.async.commit_group;\n");
    }

    #pragma unroll
    for (int mi=0; mi<4; mi++){
        int r0 = m0 + wm + 16*mi + gid;
        #pragma unroll
        for (int ni=0; ni<4; ni++){
            int c0 = n0 + wn + 8*ni + 2*tig;
            float* a = acc[mi][ni];
            if (MODE){
                #pragma unroll
                for (int half=0; half<2; half++){
                    int cc = c0 + half;
                    if (cc < N){
                        atomicAdd(&C[(size_t)r0*N + cc],     a[half]);
                        atomicAdd(&C[(size_t)(r0+8)*N + cc], a[2+half]);
                    }
                }
            } else {
                if (c0 + 1 < N){
                    *(float2*)&C[(size_t)r0*N + c0]     = make_float2(a[0], a[1]);
                    *(float2*)&C[(size_t)(r0+8)*N + c0] = make_float2(a[2], a[3]);
                } else if (c0 < N){
                    C[(size_t)r0*N + c0]     = a[0];
                    C[(size_t)(r0+8)*N + c0] = a[2];
                }
            }
        }
    }
}

// ---------------- fused conv (8-step chunks) + dt/logdA ----------------
#define CONV_BLKS (BB*64)
#define DTDA_TOT  (NT*(NH/4))
#define DTDA_BLKS ((DTDA_TOT + 223)/224)
__global__ __launch_bounds__(224) void conv_dtda_kernel(const float* __restrict__ cw, const float* __restrict__ cb,
                                                        const float* __restrict__ dtb, const float* __restrict__ alog)
{
    int blk = blockIdx.x;
    int tid = threadIdx.x;
    if (blk < CONV_BLKS){
        int b  = blk >> 6;
        int tc = blk & 63;
        int t0 = tc * 8;
        int c  = tid << 2;

        float4 tw[4];
        #pragma unroll
        for (int k=0;k<4;k++){
            tw[k].x = cw[(c+0)*4+k];
            tw[k].y = cw[(c+1)*4+k];
            tw[k].z = cw[(c+2)*4+k];
            tw[k].w = cw[(c+3)*4+k];
        }
        float4 bias = *(const float4*)&cb[c];

        const float* base = g_zx + (size_t)(b*LL + t0)*DIP + DI + c;
        float* obase = g_xBC + (size_t)(b*LL + t0)*CD + c;

        float4 p1, p2, p3;
        if (t0 > 0){
            p1 = *(const float4*)(base - 3*DIP);
            p2 = *(const float4*)(base - 2*DIP);
            p3 = *(const float4*)(base - 1*DIP);
        } else {
            p1 = p2 = p3 = make_float4(0.f,0.f,0.f,0.f);
        }

        #pragma unroll
        for (int i=0;i<8;i++){
            float4 v = *(const float4*)(base + (size_t)i*DIP);
            float4 a;
            a.x = bias.x + p1.x*tw[0].x + p2.x*tw[1].x + p3.x*tw[2].x + v.x*tw[3].x;
            a.y = bias.y + p1.y*tw[0].y + p2.y*tw[1].y + p3.y*tw[2].y + v.y*tw[3].y;
            a.z = bias.z + p1.z*tw[0].z + p2.z*tw[1].z + p3.z*tw[2].z + v.z*tw[3].z;
            a.w = bias.w + p1.w*tw[0].w + p2.w*tw[1].w + p3.w*tw[2].w + v.w*tw[3].w;
            float4 r;
            r.x = a.x / (1.f + __expf(-a.x));
            r.y = a.y / (1.f + __expf(-a.y));
            r.z = a.z / (1.f + __expf(-a.z));
            r.w = a.w / (1.f + __expf(-a.w));
            *(float4*)(obase + (size_t)i*CD) = r;
            p1 = p2; p2 = p3; p3 = v;
        }
    } else {
        int j = (blk - CONV_BLKS)*224 + tid;
        if (j >= DTDA_TOT) return;
        int hq = (j & 3) << 2;
        int bt = j >> 2;
        #pragma unroll
        for (int q=0;q<4;q++){
            int hh = hq + q;
            float raw = g_zx[(size_t)bt*DIP + (DIP-NH) + hh] + dtb[hh];
            float sp = (raw > 20.f) ? raw : log1pf(expf(raw));
            g_dt[bt*NH + hh] = sp;
            g_dA[bt*NH + hh] = -expf(alog[hh]) * sp;    // log(dA)
        }
    }
}

// ---------------- SSD scan pass A: local scan + fused D*x ----------------
#define SA_STR 68
#define SSD_A_SMEM ((3*64*SA_STR + 2*48*SA_STR + 192)*4)

__global__ __launch_bounds__(128) void ssd_local_kernel(const float* __restrict__ Dp)
{
    int blk = blockIdx.x;           // BB*NH*NCHUNK
    int c  = blk & (NCHUNK-1);
    int bh = blk >> 3;
    int b  = bh >> 4;
    int h  = bh & 15;
    int tid = threadIdx.x;
    int warp = tid >> 5, lane = tid & 31, gid = lane >> 2, tig = lane & 3;
    int bt0 = b*LL + c*CLEN;

    extern __shared__ float sa[];
    float* sC   = sa;
    float* sBW  = sC  + 64*SA_STR;
    float* sBT  = sBW + 64*SA_STR;
    float* sXT  = sBT + 64*SA_STR;
    float* sXwT = sXT + 48*SA_STR;
    float* lc_sh = sXwT + 48*SA_STR;
    float* dt_sh = lc_sh + 64;
    float* w2_sh = dt_sh + 64;

    for (int i = tid; i < 64*16; i += 128){
        int t = i >> 4, q = (i & 15) << 2;
        const float* row = g_xBC + (size_t)(bt0+t)*CD + DI;
        float4 vb = *(const float4*)(row + q);
        float4 vc = *(const float4*)(row + DS + q);
        *(float4*)&sBW[t*SA_STR + q] = vb;
        *(float4*)&sC [t*SA_STR + q] = vc;
        sBT[(q+0)*SA_STR + t] = vb.x;
        sBT[(q+1)*SA_STR + t] = vb.y;
        sBT[(q+2)*SA_STR + t] = vb.z;
        sBT[(q+3)*SA_STR + t] = vb.w;
    }
    for (int i = tid; i < 64*12; i += 128){
        int t = i / 12, q = (i % 12) << 2;
        float4 vx = *(const float4*)(g_xBC + (size_t)(bt0+t)*CD + h*HD + q);
        sXT[(q+0)*SA_STR + t] = vx.x;
        sXT[(q+1)*SA_STR + t] = vx.y;
        sXT[(q+2)*SA_STR + t] = vx.z;
        sXT[(q+3)*SA_STR + t] = vx.w;
    }
    if (tid < 64) dt_sh[tid] = g_dt[(size_t)(bt0+tid)*NH + h];
    if (warp == 0){
        float v0 = g_dA[(size_t)(bt0+lane)*NH + h];
        float v1 = g_dA[(size_t)(bt0+32+lane)*NH + h];
        #pragma unroll
        for (int d=1; d<32; d<<=1){
            float u0 = __shfl_up_sync(0xffffffffu, v0, d);
            float u1 = __shfl_up_sync(0xffffffffu, v1, d);
            if (lane >= d){ v0 += u0; v1 += u1; }
        }
        float tot = __shfl_sync(0xffffffffu, v0, 31);
        v1 += tot;
        lc_sh[lane]    = v0;
        lc_sh[32+lane] = v1;
        g_lc[(size_t)(bt0+lane)*NH + h]    = v0;
        g_lc[(size_t)(bt0+32+lane)*NH + h] = v1;
    }
    __syncthreads();

    int wt0 = warp*16;
    float gacc[8][4];
    #pragma unroll
    for (int ni=0;ni<8;ni++){ gacc[ni][0]=0.f; gacc[ni][1]=0.f; gacc[ni][2]=0.f; gacc[ni][3]=0.f; }
    #pragma unroll
    for (int kk=0; kk<64; kk+=8){
        uint32_t af[4];
        af[0] = __float_as_uint(sC[(wt0+gid  )*SA_STR + kk+tig  ]);
        af[1] = __float_as_uint(sC[(wt0+gid+8)*SA_STR + kk+tig  ]);
        af[2] = __float_as_uint(sC[(wt0+gid  )*SA_STR + kk+tig+4]);
        af[3] = __float_as_uint(sC[(wt0+gid+8)*SA_STR + kk+tig+4]);
        #pragma unroll
        for (int ni=0; ni<8; ni++){
            uint32_t bf[2];
            bf[0] = __float_as_uint(sBW[(8*ni+gid)*SA_STR + kk+tig  ]);
            bf[1] = __float_as_uint(sBW[(8*ni+gid)*SA_STR + kk+tig+4]);
            mma_tf32(gacc[ni], af, bf);
        }
    }
    if (tid < 64) w2_sh[tid] = __expf(lc_sh[63] - lc_sh[tid]) * dt_sh[tid];
    __syncthreads();

    {
        int t0r = wt0 + gid, t1r = t0r + 8;
        float lct0 = lc_sh[t0r], lct1 = lc_sh[t1r];
        #pragma unroll
        for (int ni=0; ni<8; ni++){
            int s0 = 8*ni + 2*tig, s1 = s0 + 1;
            float lcs0 = lc_sh[s0], lcs1 = lc_sh[s1];
            float d0 = dt_sh[s0],   d1 = dt_sh[s1];
            sBW[t0r*SA_STR + s0] = (s0<=t0r) ? gacc[ni][0]*__expf(lct0-lcs0)*d0 : 0.f;
            sBW[t0r*SA_STR + s1] = (s1<=t0r) ? gacc[ni][1]*__expf(lct0-lcs1)*d1 : 0.f;
            sBW[t1r*SA_STR + s0] = (s0<=t1r) ? gacc[ni][2]*__expf(lct1-lcs0)*d0 : 0.f;
            sBW[t1r*SA_STR + s1] = (s1<=t1r) ? gacc[ni][3]*__expf(lct1-lcs1)*d1 : 0.f;
        }
    }
    for (int i = tid; i < 48*64; i += 128){
        int p = i >> 6, s = i & 63;
        sXwT[p*SA_STR + s] = sXT[p*SA_STR + s] * w2_sh[s];
    }
    __syncthreads();

    float yacc[6][4], sacc[6][4];
    #pragma unroll
    for (int ni=0;ni<6;ni++){
        yacc[ni][0]=yacc[ni][1]=yacc[ni][2]=yacc[ni][3]=0.f;
        sacc[ni][0]=sacc[ni][1]=sacc[ni][2]=sacc[ni][3]=0.f;
    }
    #pragma unroll
    for (int kk=0; kk<64; kk+=8){
        uint32_t afW[4], afB[4];
        afW[0] = __float_as_uint(sBW[(wt0+gid  )*SA_STR + kk+tig  ]);
        afW[1] = __float_as_uint(sBW[(wt0+gid+8)*SA_STR + kk+tig  ]);
        afW[2] = __float_as_uint(sBW[(wt0+gid  )*SA_STR + kk+tig+4]);
        afW[3] = __float_as_uint(sBW[(wt0+gid+8)*SA_STR + kk+tig+4]);
        afB[0] = __float_as_uint(sBT[(wt0+gid  )*SA_STR + kk+tig  ]);
        afB[1] = __float_as_uint(sBT[(wt0+gid+8)*SA_STR + kk+tig  ]);
        afB[2] = __float_as_uint(sBT[(wt0+gid  )*SA_STR + kk+tig+4]);
        afB[3] = __float_as_uint(sBT[(wt0+gid+8)*SA_STR + kk+tig+4]);
        #pragma unroll
        for (int ni=0; ni<6; ni++){
            uint32_t bfX[2], bfW2[2];
            bfX[0]  = __float_as_uint(sXT [(8*ni+gid)*SA_STR + kk+tig  ]);
            bfX[1]  = __float_as_uint(sXT [(8*ni+gid)*SA_STR + kk+tig+4]);
            mma_tf32(yacc[ni], afW, bfX);
            bfW2[0] = __float_as_uint(sXwT[(8*ni+gid)*SA_STR + kk+tig  ]);
            bfW2[1] = __float_as_uint(sXwT[(8*ni+gid)*SA_STR + kk+tig+4]);
            mma_tf32(sacc[ni], afB, bfW2);
        }
    }

    float Dh = Dp[h];
    size_t sbase = ((size_t)bh*NCHUNK + c)*SFL;
    #pragma unroll
    for (int ni=0; ni<6; ni++){
        int p = 8*ni + 2*tig;
        int tr = wt0 + gid;
        // fused skip term: y += D_h * x (x still resident in smem)
        float y0a = yacc[ni][0] + Dh*sXT[(p  )*SA_STR + tr];
        float y0b = yacc[ni][1] + Dh*sXT[(p+1)*SA_STR + tr];
        float y1a = yacc[ni][2] + Dh*sXT[(p  )*SA_STR + tr+8];
        float y1b = yacc[ni][3] + Dh*sXT[(p+1)*SA_STR + tr+8];
        float* y0 = &g_ys[(size_t)(bt0+tr)*DI + h*HD + p];
        *(float2*)y0            = make_float2(y0a, y0b);
        *(float2*)(y0 + 8*DI)   = make_float2(y1a, y1b);
        float* s0 = &g_state[sbase + tr*HD + p];
        *(float2*)s0            = make_float2(sacc[ni][0], sacc[ni][1]);
        *(float2*)(s0 + 8*HD)   = make_float2(sacc[ni][2], sacc[ni][3]);
    }
}

// ---------------- SSD pass B: sequential chunk-state combine (float4) ----------------
__global__ __launch_bounds__(128) void ssd_combine_kernel()
{
    int bh = blockIdx.x;
    int b  = bh >> 4;
    int h  = bh & 15;
    int tid = threadIdx.x;
    size_t base = (size_t)bh*NCHUNK*SFL;

    float4 sin[SFL/512];
    #pragma unroll
    for (int j=0;j<SFL/512;j++) sin[j]=make_float4(0.f,0.f,0.f,0.f);

    for (int c=0;c<NCHUNK-1;c++){
        float ef = __expf(g_lc[(size_t)(b*LL + c*CLEN + CLEN-1)*NH + h]);
        #pragma unroll
        for (int j=0;j<SFL/512;j++){
            float4 S = *(const float4*)&g_state[base + (size_t)c*SFL + j*512 + tid*4];
            sin[j].x = sin[j].x*ef + S.x;
            sin[j].y = sin[j].y*ef + S.y;
            sin[j].z = sin[j].z*ef + S.z;
            sin[j].w = sin[j].w*ef + S.w;
        }
        #pragma unroll
        for (int j=0;j<SFL/512;j++)
            *(float4*)&g_sin[base + (size_t)(c+1)*SFL + j*512 + tid*4] = sin[j];
    }
}

// ---------------- SSD pass C: y += exp(lc_t) * (C @ S_in) ----------------
__global__ __launch_bounds__(128) void ssd_fix_kernel()
{
    int blk = blockIdx.x;
    int bh  = blk / (NCHUNK-1);
    int c   = blk - bh*(NCHUNK-1) + 1;
    int b   = bh >> 4;
    int h   = bh & 15;
    int tid = threadIdx.x;
    int warp = tid >> 5, lane = tid & 31, gid = lane >> 2, tig = lane & 3;
    int bt0 = b*LL + c*CLEN;

    __shared__ float sC2[64*SA_STR];
    __shared__ float sST[48*SA_STR];
    __shared__ float lc2[64];

    for (int i = tid; i < 64*16; i += 128){
        int t = i >> 4, q = (i & 15) << 2;
        float4 vc = *(const float4*)(g_xBC + (size_t)(bt0+t)*CD + DI + DS + q);
        *(float4*)&sC2[t*SA_STR + q] = vc;
    }
    size_t sbase = ((size_t)bh*NCHUNK + c)*SFL;
    for (int i = tid; i < SFL; i += 128){
        int n = i / HD, p = i - n*HD;
        sST[p*SA_STR + n] = g_sin[sbase + i];
    }
    if (tid < 64) lc2[tid] = g_lc[(size_t)(bt0+tid)*NH + h];
    __syncthreads();

    int wt0 = warp*16;
    float facc[6][4];
    #pragma unroll
    for (int ni=0;ni<6;ni++){ facc[ni][0]=facc[ni][1]=facc[ni][2]=facc[ni][3]=0.f; }
    #pragma unroll
    for (int kk=0; kk<64; kk+=8){
        uint32_t af[4];
        af[0] = __float_as_uint(sC2[(wt0+gid  )*SA_STR + kk+tig  ]);
        af[1] = __float_as_uint(sC2[(wt0+gid+8)*SA_STR + kk+tig  ]);
        af[2] = __float_as_uint(sC2[(wt0+gid  )*SA_STR + kk+tig+4]);
        af[3] = __float_as_uint(sC2[(wt0+gid+8)*SA_STR + kk+tig+4]);
        #pragma unroll
        for (int ni=0; ni<6; ni++){
            uint32_t bf[2];
            bf[0] = __float_as_uint(sST[(8*ni+gid)*SA_STR + kk+tig  ]);
            bf[1] = __float_as_uint(sST[(8*ni+gid)*SA_STR + kk+tig+4]);
            mma_tf32(facc[ni], af, bf);
        }
    }

    int tr = wt0 + gid;
    float e0 = __expf(lc2[tr]);
    float e1 = __expf(lc2[tr+8]);
    #pragma unroll
    for (int ni=0; ni<6; ni++){
        int p = 8*ni + 2*tig;
        float2* y0 = (float2*)&g_ys[(size_t)(bt0+tr)*DI + h*HD + p];
        float2 v0 = *y0; v0.x += e0*facc[ni][0]; v0.y += e0*facc[ni][1]; *y0 = v0;
        float2* y1 = (float2*)&g_ys[(size_t)(bt0+tr+8)*DI + h*HD + p];
        float2 v1 = *y1; v1.x += e1*facc[ni][2]; v1.y += e1*facc[ni][3]; *y1 = v1;
    }
}

// ---------------- y = ys * silu(z); RMS-norm -> g_yn (tf32, k-permuted) ----------------
// (D*x already folded into ys by ssd_local)
__global__ __launch_bounds__(256) void gate_rms_kernel(const float* __restrict__ gnorm)
{
    __shared__ float red[256];
    int row = blockIdx.x, tid = threadIdx.x;
    float v[3]; float ss = 0.f;
    #pragma unroll
    for (int q=0;q<3;q++){
        int i = tid + q*256;
        float ys = g_ys[(size_t)row*DI + i];
        float z  = g_zx [(size_t)row*DIP + i];
        float val = ys * (z / (1.f + __expf(-z)));
        v[q] = val; ss += val*val;
    }
    red[tid] = ss; __syncthreads();
    for (int s=128;s>0;s>>=1){ if(tid<s) red[tid]+=red[tid+s]; __syncthreads(); }
    float scale = rsqrtf(red[0]*(1.0f/DI) + 1e-5f);
    #pragma unroll
    for (int q=0;q<3;q++){
        int i = tid + q*256;
        g_yn[(size_t)row*DI + kperm(i)] = __uint_as_float(f2tf(v[q]*scale*gnorm[i]));
    }
}

// ---------------- pool stage 1 ----------------
__global__ __launch_bounds__(128) void pool1_kernel()
{
    int blk = blockIdx.x;
    int b   = blk >> 4;
    int tc  = blk & 15;
    int tid = threadIdx.x;
    #pragma unroll
    for (int q=0;q<3;q++){
        int d = tid + q*128;
        const float* p = g_h + (size_t)(b*LL + tc*32)*DM + d;
        float s = 0.f;
        #pragma unroll 8
        for (int t=0;t<32;t++) s += p[(size_t)t*DM];
        g_pool[blk*DM + d] = s;
    }
}

// ---------------- pool stage 2 ----------------
__global__ __launch_bounds__(128) void pool2_kernel(const float* __restrict__ w,
                                                    const float* __restrict__ b2)
{
    __shared__ float red[128];
    int b = blockIdx.x, tid = threadIdx.x;
    float v[3];
    #pragma unroll
    for (int q=0;q<3;q++){
        int d = tid + q*128;
        float s = 0.f;
        #pragma unroll
        for (int tc=0;tc<16;tc++) s += g_pool[(b*16+tc)*DM + d];
        v[q] = s * (1.0f/LL);
    }
    red[tid] = v[0]+v[1]+v[2]; __syncthreads();
    for (int s=64;s>0;s>>=1){ if(tid<s) red[tid]+=red[tid+s]; __syncthreads(); }
    float mu = red[0]*(1.0f/DM);
    __syncthreads();
    float d0=v[0]-mu, d1=v[1]-mu, d2=v[2]-mu;
    red[tid] = d0*d0+d1*d1+d2*d2; __syncthreads();
    for (int s=64;s>0;s>>=1){ if(tid<s) red[tid]+=red[tid+s]; __syncthreads(); }
    float inv = rsqrtf(red[0]*(1.0f/DM) + 1e-5f);
    g_featT[(tid    )*BB + b] = d0*inv*w[tid]     + b2[tid];
    g_featT[(tid+128)*BB + b] = d1*inv*w[tid+128] + b2[tid+128];
    g_featT[(tid+256)*BB + b] = d2*inv*w[tid+256] + b2[tid+256];
}

// ---------------- classification heads (R8 form) ----------------
__global__ __launch_bounds__(256) void heads_kernel(
    const float* __restrict__ ow, const float* __restrict__ ob,
    const float* __restrict__ fw, const float* __restrict__ fb,
    const float* __restrict__ gw, const float* __restrict__ gb,
    const float* __restrict__ sw, const float* __restrict__ sb,
    float* __restrict__ out)
{
    __shared__ __align__(16) float sf[DM*BB];
    int tid = threadIdx.x;
    for (int i = tid; i < DM*BB; i += blockDim.x) sf[i] = g_featT[i];
    __syncthreads();

    int j = blockIdx.x * blockDim.x + tid;
    if (j >= NOUT) return;

    const float* W; const float* Bv; int jj, Nseg;
    if (j < N_ORDER)                      { W=ow; Bv=ob; jj=j;                     Nseg=N_ORDER; }
    else if (j < N_ORDER+N_FAMILY)        { W=fw; Bv=fb; jj=j-N_ORDER;             Nseg=N_FAMILY; }
    else if (j < N_ORDER+N_FAMILY+N_GENUS){ W=gw; Bv=gb; jj=j-N_ORDER-N_FAMILY;    Nseg=N_GENUS; }
    else                                  { W=sw; Bv=sb; jj=j-N_ORDER-N_FAMILY-N_GENUS; Nseg=N_SPECIES; }

    float acc[BB];
    #pragma unroll
    for (int b=0;b<BB;b++) acc[b]=0.f;
    for (int k=0;k<DM;k++){
        float wv = W[(size_t)k*Nseg + jj];
        const float4* row = (const float4*)&sf[k*BB];
        #pragma unroll
        for (int bq=0;bq<8;bq++){
            float4 f = row[bq];
            acc[4*bq+0] = fmaf(f.x, wv, acc[4*bq+0]);
            acc[4*bq+1] = fmaf(f.y, wv, acc[4*bq+1]);
            acc[4*bq+2] = fmaf(f.z, wv, acc[4*bq+2]);
            acc[4*bq+3] = fmaf(f.w, wv, acc[4*bq+3]);
        }
    }
    float bias = Bv[jj];
    #pragma unroll
    for (int b=0;b<BB;b++) out[(size_t)b*NOUT + j] = acc[b] + bias;
}

// ---------------- orchestration ----------------
extern "C" void kernel_launch(void* const* d_in, const int* in_sizes, int n_in,
                              void* d_out, int out_size)
{
    const int*   tokens = (const int*)  d_in[0];
    const float* emb    = (const float*)d_in[1];
    const float* ln_w   = (const float*)d_in[2];
    const float* ln_b   = (const float*)d_in[3];
    const float* Win    = (const float*)d_in[4];
    const float* cw     = (const float*)d_in[5];
    const float* cb     = (const float*)d_in[6];
    const float* dtb    = (const float*)d_in[7];
    const float* alog   = (const float*)d_in[8];
    const float* Dd     = (const float*)d_in[9];
    const float* gnw    = (const float*)d_in[10];
    const float* Wout   = (const float*)d_in[11];
    const float* nfw    = (const float*)d_in[12];
    const float* nfb    = (const float*)d_in[13];
    const float* plw    = (const float*)d_in[14];
    const float* plb    = (const float*)d_in[15];
    const float* ow     = (const float*)d_in[16];
    const float* ob     = (const float*)d_in[17];
    const float* fw     = (const float*)d_in[18];
    const float* fb     = (const float*)d_in[19];
    const float* gw     = (const float*)d_in[20];
    const float* gb     = (const float*)d_in[21];
    const float* sw     = (const float*)d_in[22];
    const float* sb     = (const float*)d_in[23];
    float* out = (float*)d_out;

    const int smem_bytes = SMEM_FLOATS * 4;
    cudaFuncSetAttribute((const void*)gemm_tc<0,1>, cudaFuncAttributeMaxDynamicSharedMemorySize, smem_bytes);
    cudaFuncSetAttribute((const void*)gemm_tc<1,2>, cudaFuncAttributeMaxDynamicSharedMemorySize, smem_bytes);
    cudaFuncSetAttribute((const void*)ssd_local_kernel, cudaFuncAttributeMaxDynamicSharedMemorySize, SSD_A_SMEM);

    wcvt_t_kernel<<<dim3((DIP+31)/32, (DI+31)/32, 4), 256>>>(Win, Wout);
    embed_ln_kernel<<<NT, 128>>>(tokens, emb, ln_w, ln_b);

    for (int l = 0; l < 2; l++) {
        if (l > 0) ln_kernel<<<NT, 128>>>(ln_w + l*DM, ln_b + l*DM, 1);
        gemm_tc<0,1><<<dim3((DIP+GBN-1)/GBN, NT/GBM, 1), 256, smem_bytes>>>(l);
        conv_dtda_kernel<<<CONV_BLKS + DTDA_BLKS, 224>>>(cw + (size_t)l*CD*4, cb + l*CD,
                                                         dtb + l*NH, alog + l*NH);
        ssd_local_kernel  <<<BB*NH*NCHUNK, 128, SSD_A_SMEM>>>(Dd + l*NH);
        ssd_combine_kernel<<<BB*NH, 128>>>();
        ssd_fix_kernel    <<<BB*NH*(NCHUNK-1), 128>>>();
        gate_rms_kernel<<<NT, 256>>>(gnw + l*DI);
        gemm_tc<1,2><<<dim3((DM+GBN-1)/GBN, NT/GBM, 2), 256, smem_bytes>>>(l);
    }

    ln_kernel<<<NT, 128>>>(nfw, nfb, 0);
    pool1_kernel<<<BB*16, 128>>>();
    pool2_kernel<<<BB, 128>>>(plw, plb);
    heads_kernel<<<(NOUT + 255)/256, 256>>>(ow, ob, fw, fb, gw, gb, sw, sb, out);
}

// round 16
// speedup vs baseline: 1.2724x; 1.0065x over previous
#include <cuda_runtime.h>
#include <math.h>
#include <stddef.h>
#include <stdint.h>

typedef unsigned long long ull;

// ---------------- problem constants ----------------
#define BB   32
#define LL   512
#define DM   384
#define DI   768
#define DS   64
#define NH   16
#define HD   48
#define DIP  1680
#define CD   896
#define NT   (BB*LL)
#define NOUT 38667
#define N_ORDER 60
#define N_FAMILY 427
#define N_GENUS 14216
#define N_SPECIES 23964

#define WIN1  (DM*DIP)
#define WOUT1 (DI*DM)

#define NCHUNK 8
#define CLEN   64
#define SFL    3072          // DS*HD floats per (b,h,chunk) state

// k-permutation within each 8-group: pos = k<4 ? 2k : 2(k-4)+1
__device__ __forceinline__ int kperm(int k){
    int j = k & 7;
    return (k & ~7) | ((j<4) ? (j<<1) : (((j-4)<<1)|1));
}

// ---------------- scratch ----------------
__device__ float g_resid[(size_t)NT*DM];
__device__ float g_h    [(size_t)NT*DM];
__device__ float g_zx   [(size_t)NT*DIP];
__device__ float g_xBC  [(size_t)NT*CD];
__device__ float g_dt   [(size_t)NT*NH];
__device__ float g_dA   [(size_t)NT*NH];    // stores log(dA) = -exp(A_log)*dt
__device__ float g_lc   [(size_t)NT*NH];    // chunk-local cumsum of log dA
__device__ float g_ys   [(size_t)NT*DI];
__device__ float g_yn   [(size_t)NT*DI];
__device__ float g_wtB  [2*WIN1 + 2*WOUT1];
__device__ float g_state[(size_t)BB*NH*NCHUNK*SFL];
__device__ float g_sin  [(size_t)BB*NH*NCHUNK*SFL];
__device__ float g_poolf[BB*DM];
__device__ float g_featT[DM*BB];

__device__ __forceinline__ uint32_t f2tf(float x){
    uint32_t y;
    asm volatile("cvt.rna.tf32.f32 %0, %1;" : "=r"(y) : "f"(x));
    return y;
}
__device__ __forceinline__ void upk2u(uint32_t& lo, uint32_t& hi, ull v){
    asm("mov.b64 {%0, %1}, %2;" : "=r"(lo), "=r"(hi) : "l"(v));
}

// ---------------- weight transpose + permute + tf32 convert ----------------
__global__ __launch_bounds__(256) void wcvt_t_kernel(const float* __restrict__ Win,
                                                     const float* __restrict__ Wout)
{
    int r = blockIdx.z;
    const float* src; float* dst; int K_, N_;
    if (r < 2){ src = Win  + (size_t)r*WIN1;      dst = g_wtB + (size_t)r*WIN1;              K_ = DM; N_ = DIP; }
    else      { src = Wout + (size_t)(r-2)*WOUT1; dst = g_wtB + 2*WIN1 + (size_t)(r-2)*WOUT1; K_ = DI; N_ = DM; }
    int k0 = blockIdx.y*32, n0 = blockIdx.x*32;
    if (k0 >= K_ || n0 >= N_) return;
    __shared__ float sm[32][33];
    int tx = threadIdx.x & 31, ty = threadIdx.x >> 5;
    #pragma unroll
    for (int q=0;q<4;q++){
        int k = k0 + ty + q*8;
        if (k < K_ && n0+tx < N_) sm[ty+q*8][tx] = src[(size_t)k*N_ + n0+tx];
    }
    __syncthreads();
    #pragma unroll
    for (int q=0;q<4;q++){
        int n = n0 + ty + q*8;
        int k = k0 + tx;
        if (n < N_ && k < K_)
            dst[(size_t)n*K_ + kperm(k)] = __uint_as_float(f2tf(sm[tx][ty+q*8]));
    }
}

// ---------------- zero poolf ----------------
__global__ void zero_poolf_kernel(){
    int i = blockIdx.x*256 + threadIdx.x;
    if (i < BB*DM) g_poolf[i] = 0.f;
}

// ---------------- fused embedding + layer-0 layernorm (k-permuted) ----------------
__global__ __launch_bounds__(128) void embed_ln_kernel(const int* __restrict__ tokens,
                                                       const float* __restrict__ emb,
                                                       const float* __restrict__ w,
                                                       const float* __restrict__ b)
{
    __shared__ float red[128];
    int row = blockIdx.x, tid = threadIdx.x;
    const float* er = emb + (size_t)tokens[row]*DM;
    float v0 = er[tid], v1 = er[tid+128], v2 = er[tid+256];
    float* rr = g_resid + (size_t)row*DM;
    rr[tid] = v0; rr[tid+128] = v1; rr[tid+256] = v2;

    red[tid] = v0+v1+v2; __syncthreads();
    for (int s=64;s>0;s>>=1){ if(tid<s) red[tid]+=red[tid+s]; __syncthreads(); }
    float mu = red[0] * (1.0f/DM);
    __syncthreads();
    float d0=v0-mu, d1=v1-mu, d2=v2-mu;
    red[tid] = d0*d0+d1*d1+d2*d2; __syncthreads();
    for (int s=64;s>0;s>>=1){ if(tid<s) red[tid]+=red[tid+s]; __syncthreads(); }
    float inv = rsqrtf(red[0]*(1.0f/DM) + 1e-5f);
    float* o = g_h + (size_t)row*DM;
    o[kperm(tid)]     = __uint_as_float(f2tf(d0*inv*w[tid]     + b[tid]));
    o[kperm(tid+128)] = __uint_as_float(f2tf(d1*inv*w[tid+128] + b[tid+128]));
    o[kperm(tid+256)] = __uint_as_float(f2tf(d2*inv*w[tid+256] + b[tid+256]));
}

// ---------------- layernorm: g_resid -> g_h (tf32, k-permuted) ----------------
__global__ __launch_bounds__(128) void ln_kernel(const float* __restrict__ w, const float* __restrict__ b)
{
    __shared__ float red[128];
    int row = blockIdx.x, tid = threadIdx.x;
    const float* xr = g_resid + (size_t)row*DM;
    float v0 = xr[tid], v1 = xr[tid+128], v2 = xr[tid+256];
    red[tid] = v0+v1+v2; __syncthreads();
    for (int s=64;s>0;s>>=1){ if(tid<s) red[tid]+=red[tid+s]; __syncthreads(); }
    float mu = red[0] * (1.0f/DM);
    __syncthreads();
    float d0=v0-mu, d1=v1-mu, d2=v2-mu;
    red[tid] = d0*d0+d1*d1+d2*d2; __syncthreads();
    for (int s=64;s>0;s>>=1){ if(tid<s) red[tid]+=red[tid+s]; __syncthreads(); }
    float inv = rsqrtf(red[0]*(1.0f/DM) + 1e-5f);
    float* o = g_h + (size_t)row*DM;
    o[kperm(tid)]     = __uint_as_float(f2tf(d0*inv*w[tid]     + b[tid]));
    o[kperm(tid+128)] = __uint_as_float(f2tf(d1*inv*w[tid+128] + b[tid+128]));
    o[kperm(tid+256)] = __uint_as_float(f2tf(d2*inv*w[tid+256] + b[tid+256]));
}

// ---------------- final layernorm: LN then atomic-accumulate into poolf ----------------
__global__ __launch_bounds__(128) void ln_final_kernel(const float* __restrict__ w, const float* __restrict__ b)
{
    __shared__ float red[128];
    int row = blockIdx.x, tid = threadIdx.x;
    int bb = row / LL;
    const float* xr = g_resid + (size_t)row*DM;
    float v0 = xr[tid], v1 = xr[tid+128], v2 = xr[tid+256];
    red[tid] = v0+v1+v2; __syncthreads();
    for (int s=64;s>0;s>>=1){ if(tid<s) red[tid]+=red[tid+s]; __syncthreads(); }
    float mu = red[0] * (1.0f/DM);
    __syncthreads();
    float d0=v0-mu, d1=v1-mu, d2=v2-mu;
    red[tid] = d0*d0+d1*d1+d2*d2; __syncthreads();
    for (int s=64;s>0;s>>=1){ if(tid<s) red[tid]+=red[tid+s]; __syncthreads(); }
    float inv = rsqrtf(red[0]*(1.0f/DM) + 1e-5f);
    atomicAdd(&g_poolf[bb*DM + tid],     d0*inv*w[tid]     + b[tid]);
    atomicAdd(&g_poolf[bb*DM + tid+128], d1*inv*w[tid+128] + b[tid+128]);
    atomicAdd(&g_poolf[bb*DM + tid+256], d2*inv*w[tid+256] + b[tid+256]);
}

// ---------------- tf32 mma helper ----------------
__device__ __forceinline__ void mma_tf32(float* c, const uint32_t* a, const uint32_t* b){
    asm volatile(
      "mma.sync.aligned.m16n8k8.row.col.f32.tf32.tf32.f32 "
      "{%0,%1,%2,%3}, {%4,%5,%6,%7}, {%8,%9}, {%0,%1,%2,%3};\n"
      : "+f"(c[0]), "+f"(c[1]), "+f"(c[2]), "+f"(c[3])
      : "r"(a[0]), "r"(a[1]), "r"(a[2]), "r"(a[3]), "r"(b[0]), "r"(b[1]));
}

// ---------------- tf32 tensor-core GEMM ----------------
#define GBM 128
#define GBN 128
#define GBK 16
#define NSTAGE 4
#define TSTR 24
#define AS_FLOATS (GBM*TSTR)
#define BS_FLOATS (GBN*TSTR)
#define SMEM_FLOATS (NSTAGE*(AS_FLOATS+BS_FLOATS))

template<int MODE, int SPLITK>
__global__ __launch_bounds__(256,2) void gemm_tc(int layer)
{
    const float* __restrict__ A = (MODE==0) ? g_h : g_yn;
    const float* __restrict__ W = (MODE==0) ? (g_wtB + (size_t)layer*WIN1)
                                            : (g_wtB + 2*WIN1 + (size_t)layer*WOUT1);
    float* C = (MODE==0) ? g_zx : g_resid;
    const int N = (MODE==0) ? DIP : DM;
    const int K = (MODE==0) ? DM  : DI;
    const int Ks = K / SPLITK;
    const int k_origin = blockIdx.z * Ks;

    extern __shared__ float sh[];
    float* shB = sh + NSTAGE*AS_FLOATS;

    int tid  = threadIdx.x;
    int warp = tid >> 5;
    int lane = tid & 31;
    int gid  = lane >> 2;
    int tig  = lane & 3;

    int m0 = blockIdx.y * GBM;
    int n0 = blockIdx.x * GBN;
    int wm = (warp & 1) * 64;
    int wn = (warp >> 1) * 32;

    float acc[4][4][4];
    #pragma unroll
    for (int i=0;i<4;i++)
        #pragma unroll
        for (int j=0;j<4;j++)
            #pragma unroll
            for (int q=0;q<4;q++) acc[i][j][q]=0.f;

    const int niter = Ks / GBK;

    int row0 = tid >> 2,        kc0 = (tid & 3) << 2;
    int row1 = (tid+256) >> 2,  kc1 = (tid & 3) << 2;
    int b_ok0 = (n0 + row0 < N) ? 16 : 0;
    int b_ok1 = (n0 + row1 < N) ? 16 : 0;
    const float* asrc0 = A + (size_t)(m0 + row0)*K + k_origin + kc0;
    const float* asrc1 = A + (size_t)(m0 + row1)*K + k_origin + kc1;
    const float* bsrc0 = W + (size_t)((n0 + row0 < N) ? (n0 + row0) : 0)*K + k_origin + kc0;
    const float* bsrc1 = W + (size_t)((n0 + row1 < N) ? (n0 + row1) : 0)*K + k_origin + kc1;

    uint32_t adst0 = (uint32_t)__cvta_generic_to_shared(&sh [row0*TSTR + kc0]);
    uint32_t adst1 = (uint32_t)__cvta_generic_to_shared(&sh [row1*TSTR + kc1]);
    uint32_t bdst0 = (uint32_t)__cvta_generic_to_shared(&shB[row0*TSTR + kc0]);
    uint32_t bdst1 = (uint32_t)__cvta_generic_to_shared(&shB[row1*TSTR + kc1]);

    auto issue_copy = [&](int st, int it){
        int k0 = it * GBK;
        uint32_t ao = st*AS_FLOATS*4, bo = st*BS_FLOATS*4;
        asm volatile("cp.async.cg.shared.global [%0], [%1], 16;\n"
                     :: "r"(adst0 + ao), "l"(asrc0 + k0));
        asm volatile("cp.async.cg.shared.global [%0], [%1], 16;\n"
                     :: "r"(adst1 + ao), "l"(asrc1 + k0));
        asm volatile("cp.async.cg.shared.global [%0], [%1], 16, %2;\n"
                     :: "r"(bdst0 + bo), "l"(bsrc0 + k0), "r"(b_ok0));
        asm volatile("cp.async.cg.shared.global [%0], [%1], 16, %2;\n"
                     :: "r"(bdst1 + bo), "l"(bsrc1 + k0), "r"(b_ok1));
    };

    #pragma unroll
    for (int st=0; st<NSTAGE-1; st++){
        if (st < niter) issue_copy(st, st);
        asm volatile("cp.async.commit_group;\n");
    }

    for (int it=0; it<niter; ++it){
        asm volatile("cp.async.wait_group %0;\n" :: "n"(NSTAGE-2));
        __syncthreads();

        int cb = it & (NSTAGE-1);
        const float* Asb = &sh [cb*AS_FLOATS];
        const float* Bsb = &shB[cb*BS_FLOATS];

        #pragma unroll
        for (int ks=0; ks<GBK; ks+=8){
            uint32_t af[4][4], bf[4][2];
            #pragma unroll
            for (int mi=0; mi<4; mi++){
                int mr = wm + 16*mi;
                ull lo8 = *(const ull*)&Asb[(mr+gid  )*TSTR + ks + 2*tig];
                ull hi8 = *(const ull*)&Asb[(mr+gid+8)*TSTR + ks + 2*tig];
                upk2u(af[mi][0], af[mi][2], lo8);
                upk2u(af[mi][1], af[mi][3], hi8);
            }
            #pragma unroll
            for (int ni=0; ni<4; ni++){
                int nb = wn + 8*ni;
                ull bb = *(const ull*)&Bsb[(nb+gid)*TSTR + ks + 2*tig];
                upk2u(bf[ni][0], bf[ni][1], bb);
            }
            #pragma unroll
            for (int mi=0; mi<4; mi++)
                #pragma unroll
                for (int ni=0; ni<4; ni++)
                    mma_tf32(acc[mi][ni], af[mi], bf[ni]);
        }

        int nx = it + NSTAGE - 1;
        if (nx < niter) issue_copy(nx & (NSTAGE-1), nx);
        asm volatile("cp.async.commit_group;\n");
    }

    #pragma unroll
    for (int mi=0; mi<4; mi++){
        int r0 = m0 + wm + 16*mi + gid;
        #pragma unroll
        for (int ni=0; ni<4; ni++){
            int c0 = n0 + wn + 8*ni + 2*tig;
            float* a = acc[mi][ni];
            if (MODE){
                #pragma unroll
                for (int half=0; half<2; half++){
                    int cc = c0 + half;
                    if (cc < N){
                        atomicAdd(&C[(size_t)r0*N + cc],     a[half]);
                        atomicAdd(&C[(size_t)(r0+8)*N + cc], a[2+half]);
                    }
                }
            } else {
                if (c0 + 1 < N){
                    *(float2*)&C[(size_t)r0*N + c0]     = make_float2(a[0], a[1]);
                    *(float2*)&C[(size_t)(r0+8)*N + c0] = make_float2(a[2], a[3]);
                } else if (c0 < N){
                    C[(size_t)r0*N + c0]     = a[0];
                    C[(size_t)(r0+8)*N + c0] = a[2];
                }
            }
        }
    }
}

// ---------------- fused conv (8-step chunks) + dt/logdA ----------------
#define CONV_BLKS (BB*64)
#define DTDA_TOT  (NT*(NH/4))
#define DTDA_BLKS ((DTDA_TOT + 223)/224)
__global__ __launch_bounds__(224) void conv_dtda_kernel(const float* __restrict__ cw, const float* __restrict__ cb,
                                                        const float* __restrict__ dtb, const float* __restrict__ alog)
{
    int blk = blockIdx.x;
    int tid = threadIdx.x;
    if (blk < CONV_BLKS){
        int b  = blk >> 6;
        int tc = blk & 63;
        int t0 = tc * 8;
        int c  = tid << 2;

        float4 tw[4];
        #pragma unroll
        for (int k=0;k<4;k++){
            tw[k].x = cw[(c+0)*4+k];
            tw[k].y = cw[(c+1)*4+k];
            tw[k].z = cw[(c+2)*4+k];
            tw[k].w = cw[(c+3)*4+k];
        }
        float4 bias = *(const float4*)&cb[c];

        const float* base = g_zx + (size_t)(b*LL + t0)*DIP + DI + c;
        float* obase = g_xBC + (size_t)(b*LL + t0)*CD + c;

        float4 p1, p2, p3;
        if (t0 > 0){
            p1 = *(const float4*)(base - 3*DIP);
            p2 = *(const float4*)(base - 2*DIP);
            p3 = *(const float4*)(base - 1*DIP);
        } else {
            p1 = p2 = p3 = make_float4(0.f,0.f,0.f,0.f);
        }

        #pragma unroll
        for (int i=0;i<8;i++){
            float4 v = *(const float4*)(base + (size_t)i*DIP);
            float4 a;
            a.x = bias.x + p1.x*tw[0].x + p2.x*tw[1].x + p3.x*tw[2].x + v.x*tw[3].x;
            a.y = bias.y + p1.y*tw[0].y + p2.y*tw[1].y + p3.y*tw[2].y + v.y*tw[3].y;
            a.z = bias.z + p1.z*tw[0].z + p2.z*tw[1].z + p3.z*tw[2].z + v.z*tw[3].z;
            a.w = bias.w + p1.w*tw[0].w + p2.w*tw[1].w + p3.w*tw[2].w + v.w*tw[3].w;
            float4 r;
            r.x = a.x / (1.f + __expf(-a.x));
            r.y = a.y / (1.f + __expf(-a.y));
            r.z = a.z / (1.f + __expf(-a.z));
            r.w = a.w / (1.f + __expf(-a.w));
            *(float4*)(obase + (size_t)i*CD) = r;
            p1 = p2; p2 = p3; p3 = v;
        }
    } else {
        int j = (blk - CONV_BLKS)*224 + tid;
        if (j >= DTDA_TOT) return;
        int hq = (j & 3) << 2;
        int bt = j >> 2;
        #pragma unroll
        for (int q=0;q<4;q++){
            int hh = hq + q;
            float raw = g_zx[(size_t)bt*DIP + (DIP-NH) + hh] + dtb[hh];
            float sp = (raw > 20.f) ? raw : log1pf(expf(raw));
            g_dt[bt*NH + hh] = sp;
            g_dA[bt*NH + hh] = -expf(alog[hh]) * sp;    // log(dA)
        }
    }
}

// ---------------- SSD scan pass A: local scan + fused D*x ----------------
#define SA_STR 68
#define SSD_A_SMEM ((3*64*SA_STR + 2*48*SA_STR + 192)*4)

__global__ __launch_bounds__(128) void ssd_local_kernel(const float* __restrict__ Dp)
{
    int blk = blockIdx.x;           // BB*NH*NCHUNK
    int c  = blk & (NCHUNK-1);
    int bh = blk >> 3;
    int b  = bh >> 4;
    int h  = bh & 15;
    int tid = threadIdx.x;
    int warp = tid >> 5, lane = tid & 31, gid = lane >> 2, tig = lane & 3;
    int bt0 = b*LL + c*CLEN;

    extern __shared__ float sa[];
    float* sC   = sa;
    float* sBW  = sC  + 64*SA_STR;
    float* sBT  = sBW + 64*SA_STR;
    float* sXT  = sBT + 64*SA_STR;
    float* sXwT = sXT + 48*SA_STR;
    float* lc_sh = sXwT + 48*SA_STR;
    float* dt_sh = lc_sh + 64;
    float* w2_sh = dt_sh + 64;

    for (int i = tid; i < 64*16; i += 128){
        int t = i >> 4, q = (i & 15) << 2;
        const float* row = g_xBC + (size_t)(bt0+t)*CD + DI;
        float4 vb = *(const float4*)(row + q);
        float4 vc = *(const float4*)(row + DS + q);
        *(float4*)&sBW[t*SA_STR + q] = vb;
        *(float4*)&sC [t*SA_STR + q] = vc;
        sBT[(q+0)*SA_STR + t] = vb.x;
        sBT[(q+1)*SA_STR + t] = vb.y;
        sBT[(q+2)*SA_STR + t] = vb.z;
        sBT[(q+3)*SA_STR + t] = vb.w;
    }
    for (int i = tid; i < 64*12; i += 128){
        int t = i / 12, q = (i % 12) << 2;
        float4 vx = *(const float4*)(g_xBC + (size_t)(bt0+t)*CD + h*HD + q);
        sXT[(q+0)*SA_STR + t] = vx.x;
        sXT[(q+1)*SA_STR + t] = vx.y;
        sXT[(q+2)*SA_STR + t] = vx.z;
        sXT[(q+3)*SA_STR + t] = vx.w;
    }
    if (tid < 64) dt_sh[tid] = g_dt[(size_t)(bt0+tid)*NH + h];
    if (warp == 0){
        float v0 = g_dA[(size_t)(bt0+lane)*NH + h];
        float v1 = g_dA[(size_t)(bt0+32+lane)*NH + h];
        #pragma unroll
        for (int d=1; d<32; d<<=1){
            float u0 = __shfl_up_sync(0xffffffffu, v0, d);
            float u1 = __shfl_up_sync(0xffffffffu, v1, d);
            if (lane >= d){ v0 += u0; v1 += u1; }
        }
        float tot = __shfl_sync(0xffffffffu, v0, 31);
        v1 += tot;
        lc_sh[lane]    = v0;
        lc_sh[32+lane] = v1;
        g_lc[(size_t)(bt0+lane)*NH + h]    = v0;
        g_lc[(size_t)(bt0+32+lane)*NH + h] = v1;
    }
    __syncthreads();

    int wt0 = warp*16;
    float gacc[8][4];
    #pragma unroll
    for (int ni=0;ni<8;ni++){ gacc[ni][0]=0.f; gacc[ni][1]=0.f; gacc[ni][2]=0.f; gacc[ni][3]=0.f; }
    #pragma unroll
    for (int kk=0; kk<64; kk+=8){
        uint32_t af[4];
        af[0] = __float_as_uint(sC[(wt0+gid  )*SA_STR + kk+tig  ]);
        af[1] = __float_as_uint(sC[(wt0+gid+8)*SA_STR + kk+tig  ]);
        af[2] = __float_as_uint(sC[(wt0+gid  )*SA_STR + kk+tig+4]);
        af[3] = __float_as_uint(sC[(wt0+gid+8)*SA_STR + kk+tig+4]);
        #pragma unroll
        for (int ni=0; ni<8; ni++){
            uint32_t bf[2];
            bf[0] = __float_as_uint(sBW[(8*ni+gid)*SA_STR + kk+tig  ]);
            bf[1] = __float_as_uint(sBW[(8*ni+gid)*SA_STR + kk+tig+4]);
            mma_tf32(gacc[ni], af, bf);
        }
    }
    if (tid < 64) w2_sh[tid] = __expf(lc_sh[63] - lc_sh[tid]) * dt_sh[tid];
    __syncthreads();

    {
        int t0r = wt0 + gid, t1r = t0r + 8;
        float lct0 = lc_sh[t0r], lct1 = lc_sh[t1r];
        #pragma unroll
        for (int ni=0; ni<8; ni++){
            int s0 = 8*ni + 2*tig, s1 = s0 + 1;
            float lcs0 = lc_sh[s0], lcs1 = lc_sh[s1];
            float d0 = dt_sh[s0],   d1 = dt_sh[s1];
            sBW[t0r*SA_STR + s0] = (s0<=t0r) ? gacc[ni][0]*__expf(lct0-lcs0)*d0 : 0.f;
            sBW[t0r*SA_STR + s1] = (s1<=t0r) ? gacc[ni][1]*__expf(lct0-lcs1)*d1 : 0.f;
            sBW[t1r*SA_STR + s0] = (s0<=t1r) ? gacc[ni][2]*__expf(lct1-lcs0)*d0 : 0.f;
            sBW[t1r*SA_STR + s1] = (s1<=t1r) ? gacc[ni][3]*__expf(lct1-lcs1)*d1 : 0.f;
        }
    }
    for (int i = tid; i < 48*64; i += 128){
        int p = i >> 6, s = i & 63;
        sXwT[p*SA_STR + s] = sXT[p*SA_STR + s] * w2_sh[s];
    }
    __syncthreads();

    float yacc[6][4], sacc[6][4];
    #pragma unroll
    for (int ni=0;ni<6;ni++){
        yacc[ni][0]=yacc[ni][1]=yacc[ni][2]=yacc[ni][3]=0.f;
        sacc[ni][0]=sacc[ni][1]=sacc[ni][2]=sacc[ni][3]=0.f;
    }
    #pragma unroll
    for (int kk=0; kk<64; kk+=8){
        uint32_t afW[4], afB[4];
        afW[0] = __float_as_uint(sBW[(wt0+gid  )*SA_STR + kk+tig  ]);
        afW[1] = __float_as_uint(sBW[(wt0+gid+8)*SA_STR + kk+tig  ]);
        afW[2] = __float_as_uint(sBW[(wt0+gid  )*SA_STR + kk+tig+4]);
        afW[3] = __float_as_uint(sBW[(wt0+gid+8)*SA_STR + kk+tig+4]);
        afB[0] = __float_as_uint(sBT[(wt0+gid  )*SA_STR + kk+tig  ]);
        afB[1] = __float_as_uint(sBT[(wt0+gid+8)*SA_STR + kk+tig  ]);
        afB[2] = __float_as_uint(sBT[(wt0+gid  )*SA_STR + kk+tig+4]);
        afB[3] = __float_as_uint(sBT[(wt0+gid+8)*SA_STR + kk+tig+4]);
        #pragma unroll
        for (int ni=0; ni<6; ni++){
            uint32_t bfX[2], bfW2[2];
            bfX[0]  = __float_as_uint(sXT [(8*ni+gid)*SA_STR + kk+tig  ]);
            bfX[1]  = __float_as_uint(sXT [(8*ni+gid)*SA_STR + kk+tig+4]);
            mma_tf32(yacc[ni], afW, bfX);
            bfW2[0] = __float_as_uint(sXwT[(8*ni+gid)*SA_STR + kk+tig  ]);
            bfW2[1] = __float_as_uint(sXwT[(8*ni+gid)*SA_STR + kk+tig+4]);
            mma_tf32(sacc[ni], afB, bfW2);
        }
    }

    float Dh = Dp[h];
    size_t sbase = ((size_t)bh*NCHUNK + c)*SFL;
    #pragma unroll
    for (int ni=0; ni<6; ni++){
        int p = 8*ni + 2*tig;
        int tr = wt0 + gid;
        float y0a = yacc[ni][0] + Dh*sXT[(p  )*SA_STR + tr];
        float y0b = yacc[ni][1] + Dh*sXT[(p+1)*SA_STR + tr];
        float y1a = yacc[ni][2] + Dh*sXT[(p  )*SA_STR + tr+8];
        float y1b = yacc[ni][3] + Dh*sXT[(p+1)*SA_STR + tr+8];
        float* y0 = &g_ys[(size_t)(bt0+tr)*DI + h*HD + p];
        *(float2*)y0            = make_float2(y0a, y0b);
        *(float2*)(y0 + 8*DI)   = make_float2(y1a, y1b);
        float* s0 = &g_state[sbase + tr*HD + p];
        *(float2*)s0            = make_float2(sacc[ni][0], sacc[ni][1]);
        *(float2*)(s0 + 8*HD)   = make_float2(sacc[ni][2], sacc[ni][3]);
    }
}

// ---------------- SSD pass B: sequential chunk-state combine (float4) ----------------
__global__ __launch_bounds__(128) void ssd_combine_kernel()
{
    int bh = blockIdx.x;
    int b  = bh >> 4;
    int h  = bh & 15;
    int tid = threadIdx.x;
    size_t base = (size_t)bh*NCHUNK*SFL;

    float4 sin[SFL/512];
    #pragma unroll
    for (int j=0;j<SFL/512;j++) sin[j]=make_float4(0.f,0.f,0.f,0.f);

    for (int c=0;c<NCHUNK-1;c++){
        float ef = __expf(g_lc[(size_t)(b*LL + c*CLEN + CLEN-1)*NH + h]);
        #pragma unroll
        for (int j=0;j<SFL/512;j++){
            float4 S = *(const float4*)&g_state[base + (size_t)c*SFL + j*512 + tid*4];
            sin[j].x = sin[j].x*ef + S.x;
            sin[j].y = sin[j].y*ef + S.y;
            sin[j].z = sin[j].z*ef + S.z;
            sin[j].w = sin[j].w*ef + S.w;
        }
        #pragma unroll
        for (int j=0;j<SFL/512;j++)
            *(float4*)&g_sin[base + (size_t)(c+1)*SFL + j*512 + tid*4] = sin[j];
    }
}

// ---------------- SSD pass C: y += exp(lc_t) * (C @ S_in) ----------------
__global__ __launch_bounds__(128) void ssd_fix_kernel()
{
    int blk = blockIdx.x;
    int bh  = blk / (NCHUNK-1);
    int c   = blk - bh*(NCHUNK-1) + 1;
    int b   = bh >> 4;
    int h   = bh & 15;
    int tid = threadIdx.x;
    int warp = tid >> 5, lane = tid & 31, gid = lane >> 2, tig = lane & 3;
    int bt0 = b*LL + c*CLEN;

    __shared__ float sC2[64*SA_STR];
    __shared__ float sST[48*SA_STR];
    __shared__ float lc2[64];

    for (int i = tid; i < 64*16; i += 128){
        int t = i >> 4, q = (i & 15) << 2;
        float4 vc = *(const float4*)(g_xBC + (size_t)(bt0+t)*CD + DI + DS + q);
        *(float4*)&sC2[t*SA_STR + q] = vc;
    }
    size_t sbase = ((size_t)bh*NCHUNK + c)*SFL;
    for (int i = tid; i < SFL; i += 128){
        int n = i / HD, p = i - n*HD;
        sST[p*SA_STR + n] = g_sin[sbase + i];
    }
    if (tid < 64) lc2[tid] = g_lc[(size_t)(bt0+tid)*NH + h];
    __syncthreads();

    int wt0 = warp*16;
    float facc[6][4];
    #pragma unroll
    for (int ni=0;ni<6;ni++){ facc[ni][0]=facc[ni][1]=facc[ni][2]=facc[ni][3]=0.f; }
    #pragma unroll
    for (int kk=0; kk<64; kk+=8){
        uint32_t af[4];
        af[0] = __float_as_uint(sC2[(wt0+gid  )*SA_STR + kk+tig  ]);
        af[1] = __float_as_uint(sC2[(wt0+gid+8)*SA_STR + kk+tig  ]);
        af[2] = __float_as_uint(sC2[(wt0+gid  )*SA_STR + kk+tig+4]);
        af[3] = __float_as_uint(sC2[(wt0+gid+8)*SA_STR + kk+tig+4]);
        #pragma unroll
        for (int ni=0; ni<6; ni++){
            uint32_t bf[2];
            bf[0] = __float_as_uint(sST[(8*ni+gid)*SA_STR + kk+tig  ]);
            bf[1] = __float_as_uint(sST[(8*ni+gid)*SA_STR + kk+tig+4]);
            mma_tf32(facc[ni], af, bf);
        }
    }

    int tr = wt0 + gid;
    float e0 = __expf(lc2[tr]);
    float e1 = __expf(lc2[tr+8]);
    #pragma unroll
    for (int ni=0; ni<6; ni++){
        int p = 8*ni + 2*tig;
        float2* y0 = (float2*)&g_ys[(size_t)(bt0+tr)*DI + h*HD + p];
        float2 v0 = *y0; v0.x += e0*facc[ni][0]; v0.y += e0*facc[ni][1]; *y0 = v0;
        float2* y1 = (float2*)&g_ys[(size_t)(bt0+tr+8)*DI + h*HD + p];
        float2 v1 = *y1; v1.x += e1*facc[ni][2]; v1.y += e1*facc[ni][3]; *y1 = v1;
    }
}

// ---------------- y = ys * silu(z); RMS-norm -> g_yn (tf32, k-permuted); float4 loads ----------------
__global__ __launch_bounds__(256) void gate_rms_kernel(const float* __restrict__ gnorm)
{
    __shared__ float red[256];
    int row = blockIdx.x, tid = threadIdx.x;
    float4 v = make_float4(0.f,0.f,0.f,0.f);
    float ss = 0.f;
    if (tid < 192){
        int i = tid << 2;
        float4 ys = *(const float4*)&g_ys[(size_t)row*DI + i];
        float4 z  = *(const float4*)&g_zx[(size_t)row*DIP + i];
        v.x = ys.x * (z.x / (1.f + __expf(-z.x)));
        v.y = ys.y * (z.y / (1.f + __expf(-z.y)));
        v.z = ys.z * (z.z / (1.f + __expf(-z.z)));
        v.w = ys.w * (z.w / (1.f + __expf(-z.w)));
        ss = v.x*v.x + v.y*v.y + v.z*v.z + v.w*v.w;
    }
    red[tid] = ss; __syncthreads();
    for (int s=128;s>0;s>>=1){ if(tid<s) red[tid]+=red[tid+s]; __syncthreads(); }
    float scale = rsqrtf(red[0]*(1.0f/DI) + 1e-5f);
    if (tid < 192){
        int i = tid << 2;
        float* o = g_yn + (size_t)row*DI;
        o[kperm(i  )] = __uint_as_float(f2tf(v.x*scale*gnorm[i  ]));
        o[kperm(i+1)] = __uint_as_float(f2tf(v.y*scale*gnorm[i+1]));
        o[kperm(i+2)] = __uint_as_float(f2tf(v.z*scale*gnorm[i+2]));
        o[kperm(i+3)] = __uint_as_float(f2tf(v.w*scale*gnorm[i+3]));
    }
}

// ---------------- pool stage 2: mean + LN -> g_featT ----------------
__global__ __launch_bounds__(128) void pool2_kernel(const float* __restrict__ w,
                                                    const float* __restrict__ b2)
{
    __shared__ float red[128];
    int b = blockIdx.x, tid = threadIdx.x;
    float v[3];
    #pragma unroll
    for (int q=0;q<3;q++){
        int d = tid + q*128;
        v[q] = g_poolf[b*DM + d] * (1.0f/LL);
    }
    red[tid] = v[0]+v[1]+v[2]; __syncthreads();
    for (int s=64;s>0;s>>=1){ if(tid<s) red[tid]+=red[tid+s]; __syncthreads(); }
    float mu = red[0]*(1.0f/DM);
    __syncthreads();
    float d0=v[0]-mu, d1=v[1]-mu, d2=v[2]-mu;
    red[tid] = d0*d0+d1*d1+d2*d2; __syncthreads();
    for (int s=64;s>0;s>>=1){ if(tid<s) red[tid]+=red[tid+s]; __syncthreads(); }
    float inv = rsqrtf(red[0]*(1.0f/DM) + 1e-5f);
    g_featT[(tid    )*BB + b] = d0*inv*w[tid]     + b2[tid];
    g_featT[(tid+128)*BB + b] = d1*inv*w[tid+128] + b2[tid+128];
    g_featT[(tid+256)*BB + b] = d2*inv*w[tid+256] + b2[tid+256];
}

// ---------------- classification heads ----------------
__global__ __launch_bounds__(256) void heads_kernel(
    const float* __restrict__ ow, const float* __restrict__ ob,
    const float* __restrict__ fw, const float* __restrict__ fb,
    const float* __restrict__ gw, const float* __restrict__ gb,
    const float* __restrict__ sw, const float* __restrict__ sb,
    float* __restrict__ out)
{
    __shared__ __align__(16) float sf[DM*BB];
    int tid = threadIdx.x;
    for (int i = tid; i < DM*BB; i += blockDim.x) sf[i] = g_featT[i];
    __syncthreads();

    int j = blockIdx.x * blockDim.x + tid;
    if (j >= NOUT) return;

    const float* W; const float* Bv; int jj, Nseg;
    if (j < N_ORDER)                      { W=ow; Bv=ob; jj=j;                     Nseg=N_ORDER; }
    else if (j < N_ORDER+N_FAMILY)        { W=fw; Bv=fb; jj=j-N_ORDER;             Nseg=N_FAMILY; }
    else if (j < N_ORDER+N_FAMILY+N_GENUS){ W=gw; Bv=gb; jj=j-N_ORDER-N_FAMILY;    Nseg=N_GENUS; }
    else                                  { W=sw; Bv=sb; jj=j-N_ORDER-N_FAMILY-N_GENUS; Nseg=N_SPECIES; }

    float acc[BB];
    #pragma unroll
    for (int b=0;b<BB;b++) acc[b]=0.f;
    for (int k=0;k<DM;k++){
        float wv = W[(size_t)k*Nseg + jj];
        const float4* row = (const float4*)&sf[k*BB];
        #pragma unroll
        for (int bq=0;bq<8;bq++){
            float4 f = row[bq];
            acc[4*bq+0] = fmaf(f.x, wv, acc[4*bq+0]);
            acc[4*bq+1] = fmaf(f.y, wv, acc[4*bq+1]);
            acc[4*bq+2] = fmaf(f.z, wv, acc[4*bq+2]);
            acc[4*bq+3] = fmaf(f.w, wv, acc[4*bq+3]);
        }
    }
    float bias = Bv[jj];
    #pragma unroll
    for (int b=0;b<BB;b++) out[(size_t)b*NOUT + j] = acc[b] + bias;
}

// ---------------- orchestration ----------------
extern "C" void kernel_launch(void* const* d_in, const int* in_sizes, int n_in,
                              void* d_out, int out_size)
{
    const int*   tokens = (const int*)  d_in[0];
    const float* emb    = (const float*)d_in[1];
    const float* ln_w   = (const float*)d_in[2];
    const float* ln_b   = (const float*)d_in[3];
    const float* Win    = (const float*)d_in[4];
    const float* cw     = (const float*)d_in[5];
    const float* cb     = (const float*)d_in[6];
    const float* dtb    = (const float*)d_in[7];
    const float* alog   = (const float*)d_in[8];
    const float* Dd     = (const float*)d_in[9];
    const float* gnw    = (const float*)d_in[10];
    const float* Wout   = (const float*)d_in[11];
    const float* nfw    = (const float*)d_in[12];
    const float* nfb    = (const float*)d_in[13];
    const float* plw    = (const float*)d_in[14];
    const float* plb    = (const float*)d_in[15];
    const float* ow     = (const float*)d_in[16];
    const float* ob     = (const float*)d_in[17];
    const float* fw     = (const float*)d_in[18];
    const float* fb     = (const float*)d_in[19];
    const float* gw     = (const float*)d_in[20];
    const float* gb     = (const float*)d_in[21];
    const float* sw     = (const float*)d_in[22];
    const float* sb     = (const float*)d_in[23];
    float* out = (float*)d_out;

    const int smem_bytes = SMEM_FLOATS * 4;
    cudaFuncSetAttribute((const void*)gemm_tc<0,1>, cudaFuncAttributeMaxDynamicSharedMemorySize, smem_bytes);
    cudaFuncSetAttribute((const void*)gemm_tc<1,2>, cudaFuncAttributeMaxDynamicSharedMemorySize, smem_bytes);
    cudaFuncSetAttribute((const void*)ssd_local_kernel, cudaFuncAttributeMaxDynamicSharedMemorySize, SSD_A_SMEM);

    wcvt_t_kernel<<<dim3((DIP+31)/32, (DI+31)/32, 4), 256>>>(Win, Wout);
    zero_poolf_kernel<<<(BB*DM + 255)/256, 256>>>();
    embed_ln_kernel<<<NT, 128>>>(tokens, emb, ln_w, ln_b);

    for (int l = 0; l < 2; l++) {
        if (l > 0) ln_kernel<<<NT, 128>>>(ln_w + l*DM, ln_b + l*DM);
        gemm_tc<0,1><<<dim3((DIP+GBN-1)/GBN, NT/GBM, 1), 256, smem_bytes>>>(l);
        conv_dtda_kernel<<<CONV_BLKS + DTDA_BLKS, 224>>>(cw + (size_t)l*CD*4, cb + l*CD,
                                                         dtb + l*NH, alog + l*NH);
        ssd_local_kernel  <<<BB*NH*NCHUNK, 128, SSD_A_SMEM>>>(Dd + l*NH);
        ssd_combine_kernel<<<BB*NH, 128>>>();
        ssd_fix_kernel    <<<BB*NH*(NCHUNK-1), 128>>>();
        gate_rms_kernel<<<NT, 256>>>(gnw + l*DI);
        gemm_tc<1,2><<<dim3((DM+GBN-1)/GBN, NT/GBM, 2), 256, smem_bytes>>>(l);
    }

    ln_final_kernel<<<NT, 128>>>(nfw, nfb);
    pool2_kernel<<<BB, 128>>>(plw, plb);
    heads_kernel<<<(NOUT + 255)/256, 256>>>(ow, ob, fw, fb, gw, gb, sw, sb, out);
}

// round 17
// speedup vs baseline: 1.2835x; 1.0087x over previous
#include <cuda_runtime.h>
#include <math.h>
#include <stddef.h>
#include <stdint.h>

typedef unsigned long long ull;

// ---------------- problem constants ----------------
#define BB   32
#define LL   512
#define DM   384
#define DI   768
#define DS   64
#define NH   16
#define HD   48
#define DIP  1680
#define CD   896
#define NT   (BB*LL)
#define NOUT 38667
#define N_ORDER 60
#define N_FAMILY 427
#define N_GENUS 14216
#define N_SPECIES 23964

#define WIN1  (DM*DIP)
#define WOUT1 (DI*DM)

#define NCHUNK 8
#define CLEN   64
#define SFL    3072          // DS*HD floats per (b,h,chunk) state

// k-permutation within each 8-group: pos = k<4 ? 2k : 2(k-4)+1
__device__ __forceinline__ int kperm(int k){
    int j = k & 7;
    return (k & ~7) | ((j<4) ? (j<<1) : (((j-4)<<1)|1));
}

// ---------------- scratch ----------------
__device__ float g_resid[(size_t)NT*DM];
__device__ float g_h    [(size_t)NT*DM];
__device__ float g_zx   [(size_t)NT*DIP];
__device__ float g_xBC  [(size_t)NT*CD];
__device__ float g_dt   [(size_t)NT*NH];
__device__ float g_dA   [(size_t)NT*NH];    // stores log(dA) = -exp(A_log)*dt
__device__ float g_lc   [(size_t)NT*NH];    // chunk-local cumsum of log dA
__device__ float g_ys   [(size_t)NT*DI];
__device__ float g_yn   [(size_t)NT*DI];
__device__ float g_wtB  [2*WIN1 + 2*WOUT1];
__device__ float g_state[(size_t)BB*NH*NCHUNK*SFL];
__device__ float g_sin  [(size_t)BB*NH*NCHUNK*SFL];
__device__ float g_poolf[BB*DM];
__device__ float g_featT[DM*BB];

__device__ __forceinline__ uint32_t f2tf(float x){
    uint32_t y;
    asm volatile("cvt.rna.tf32.f32 %0, %1;" : "=r"(y) : "f"(x));
    return y;
}
__device__ __forceinline__ void upk2u(uint32_t& lo, uint32_t& hi, ull v){
    asm("mov.b64 {%0, %1}, %2;" : "=r"(lo), "=r"(hi) : "l"(v));
}
__device__ __forceinline__ void red_add_v2(float* p, float a, float b){
    asm volatile("red.global.add.v2.f32 [%0], {%1, %2};" :: "l"(p), "f"(a), "f"(b) : "memory");
}

// ---------------- weight transpose + permute + tf32 convert ----------------
__global__ __launch_bounds__(256) void wcvt_t_kernel(const float* __restrict__ Win,
                                                     const float* __restrict__ Wout)
{
    int r = blockIdx.z;
    const float* src; float* dst; int K_, N_;
    if (r < 2){ src = Win  + (size_t)r*WIN1;      dst = g_wtB + (size_t)r*WIN1;              K_ = DM; N_ = DIP; }
    else      { src = Wout + (size_t)(r-2)*WOUT1; dst = g_wtB + 2*WIN1 + (size_t)(r-2)*WOUT1; K_ = DI; N_ = DM; }
    int k0 = blockIdx.y*32, n0 = blockIdx.x*32;
    if (k0 >= K_ || n0 >= N_) return;
    __shared__ float sm[32][33];
    int tx = threadIdx.x & 31, ty = threadIdx.x >> 5;
    #pragma unroll
    for (int q=0;q<4;q++){
        int k = k0 + ty + q*8;
        if (k < K_ && n0+tx < N_) sm[ty+q*8][tx] = src[(size_t)k*N_ + n0+tx];
    }
    __syncthreads();
    #pragma unroll
    for (int q=0;q<4;q++){
        int n = n0 + ty + q*8;
        int k = k0 + tx;
        if (n < N_ && k < K_)
            dst[(size_t)n*K_ + kperm(k)] = __uint_as_float(f2tf(sm[tx][ty+q*8]));
    }
}

// ---------------- fused embedding + layer-0 layernorm (k-permuted) + poolf zero ----------------
__global__ __launch_bounds__(128) void embed_ln_kernel(const int* __restrict__ tokens,
                                                       const float* __restrict__ emb,
                                                       const float* __restrict__ w,
                                                       const float* __restrict__ b)
{
    __shared__ float red[128];
    int row = blockIdx.x, tid = threadIdx.x;
    if (row < BB){
        float* pf = g_poolf + row*DM;
        pf[tid] = 0.f; pf[tid+128] = 0.f; pf[tid+256] = 0.f;
    }
    const float* er = emb + (size_t)tokens[row]*DM;
    float v0 = er[tid], v1 = er[tid+128], v2 = er[tid+256];
    float* rr = g_resid + (size_t)row*DM;
    rr[tid] = v0; rr[tid+128] = v1; rr[tid+256] = v2;

    red[tid] = v0+v1+v2; __syncthreads();
    for (int s=64;s>0;s>>=1){ if(tid<s) red[tid]+=red[tid+s]; __syncthreads(); }
    float mu = red[0] * (1.0f/DM);
    __syncthreads();
    float d0=v0-mu, d1=v1-mu, d2=v2-mu;
    red[tid] = d0*d0+d1*d1+d2*d2; __syncthreads();
    for (int s=64;s>0;s>>=1){ if(tid<s) red[tid]+=red[tid+s]; __syncthreads(); }
    float inv = rsqrtf(red[0]*(1.0f/DM) + 1e-5f);
    float* o = g_h + (size_t)row*DM;
    o[kperm(tid)]     = __uint_as_float(f2tf(d0*inv*w[tid]     + b[tid]));
    o[kperm(tid+128)] = __uint_as_float(f2tf(d1*inv*w[tid+128] + b[tid+128]));
    o[kperm(tid+256)] = __uint_as_float(f2tf(d2*inv*w[tid+256] + b[tid+256]));
}

// ---------------- layernorm: g_resid -> g_h (tf32, k-permuted) ----------------
__global__ __launch_bounds__(128) void ln_kernel(const float* __restrict__ w, const float* __restrict__ b)
{
    __shared__ float red[128];
    int row = blockIdx.x, tid = threadIdx.x;
    const float* xr = g_resid + (size_t)row*DM;
    float v0 = xr[tid], v1 = xr[tid+128], v2 = xr[tid+256];
    red[tid] = v0+v1+v2; __syncthreads();
    for (int s=64;s>0;s>>=1){ if(tid<s) red[tid]+=red[tid+s]; __syncthreads(); }
    float mu = red[0] * (1.0f/DM);
    __syncthreads();
    float d0=v0-mu, d1=v1-mu, d2=v2-mu;
    red[tid] = d0*d0+d1*d1+d2*d2; __syncthreads();
    for (int s=64;s>0;s>>=1){ if(tid<s) red[tid]+=red[tid+s]; __syncthreads(); }
    float inv = rsqrtf(red[0]*(1.0f/DM) + 1e-5f);
    float* o = g_h + (size_t)row*DM;
    o[kperm(tid)]     = __uint_as_float(f2tf(d0*inv*w[tid]     + b[tid]));
    o[kperm(tid+128)] = __uint_as_float(f2tf(d1*inv*w[tid+128] + b[tid+128]));
    o[kperm(tid+256)] = __uint_as_float(f2tf(d2*inv*w[tid+256] + b[tid+256]));
}

// ---------------- final layernorm: LN then atomic-accumulate into poolf ----------------
__global__ __launch_bounds__(128) void ln_final_kernel(const float* __restrict__ w, const float* __restrict__ b)
{
    __shared__ float red[128];
    int row = blockIdx.x, tid = threadIdx.x;
    int bb = row / LL;
    const float* xr = g_resid + (size_t)row*DM;
    float v0 = xr[tid], v1 = xr[tid+128], v2 = xr[tid+256];
    red[tid] = v0+v1+v2; __syncthreads();
    for (int s=64;s>0;s>>=1){ if(tid<s) red[tid]+=red[tid+s]; __syncthreads(); }
    float mu = red[0] * (1.0f/DM);
    __syncthreads();
    float d0=v0-mu, d1=v1-mu, d2=v2-mu;
    red[tid] = d0*d0+d1*d1+d2*d2; __syncthreads();
    for (int s=64;s>0;s>>=1){ if(tid<s) red[tid]+=red[tid+s]; __syncthreads(); }
    float inv = rsqrtf(red[0]*(1.0f/DM) + 1e-5f);
    atomicAdd(&g_poolf[bb*DM + tid],     d0*inv*w[tid]     + b[tid]);
    atomicAdd(&g_poolf[bb*DM + tid+128], d1*inv*w[tid+128] + b[tid+128]);
    atomicAdd(&g_poolf[bb*DM + tid+256], d2*inv*w[tid+256] + b[tid+256]);
}

// ---------------- tf32 mma helper ----------------
__device__ __forceinline__ void mma_tf32(float* c, const uint32_t* a, const uint32_t* b){
    asm volatile(
      "mma.sync.aligned.m16n8k8.row.col.f32.tf32.tf32.f32 "
      "{%0,%1,%2,%3}, {%4,%5,%6,%7}, {%8,%9}, {%0,%1,%2,%3};\n"
      : "+f"(c[0]), "+f"(c[1]), "+f"(c[2]), "+f"(c[3])
      : "r"(a[0]), "r"(a[1]), "r"(a[2]), "r"(a[3]), "r"(b[0]), "r"(b[1]));
}

// ---------------- tf32 tensor-core GEMM ----------------
#define GBM 128
#define GBN 128
#define GBK 16
#define NSTAGE 4
#define TSTR 24
#define AS_FLOATS (GBM*TSTR)
#define BS_FLOATS (GBN*TSTR)
#define SMEM_FLOATS (NSTAGE*(AS_FLOATS+BS_FLOATS))

template<int MODE, int SPLITK>
__global__ __launch_bounds__(256,2) void gemm_tc(int layer)
{
    const float* __restrict__ A = (MODE==0) ? g_h : g_yn;
    const float* __restrict__ W = (MODE==0) ? (g_wtB + (size_t)layer*WIN1)
                                            : (g_wtB + 2*WIN1 + (size_t)layer*WOUT1);
    float* C = (MODE==0) ? g_zx : g_resid;
    const int N = (MODE==0) ? DIP : DM;
    const int K = (MODE==0) ? DM  : DI;
    const int Ks = K / SPLITK;
    const int k_origin = blockIdx.z * Ks;

    extern __shared__ float sh[];
    float* shB = sh + NSTAGE*AS_FLOATS;

    int tid  = threadIdx.x;
    int warp = tid >> 5;
    int lane = tid & 31;
    int gid  = lane >> 2;
    int tig  = lane & 3;

    int m0 = blockIdx.y * GBM;
    int n0 = blockIdx.x * GBN;
    int wm = (warp & 1) * 64;
    int wn = (warp >> 1) * 32;

    float acc[4][4][4];
    #pragma unroll
    for (int i=0;i<4;i++)
        #pragma unroll
        for (int j=0;j<4;j++)
            #pragma unroll
            for (int q=0;q<4;q++) acc[i][j][q]=0.f;

    const int niter = Ks / GBK;

    int row0 = tid >> 2,        kc0 = (tid & 3) << 2;
    int row1 = (tid+256) >> 2,  kc1 = (tid & 3) << 2;
    int b_ok0 = (n0 + row0 < N) ? 16 : 0;
    int b_ok1 = (n0 + row1 < N) ? 16 : 0;
    const float* asrc0 = A + (size_t)(m0 + row0)*K + k_origin + kc0;
    const float* asrc1 = A + (size_t)(m0 + row1)*K + k_origin + kc1;
    const float* bsrc0 = W + (size_t)((n0 + row0 < N) ? (n0 + row0) : 0)*K + k_origin + kc0;
    const float* bsrc1 = W + (size_t)((n0 + row1 < N) ? (n0 + row1) : 0)*K + k_origin + kc1;

    uint32_t adst0 = (uint32_t)__cvta_generic_to_shared(&sh [row0*TSTR + kc0]);
    uint32_t adst1 = (uint32_t)__cvta_generic_to_shared(&sh [row1*TSTR + kc1]);
    uint32_t bdst0 = (uint32_t)__cvta_generic_to_shared(&shB[row0*TSTR + kc0]);
    uint32_t bdst1 = (uint32_t)__cvta_generic_to_shared(&shB[row1*TSTR + kc1]);

    auto issue_copy = [&](int st, int it){
        int k0 = it * GBK;
        uint32_t ao = st*AS_FLOATS*4, bo = st*BS_FLOATS*4;
        asm volatile("cp.async.cg.shared.global [%0], [%1], 16;\n"
                     :: "r"(adst0 + ao), "l"(asrc0 + k0));
        asm volatile("cp.async.cg.shared.global [%0], [%1], 16;\n"
                     :: "r"(adst1 + ao), "l"(asrc1 + k0));
        asm volatile("cp.async.cg.shared.global [%0], [%1], 16, %2;\n"
                     :: "r"(bdst0 + bo), "l"(bsrc0 + k0), "r"(b_ok0));
        asm volatile("cp.async.cg.shared.global [%0], [%1], 16, %2;\n"
                     :: "r"(bdst1 + bo), "l"(bsrc1 + k0), "r"(b_ok1));
    };

    #pragma unroll
    for (int st=0; st<NSTAGE-1; st++){
        if (st < niter) issue_copy(st, st);
        asm volatile("cp.async.commit_group;\n");
    }

    for (int it=0; it<niter; ++it){
        asm volatile("cp.async.wait_group %0;\n" :: "n"(NSTAGE-2));
        __syncthreads();

        int cb = it & (NSTAGE-1);
        const float* Asb = &sh [cb*AS_FLOATS];
        const float* Bsb = &shB[cb*BS_FLOATS];

        #pragma unroll
        for (int ks=0; ks<GBK; ks+=8){
            uint32_t af[4][4], bf[4][2];
            #pragma unroll
            for (int mi=0; mi<4; mi++){
                int mr = wm + 16*mi;
                ull lo8 = *(const ull*)&Asb[(mr+gid  )*TSTR + ks + 2*tig];
                ull hi8 = *(const ull*)&Asb[(mr+gid+8)*TSTR + ks + 2*tig];
                upk2u(af[mi][0], af[mi][2], lo8);
                upk2u(af[mi][1], af[mi][3], hi8);
            }
            #pragma unroll
            for (int ni=0; ni<4; ni++){
                int nb = wn + 8*ni;
                ull bb = *(const ull*)&Bsb[(nb+gid)*TSTR + ks + 2*tig];
                upk2u(bf[ni][0], bf[ni][1], bb);
            }
            #pragma unroll
            for (int mi=0; mi<4; mi++)
                #pragma unroll
                for (int ni=0; ni<4; ni++)
                    mma_tf32(acc[mi][ni], af[mi], bf[ni]);
        }

        int nx = it + NSTAGE - 1;
        if (nx < niter) issue_copy(nx & (NSTAGE-1), nx);
        asm volatile("cp.async.commit_group;\n");
    }

    #pragma unroll
    for (int mi=0; mi<4; mi++){
        int r0 = m0 + wm + 16*mi + gid;
        #pragma unroll
        for (int ni=0; ni<4; ni++){
            int c0 = n0 + wn + 8*ni + 2*tig;
            float* a = acc[mi][ni];
            if (MODE){
                // N=384: tiles exact, c0+1 always < N; 8B-aligned pairs
                red_add_v2(&C[(size_t)r0*N + c0],     a[0], a[1]);
                red_add_v2(&C[(size_t)(r0+8)*N + c0], a[2], a[3]);
            } else {
                if (c0 + 1 < N){
                    *(float2*)&C[(size_t)r0*N + c0]     = make_float2(a[0], a[1]);
                    *(float2*)&C[(size_t)(r0+8)*N + c0] = make_float2(a[2], a[3]);
                } else if (c0 < N){
                    C[(size_t)r0*N + c0]     = a[0];
                    C[(size_t)(r0+8)*N + c0] = a[2];
                }
            }
        }
    }
}

// ---------------- fused conv (8-step chunks) + dt/logdA ----------------
#define CONV_BLKS (BB*64)
#define DTDA_TOT  (NT*(NH/4))
#define DTDA_BLKS ((DTDA_TOT + 223)/224)
__global__ __launch_bounds__(224) void conv_dtda_kernel(const float* __restrict__ cw, const float* __restrict__ cb,
                                                        const float* __restrict__ dtb, const float* __restrict__ alog)
{
    int blk = blockIdx.x;
    int tid = threadIdx.x;
    if (blk < CONV_BLKS){
        int b  = blk >> 6;
        int tc = blk & 63;
        int t0 = tc * 8;
        int c  = tid << 2;

        float4 tw[4];
        #pragma unroll
        for (int k=0;k<4;k++){
            tw[k].x = cw[(c+0)*4+k];
            tw[k].y = cw[(c+1)*4+k];
            tw[k].z = cw[(c+2)*4+k];
            tw[k].w = cw[(c+3)*4+k];
        }
        float4 bias = *(const float4*)&cb[c];

        const float* base = g_zx + (size_t)(b*LL + t0)*DIP + DI + c;
        float* obase = g_xBC + (size_t)(b*LL + t0)*CD + c;

        float4 p1, p2, p3;
        if (t0 > 0){
            p1 = *(const float4*)(base - 3*DIP);
            p2 = *(const float4*)(base - 2*DIP);
            p3 = *(const float4*)(base - 1*DIP);
        } else {
            p1 = p2 = p3 = make_float4(0.f,0.f,0.f,0.f);
        }

        #pragma unroll
        for (int i=0;i<8;i++){
            float4 v = *(const float4*)(base + (size_t)i*DIP);
            float4 a;
            a.x = bias.x + p1.x*tw[0].x + p2.x*tw[1].x + p3.x*tw[2].x + v.x*tw[3].x;
            a.y = bias.y + p1.y*tw[0].y + p2.y*tw[1].y + p3.y*tw[2].y + v.y*tw[3].y;
            a.z = bias.z + p1.z*tw[0].z + p2.z*tw[1].z + p3.z*tw[2].z + v.z*tw[3].z;
            a.w = bias.w + p1.w*tw[0].w + p2.w*tw[1].w + p3.w*tw[2].w + v.w*tw[3].w;
            float4 r;
            r.x = a.x / (1.f + __expf(-a.x));
            r.y = a.y / (1.f + __expf(-a.y));
            r.z = a.z / (1.f + __expf(-a.z));
            r.w = a.w / (1.f + __expf(-a.w));
            *(float4*)(obase + (size_t)i*CD) = r;
            p1 = p2; p2 = p3; p3 = v;
        }
    } else {
        int j = (blk - CONV_BLKS)*224 + tid;
        if (j >= DTDA_TOT) return;
        int hq = (j & 3) << 2;
        int bt = j >> 2;
        #pragma unroll
        for (int q=0;q<4;q++){
            int hh = hq + q;
            float raw = g_zx[(size_t)bt*DIP + (DIP-NH) + hh] + dtb[hh];
            float sp = (raw > 20.f) ? raw : log1pf(expf(raw));
            g_dt[bt*NH + hh] = sp;
            g_dA[bt*NH + hh] = -expf(alog[hh]) * sp;    // log(dA)
        }
    }
}

// ---------------- SSD scan pass A: local scan + fused D*x ----------------
#define SA_STR 68
#define SSD_A_SMEM ((3*64*SA_STR + 2*48*SA_STR + 192)*4)

__global__ __launch_bounds__(128) void ssd_local_kernel(const float* __restrict__ Dp)
{
    int blk = blockIdx.x;           // BB*NH*NCHUNK
    int c  = blk & (NCHUNK-1);
    int bh = blk >> 3;
    int b  = bh >> 4;
    int h  = bh & 15;
    int tid = threadIdx.x;
    int warp = tid >> 5, lane = tid & 31, gid = lane >> 2, tig = lane & 3;
    int bt0 = b*LL + c*CLEN;

    extern __shared__ float sa[];
    float* sC   = sa;
    float* sBW  = sC  + 64*SA_STR;
    float* sBT  = sBW + 64*SA_STR;
    float* sXT  = sBT + 64*SA_STR;
    float* sXwT = sXT + 48*SA_STR;
    float* lc_sh = sXwT + 48*SA_STR;
    float* dt_sh = lc_sh + 64;
    float* w2_sh = dt_sh + 64;

    for (int i = tid; i < 64*16; i += 128){
        int t = i >> 4, q = (i & 15) << 2;
        const float* row = g_xBC + (size_t)(bt0+t)*CD + DI;
        float4 vb = *(const float4*)(row + q);
        float4 vc = *(const float4*)(row + DS + q);
        *(float4*)&sBW[t*SA_STR + q] = vb;
        *(float4*)&sC [t*SA_STR + q] = vc;
        sBT[(q+0)*SA_STR + t] = vb.x;
        sBT[(q+1)*SA_STR + t] = vb.y;
        sBT[(q+2)*SA_STR + t] = vb.z;
        sBT[(q+3)*SA_STR + t] = vb.w;
    }
    for (int i = tid; i < 64*12; i += 128){
        int t = i / 12, q = (i % 12) << 2;
        float4 vx = *(const float4*)(g_xBC + (size_t)(bt0+t)*CD + h*HD + q);
        sXT[(q+0)*SA_STR + t] = vx.x;
        sXT[(q+1)*SA_STR + t] = vx.y;
        sXT[(q+2)*SA_STR + t] = vx.z;
        sXT[(q+3)*SA_STR + t] = vx.w;
    }
    if (tid < 64) dt_sh[tid] = g_dt[(size_t)(bt0+tid)*NH + h];
    if (warp == 0){
        float v0 = g_dA[(size_t)(bt0+lane)*NH + h];
        float v1 = g_dA[(size_t)(bt0+32+lane)*NH + h];
        #pragma unroll
        for (int d=1; d<32; d<<=1){
            float u0 = __shfl_up_sync(0xffffffffu, v0, d);
            float u1 = __shfl_up_sync(0xffffffffu, v1, d);
            if (lane >= d){ v0 += u0; v1 += u1; }
        }
        float tot = __shfl_sync(0xffffffffu, v0, 31);
        v1 += tot;
        lc_sh[lane]    = v0;
        lc_sh[32+lane] = v1;
        g_lc[(size_t)(bt0+lane)*NH + h]    = v0;
        g_lc[(size_t)(bt0+32+lane)*NH + h] = v1;
    }
    __syncthreads();

    int wt0 = warp*16;
    float gacc[8][4];
    #pragma unroll
    for (int ni=0;ni<8;ni++){ gacc[ni][0]=0.f; gacc[ni][1]=0.f; gacc[ni][2]=0.f; gacc[ni][3]=0.f; }
    #pragma unroll
    for (int kk=0; kk<64; kk+=8){
        uint32_t af[4];
        af[0] = __float_as_uint(sC[(wt0+gid  )*SA_STR + kk+tig  ]);
        af[1] = __float_as_uint(sC[(wt0+gid+8)*SA_STR + kk+tig  ]);
        af[2] = __float_as_uint(sC[(wt0+gid  )*SA_STR + kk+tig+4]);
        af[3] = __float_as_uint(sC[(wt0+gid+8)*SA_STR + kk+tig+4]);
        #pragma unroll
        for (int ni=0; ni<8; ni++){
            uint32_t bf[2];
            bf[0] = __float_as_uint(sBW[(8*ni+gid)*SA_STR + kk+tig  ]);
            bf[1] = __float_as_uint(sBW[(8*ni+gid)*SA_STR + kk+tig+4]);
            mma_tf32(gacc[ni], af, bf);
        }
    }
    if (tid < 64) w2_sh[tid] = __expf(lc_sh[63] - lc_sh[tid]) * dt_sh[tid];
    __syncthreads();

    {
        int t0r = wt0 + gid, t1r = t0r + 8;
        float lct0 = lc_sh[t0r], lct1 = lc_sh[t1r];
        #pragma unroll
        for (int ni=0; ni<8; ni++){
            int s0 = 8*ni + 2*tig, s1 = s0 + 1;
            float lcs0 = lc_sh[s0], lcs1 = lc_sh[s1];
            float d0 = dt_sh[s0],   d1 = dt_sh[s1];
            sBW[t0r*SA_STR + s0] = (s0<=t0r) ? gacc[ni][0]*__expf(lct0-lcs0)*d0 : 0.f;
            sBW[t0r*SA_STR + s1] = (s1<=t0r) ? gacc[ni][1]*__expf(lct0-lcs1)*d1 : 0.f;
            sBW[t1r*SA_STR + s0] = (s0<=t1r) ? gacc[ni][2]*__expf(lct1-lcs0)*d0 : 0.f;
            sBW[t1r*SA_STR + s1] = (s1<=t1r) ? gacc[ni][3]*__expf(lct1-lcs1)*d1 : 0.f;
        }
    }
    for (int i = tid; i < 48*64; i += 128){
        int p = i >> 6, s = i & 63;
        sXwT[p*SA_STR + s] = sXT[p*SA_STR + s] * w2_sh[s];
    }
    __syncthreads();

    float yacc[6][4], sacc[6][4];
    #pragma unroll
    for (int ni=0;ni<6;ni++){
        yacc[ni][0]=yacc[ni][1]=yacc[ni][2]=yacc[ni][3]=0.f;
        sacc[ni][0]=sacc[ni][1]=sacc[ni][2]=sacc[ni][3]=0.f;
    }
    #pragma unroll
    for (int kk=0; kk<64; kk+=8){
        uint32_t afW[4], afB[4];
        afW[0] = __float_as_uint(sBW[(wt0+gid  )*SA_STR + kk+tig  ]);
        afW[1] = __float_as_uint(sBW[(wt0+gid+8)*SA_STR + kk+tig  ]);
        afW[2] = __float_as_uint(sBW[(wt0+gid  )*SA_STR + kk+tig+4]);
        afW[3] = __float_as_uint(sBW[(wt0+gid+8)*SA_STR + kk+tig+4]);
        afB[0] = __float_as_uint(sBT[(wt0+gid  )*SA_STR + kk+tig  ]);
        afB[1] = __float_as_uint(sBT[(wt0+gid+8)*SA_STR + kk+tig  ]);
        afB[2] = __float_as_uint(sBT[(wt0+gid  )*SA_STR + kk+tig+4]);
        afB[3] = __float_as_uint(sBT[(wt0+gid+8)*SA_STR + kk+tig+4]);
        #pragma unroll
        for (int ni=0; ni<6; ni++){
            uint32_t bfX[2], bfW2[2];
            bfX[0]  = __float_as_uint(sXT [(8*ni+gid)*SA_STR + kk+tig  ]);
            bfX[1]  = __float_as_uint(sXT [(8*ni+gid)*SA_STR + kk+tig+4]);
            mma_tf32(yacc[ni], afW, bfX);
            bfW2[0] = __float_as_uint(sXwT[(8*ni+gid)*SA_STR + kk+tig  ]);
            bfW2[1] = __float_as_uint(sXwT[(8*ni+gid)*SA_STR + kk+tig+4]);
            mma_tf32(sacc[ni], afB, bfW2);
        }
    }

    float Dh = Dp[h];
    size_t sbase = ((size_t)bh*NCHUNK + c)*SFL;
    #pragma unroll
    for (int ni=0; ni<6; ni++){
        int p = 8*ni + 2*tig;
        int tr = wt0 + gid;
        float y0a = yacc[ni][0] + Dh*sXT[(p  )*SA_STR + tr];
        float y0b = yacc[ni][1] + Dh*sXT[(p+1)*SA_STR + tr];
        float y1a = yacc[ni][2] + Dh*sXT[(p  )*SA_STR + tr+8];
        float y1b = yacc[ni][3] + Dh*sXT[(p+1)*SA_STR + tr+8];
        float* y0 = &g_ys[(size_t)(bt0+tr)*DI + h*HD + p];
        *(float2*)y0            = make_float2(y0a, y0b);
        *(float2*)(y0 + 8*DI)   = make_float2(y1a, y1b);
        float* s0 = &g_state[sbase + tr*HD + p];
        *(float2*)s0            = make_float2(sacc[ni][0], sacc[ni][1]);
        *(float2*)(s0 + 8*HD)   = make_float2(sacc[ni][2], sacc[ni][3]);
    }
}

// ---------------- SSD pass B: sequential chunk-state combine (float4) ----------------
__global__ __launch_bounds__(128) void ssd_combine_kernel()
{
    int bh = blockIdx.x;
    int b  = bh >> 4;
    int h  = bh & 15;
    int tid = threadIdx.x;
    size_t base = (size_t)bh*NCHUNK*SFL;

    float4 sin[SFL/512];
    #pragma unroll
    for (int j=0;j<SFL/512;j++) sin[j]=make_float4(0.f,0.f,0.f,0.f);

    for (int c=0;c<NCHUNK-1;c++){
        float ef = __expf(g_lc[(size_t)(b*LL + c*CLEN + CLEN-1)*NH + h]);
        #pragma unroll
        for (int j=0;j<SFL/512;j++){
            float4 S = *(const float4*)&g_state[base + (size_t)c*SFL + j*512 + tid*4];
            sin[j].x = sin[j].x*ef + S.x;
            sin[j].y = sin[j].y*ef + S.y;
            sin[j].z = sin[j].z*ef + S.z;
            sin[j].w = sin[j].w*ef + S.w;
        }
        #pragma unroll
        for (int j=0;j<SFL/512;j++)
            *(float4*)&g_sin[base + (size_t)(c+1)*SFL + j*512 + tid*4] = sin[j];
    }
}

// ---------------- SSD pass C: y += exp(lc_t) * (C @ S_in) ----------------
__global__ __launch_bounds__(128) void ssd_fix_kernel()
{
    int blk = blockIdx.x;
    int bh  = blk / (NCHUNK-1);
    int c   = blk - bh*(NCHUNK-1) + 1;
    int b   = bh >> 4;
    int h   = bh & 15;
    int tid = threadIdx.x;
    int warp = tid >> 5, lane = tid & 31, gid = lane >> 2, tig = lane & 3;
    int bt0 = b*LL + c*CLEN;

    __shared__ float sC2[64*SA_STR];
    __shared__ float sST[48*SA_STR];
    __shared__ float lc2[64];

    for (int i = tid; i < 64*16; i += 128){
        int t = i >> 4, q = (i & 15) << 2;
        float4 vc = *(const float4*)(g_xBC + (size_t)(bt0+t)*CD + DI + DS + q);
        *(float4*)&sC2[t*SA_STR + q] = vc;
    }
    size_t sbase = ((size_t)bh*NCHUNK + c)*SFL;
    for (int i = tid*4; i < SFL; i += 512){
        float4 s4 = *(const float4*)&g_sin[sbase + i];
        int n = i / HD, p = i - n*HD;    // HD=48 divisible by 4: no row crossing
        sST[(p+0)*SA_STR + n] = s4.x;
        sST[(p+1)*SA_STR + n] = s4.y;
        sST[(p+2)*SA_STR + n] = s4.z;
        sST[(p+3)*SA_STR + n] = s4.w;
    }
    if (tid < 64) lc2[tid] = g_lc[(size_t)(bt0+tid)*NH + h];
    __syncthreads();

    int wt0 = warp*16;
    float facc[6][4];
    #pragma unroll
    for (int ni=0;ni<6;ni++){ facc[ni][0]=facc[ni][1]=facc[ni][2]=facc[ni][3]=0.f; }
    #pragma unroll
    for (int kk=0; kk<64; kk+=8){
        uint32_t af[4];
        af[0] = __float_as_uint(sC2[(wt0+gid  )*SA_STR + kk+tig  ]);
        af[1] = __float_as_uint(sC2[(wt0+gid+8)*SA_STR + kk+tig  ]);
        af[2] = __float_as_uint(sC2[(wt0+gid  )*SA_STR + kk+tig+4]);
        af[3] = __float_as_uint(sC2[(wt0+gid+8)*SA_STR + kk+tig+4]);
        #pragma unroll
        for (int ni=0; ni<6; ni++){
            uint32_t bf[2];
            bf[0] = __float_as_uint(sST[(8*ni+gid)*SA_STR + kk+tig  ]);
            bf[1] = __float_as_uint(sST[(8*ni+gid)*SA_STR + kk+tig+4]);
            mma_tf32(facc[ni], af, bf);
        }
    }

    int tr = wt0 + gid;
    float e0 = __expf(lc2[tr]);
    float e1 = __expf(lc2[tr+8]);
    #pragma unroll
    for (int ni=0; ni<6; ni++){
        int p = 8*ni + 2*tig;
        float2* y0 = (float2*)&g_ys[(size_t)(bt0+tr)*DI + h*HD + p];
        float2 v0 = *y0; v0.x += e0*facc[ni][0]; v0.y += e0*facc[ni][1]; *y0 = v0;
        float2* y1 = (float2*)&g_ys[(size_t)(bt0+tr+8)*DI + h*HD + p];
        float2 v1 = *y1; v1.x += e1*facc[ni][2]; v1.y += e1*facc[ni][3]; *y1 = v1;
    }
}

// ---------------- y = ys * silu(z); RMS-norm -> g_yn (tf32, k-permuted); float4 loads ----------------
__global__ __launch_bounds__(256) void gate_rms_kernel(const float* __restrict__ gnorm)
{
    __shared__ float red[256];
    int row = blockIdx.x, tid = threadIdx.x;
    float4 v = make_float4(0.f,0.f,0.f,0.f);
    float ss = 0.f;
    if (tid < 192){
        int i = tid << 2;
        float4 ys = *(const float4*)&g_ys[(size_t)row*DI + i];
        float4 z  = *(const float4*)&g_zx[(size_t)row*DIP + i];
        v.x = ys.x * (z.x / (1.f + __expf(-z.x)));
        v.y = ys.y * (z.y / (1.f + __expf(-z.y)));
        v.z = ys.z * (z.z / (1.f + __expf(-z.z)));
        v.w = ys.w * (z.w / (1.f + __expf(-z.w)));
        ss = v.x*v.x + v.y*v.y + v.z*v.z + v.w*v.w;
    }
    red[tid] = ss; __syncthreads();
    for (int s=128;s>0;s>>=1){ if(tid<s) red[tid]+=red[tid+s]; __syncthreads(); }
    float scale = rsqrtf(red[0]*(1.0f/DI) + 1e-5f);
    if (tid < 192){
        int i = tid << 2;
        float* o = g_yn + (size_t)row*DI;
        o[kperm(i  )] = __uint_as_float(f2tf(v.x*scale*gnorm[i  ]));
        o[kperm(i+1)] = __uint_as_float(f2tf(v.y*scale*gnorm[i+1]));
        o[kperm(i+2)] = __uint_as_float(f2tf(v.z*scale*gnorm[i+2]));
        o[kperm(i+3)] = __uint_as_float(f2tf(v.w*scale*gnorm[i+3]));
    }
}

// ---------------- pool stage 2: mean + LN -> g_featT ----------------
__global__ __launch_bounds__(128) void pool2_kernel(const float* __restrict__ w,
                                                    const float* __restrict__ b2)
{
    __shared__ float red[128];
    int b = blockIdx.x, tid = threadIdx.x;
    float v[3];
    #pragma unroll
    for (int q=0;q<3;q++){
        int d = tid + q*128;
        v[q] = g_poolf[b*DM + d] * (1.0f/LL);
    }
    red[tid] = v[0]+v[1]+v[2]; __syncthreads();
    for (int s=64;s>0;s>>=1){ if(tid<s) red[tid]+=red[tid+s]; __syncthreads(); }
    float mu = red[0]*(1.0f/DM);
    __syncthreads();
    float d0=v[0]-mu, d1=v[1]-mu, d2=v[2]-mu;
    red[tid] = d0*d0+d1*d1+d2*d2; __syncthreads();
    for (int s=64;s>0;s>>=1){ if(tid<s) red[tid]+=red[tid+s]; __syncthreads(); }
    float inv = rsqrtf(red[0]*(1.0f/DM) + 1e-5f);
    g_featT[(tid    )*BB + b] = d0*inv*w[tid]     + b2[tid];
    g_featT[(tid+128)*BB + b] = d1*inv*w[tid+128] + b2[tid+128];
    g_featT[(tid+256)*BB + b] = d2*inv*w[tid+256] + b2[tid+256];
}

// ---------------- classification heads ----------------
__global__ __launch_bounds__(256) void heads_kernel(
    const float* __restrict__ ow, const float* __restrict__ ob,
    const float* __restrict__ fw, const float* __restrict__ fb,
    const float* __restrict__ gw, const float* __restrict__ gb,
    const float* __restrict__ sw, const float* __restrict__ sb,
    float* __restrict__ out)
{
    __shared__ __align__(16) float sf[DM*BB];
    int tid = threadIdx.x;
    for (int i = tid; i < DM*BB; i += blockDim.x) sf[i] = g_featT[i];
    __syncthreads();

    int j = blockIdx.x * blockDim.x + tid;
    if (j >= NOUT) return;

    const float* W; const float* Bv; int jj, Nseg;
    if (j < N_ORDER)                      { W=ow; Bv=ob; jj=j;                     Nseg=N_ORDER; }
    else if (j < N_ORDER+N_FAMILY)        { W=fw; Bv=fb; jj=j-N_ORDER;             Nseg=N_FAMILY; }
    else if (j < N_ORDER+N_FAMILY+N_GENUS){ W=gw; Bv=gb; jj=j-N_ORDER-N_FAMILY;    Nseg=N_GENUS; }
    else                                  { W=sw; Bv=sb; jj=j-N_ORDER-N_FAMILY-N_GENUS; Nseg=N_SPECIES; }

    float acc[BB];
    #pragma unroll
    for (int b=0;b<BB;b++) acc[b]=0.f;
    for (int k=0;k<DM;k++){
        float wv = W[(size_t)k*Nseg + jj];
        const float4* row = (const float4*)&sf[k*BB];
        #pragma unroll
        for (int bq=0;bq<8;bq++){
            float4 f = row[bq];
            acc[4*bq+0] = fmaf(f.x, wv, acc[4*bq+0]);
            acc[4*bq+1] = fmaf(f.y, wv, acc[4*bq+1]);
            acc[4*bq+2] = fmaf(f.z, wv, acc[4*bq+2]);
            acc[4*bq+3] = fmaf(f.w, wv, acc[4*bq+3]);
        }
    }
    float bias = Bv[jj];
    #pragma unroll
    for (int b=0;b<BB;b++) out[(size_t)b*NOUT + j] = acc[b] + bias;
}

// ---------------- orchestration ----------------
extern "C" void kernel_launch(void* const* d_in, const int* in_sizes, int n_in,
                              void* d_out, int out_size)
{
    const int*   tokens = (const int*)  d_in[0];
    const float* emb    = (const float*)d_in[1];
    const float* ln_w   = (const float*)d_in[2];
    const float* ln_b   = (const float*)d_in[3];
    const float* Win    = (const float*)d_in[4];
    const float* cw     = (const float*)d_in[5];
    const float* cb     = (const float*)d_in[6];
    const float* dtb    = (const float*)d_in[7];
    const float* alog   = (const float*)d_in[8];
    const float* Dd     = (const float*)d_in[9];
    const float* gnw    = (const float*)d_in[10];
    const float* Wout   = (const float*)d_in[11];
    const float* nfw    = (const float*)d_in[12];
    const float* nfb    = (const float*)d_in[13];
    const float* plw    = (const float*)d_in[14];
    const float* plb    = (const float*)d_in[15];
    const float* ow     = (const float*)d_in[16];
    const float* ob     = (const float*)d_in[17];
    const float* fw     = (const float*)d_in[18];
    const float* fb     = (const float*)d_in[19];
    const float* gw     = (const float*)d_in[20];
    const float* gb     = (const float*)d_in[21];
    const float* sw     = (const float*)d_in[22];
    const float* sb     = (const float*)d_in[23];
    float* out = (float*)d_out;

    const int smem_bytes = SMEM_FLOATS * 4;
    cudaFuncSetAttribute((const void*)gemm_tc<0,1>, cudaFuncAttributeMaxDynamicSharedMemorySize, smem_bytes);
    cudaFuncSetAttribute((const void*)gemm_tc<1,2>, cudaFuncAttributeMaxDynamicSharedMemorySize, smem_bytes);
    cudaFuncSetAttribute((const void*)ssd_local_kernel, cudaFuncAttributeMaxDynamicSharedMemorySize, SSD_A_SMEM);

    wcvt_t_kernel<<<dim3((DIP+31)/32, (DI+31)/32, 4), 256>>>(Win, Wout);
    embed_ln_kernel<<<NT, 128>>>(tokens, emb, ln_w, ln_b);

    for (int l = 0; l < 2; l++) {
        if (l > 0) ln_kernel<<<NT, 128>>>(ln_w + l*DM, ln_b + l*DM);
        gemm_tc<0,1><<<dim3((DIP+GBN-1)/GBN, NT/GBM, 1), 256, smem_bytes>>>(l);
        conv_dtda_kernel<<<CONV_BLKS + DTDA_BLKS, 224>>>(cw + (size_t)l*CD*4, cb + l*CD,
                                                         dtb + l*NH, alog + l*NH);
        ssd_local_kernel  <<<BB*NH*NCHUNK, 128, SSD_A_SMEM>>>(Dd + l*NH);
        ssd_combine_kernel<<<BB*NH, 128>>>();
        ssd_fix_kernel    <<<BB*NH*(NCHUNK-1), 128>>>();
        gate_rms_kernel<<<NT, 256>>>(gnw + l*DI);
        gemm_tc<1,2><<<dim3((DM+GBN-1)/GBN, NT/GBM, 2), 256, smem_bytes>>>(l);
    }

    ln_final_kernel<<<NT, 128>>>(nfw, nfb);
    pool2_kernel<<<BB, 128>>>(plw, plb);
    heads_kernel<<<(NOUT + 255)/256, 256>>>(ow, ob, fw, fb, gw, gb, sw, sb, out);
}